// round 11
// baseline (speedup 1.0000x reference)
#include <cuda_runtime.h>
#include <cuda_bf16.h>
#include <cuda_fp16.h>
#include <cstdint>
#include <cstddef>

// Problem constants
constexpr int B_ = 8;
constexpr int N_ = 2048;
constexpr int E_ = 512;
constexpr int H_ = 8;
constexpr int D_ = 64;
constexpr int M_ = B_ * N_;   // 16384 rows
constexpr int NT_ = N_ / 64;  // 32 64-row tiles (mask-flag granularity)
constexpr int KT_ = 32;       // attention kv-tile rows
constexpr int NKT_ = N_ / KT_;// 64 kv tiles
constexpr int KST_ = 72;      // K/Q attention smem row stride (halfs)
constexpr int VST_ = 40;      // Vt attention smem row stride (halfs)
constexpr int BUFH_ = 32 * KST_ + 64 * VST_;   // 4864 halfs per KV buffer

constexpr size_t WBE_ = (size_t)E_ * E_;
constexpr size_t ACT_ = (size_t)M_ * E_;

// Scratch (device globals: allocation-free per harness rules)
__device__ __half g_qh[(size_t)B_ * H_ * N_ * D_];  // [b][h][n][d], pre-scaled log2e/tau, fp16
__device__ __half g_kh[(size_t)B_ * H_ * N_ * D_];  // [b][h][n][d] fp16
__device__ __half g_vt[(size_t)B_ * H_ * D_ * N_];  // [b][h][d][n] fp16 (V transposed)
__device__ int    g_mflag[B_ * NT_ * NT_];          // 1 = 64x64 tile all-nonzero
__device__ __nv_bfloat16 g_wbh[4][WBE_];            // bf16 hi parts of Wq,Wk,Wv,Wo
__device__ __nv_bfloat16 g_wbl[4][WBE_];            // bf16 lo parts
// activation hi/lo splits: slots 0..2 = Q,K,V inputs; slot 3 = attention output
__device__ __nv_bfloat16 g_xbh[4][ACT_];
__device__ __nv_bfloat16 g_xbl[4][ACT_];

__device__ __forceinline__ float neg_inf() { return __int_as_float(0xff800000); }

__device__ __forceinline__ float fexp2(float x) {
    float y;
    asm("ex2.approx.ftz.f32 %0, %1;" : "=f"(y) : "f"(x));
    return y;
}

// pack two floats into f16x2 (hi half = first arg)
__device__ __forceinline__ uint32_t packh(float hi, float lo) {
    uint32_t r;
    asm("cvt.rn.f16x2.f32 %0, %1, %2;" : "=r"(r) : "f"(hi), "f"(lo));
    return r;
}

// m16n8k16 bf16 mma (projections)
__device__ __forceinline__ void mma16b(float* c, const uint32_t* a, const uint32_t* b) {
    asm volatile(
        "mma.sync.aligned.m16n8k16.row.col.f32.bf16.bf16.f32 "
        "{%0,%1,%2,%3}, {%4,%5,%6,%7}, {%8,%9}, {%0,%1,%2,%3};\n"
        : "+f"(c[0]), "+f"(c[1]), "+f"(c[2]), "+f"(c[3])
        : "r"(a[0]), "r"(a[1]), "r"(a[2]), "r"(a[3]), "r"(b[0]), "r"(b[1]));
}

// m16n8k16 fp16 mma, fp32 accumulate (attention)
__device__ __forceinline__ void mma16h(float* c, const uint32_t* a, const uint32_t* b) {
    asm volatile(
        "mma.sync.aligned.m16n8k16.row.col.f32.f16.f16.f32 "
        "{%0,%1,%2,%3}, {%4,%5,%6,%7}, {%8,%9}, {%0,%1,%2,%3};\n"
        : "+f"(c[0]), "+f"(c[1]), "+f"(c[2]), "+f"(c[3])
        : "r"(a[0]), "r"(a[1]), "r"(a[2]), "r"(a[3]), "r"(b[0]), "r"(b[1]));
}

// pack two floats into bf16x2 hi + residual lo (memory order: low half = x0)
__device__ __forceinline__ void pack_split(float x0, float x1, uint32_t& hi, uint32_t& lo) {
    asm("cvt.rn.bf16x2.f32 %0, %1, %2;" : "=r"(hi) : "f"(x1), "f"(x0));
    float h0 = __uint_as_float(hi << 16);
    float h1 = __uint_as_float(hi & 0xffff0000u);
    asm("cvt.rn.bf16x2.f32 %0, %1, %2;" : "=r"(lo) : "f"(x1 - h1), "f"(x0 - h0));
}

// cp.async helpers
__device__ __forceinline__ void cpb16(const void* smem_dst, const void* gmem_src) {
    uint32_t s = (uint32_t)__cvta_generic_to_shared(smem_dst);
    asm volatile("cp.async.ca.shared.global [%0], [%1], 16;" :: "r"(s), "l"(gmem_src));
}
__device__ __forceinline__ void cp_commit() { asm volatile("cp.async.commit_group;"); }
template<int N>
__device__ __forceinline__ void cp_wait() { asm volatile("cp.async.wait_group %0;" :: "n"(N) : "memory"); }

// ---------------------------------------------------------------------------
// One-time splits: weights and activations -> (hi, lo) bf16 pairs.
// ---------------------------------------------------------------------------
__global__ __launch_bounds__(256)
void split_w(const float* __restrict__ Wq, const float* __restrict__ Wk,
             const float* __restrict__ Wv, const float* __restrict__ Wo)
{
    const int m = blockIdx.y;
    const float* W = (m == 0) ? Wq : (m == 1) ? Wk : (m == 2) ? Wv : Wo;
    const size_t i4 = ((size_t)blockIdx.x * 256 + threadIdx.x) * 4;
    float4 v = *reinterpret_cast<const float4*>(W + i4);
    uint32_t h01, l01, h23, l23;
    pack_split(v.x, v.y, h01, l01);
    pack_split(v.z, v.w, h23, l23);
    *reinterpret_cast<uint2*>(&g_wbh[m][i4]) = make_uint2(h01, h23);
    *reinterpret_cast<uint2*>(&g_wbl[m][i4]) = make_uint2(l01, l23);
}

__global__ __launch_bounds__(256)
void split_acts(const float* __restrict__ Q, const float* __restrict__ K,
                const float* __restrict__ V)
{
    const int z = blockIdx.y;
    const float* X = (z == 0) ? Q : (z == 1) ? K : V;
    const size_t i4 = ((size_t)blockIdx.x * 256 + threadIdx.x) * 4;
    float4 v = *reinterpret_cast<const float4*>(X + i4);
    uint32_t h01, l01, h23, l23;
    pack_split(v.x, v.y, h01, l01);
    pack_split(v.z, v.w, h23, l23);
    *reinterpret_cast<uint2*>(&g_xbh[z][i4]) = make_uint2(h01, h23);
    *reinterpret_cast<uint2*>(&g_xbl[z][i4]) = make_uint2(l01, l23);
}

// ---------------------------------------------------------------------------
// Mask preprocessing: one flag per (b, 64-row q tile, 64-col kv tile).
// ---------------------------------------------------------------------------
__global__ __launch_bounds__(256)
void mask_flags(const int* __restrict__ mask)
{
    const int kvt = blockIdx.x, qt = blockIdx.y, b = blockIdx.z;
    const int tid = threadIdx.x;
    const int r = tid >> 2, c0 = (tid & 3) * 16;
    const int* base = mask + (size_t)b * N_ * N_ + (size_t)(qt * 64 + r) * N_ + kvt * 64 + c0;
    bool ok = true;
    #pragma unroll
    for (int i = 0; i < 4; i++) {
        int4 m = *reinterpret_cast<const int4*>(base + i * 4);
        ok &= (m.x != 0) & (m.y != 0) & (m.z != 0) & (m.w != 0);
    }
    int all = __syncthreads_and((int)ok);
    if (tid == 0) g_mflag[(b * NT_ + qt) * NT_ + kvt] = all;
}

// ---------------------------------------------------------------------------
// GEMM core v4: Y = (Xh+Xl) @ (Wh+Wl)^T, bf16 3-term, m16n8k16, ALL operands
// pre-split bf16 in smem (stride 56 halfs -> every frag LDS conflict-free).
// Block 128x64, BK=32, 256 thr = 8 warps (4m x 2n), warp 32x32.
// Zero conversion work in the mainloop. cp.async double buffer.
// ---------------------------------------------------------------------------
constexpr int XTB_ = 128 * 56 * 2;          // one X tile bytes (bf16)
constexpr int WTB_ = 64 * 56 * 2;           // one W tile bytes (bf16)
constexpr int GBUF4_ = 2 * XTB_ + 2 * WTB_; // 43008 B per buffer
constexpr int GKT_ = E_ / 32;               // 16 k tiles

__device__ __forceinline__ void gemm_prefetch4(int slot, char* buf, int m0, int n0, int kt)
{
    const int tid = threadIdx.x;
    char* xh = buf;
    char* xl = buf + XTB_;
    char* wh = buf + 2 * XTB_;
    char* wl = wh + WTB_;
    // X: 128 rows x 32 bf16 = 64B/row = 4 chunks; 512 chunks each for hi/lo
    #pragma unroll
    for (int i = 0; i < 2; i++) {
        int idx = tid + i * 256;
        int r = idx >> 2, c = idx & 3;
        const size_t src = (size_t)(m0 + r) * E_ + kt * 32 + c * 8;
        cpb16(xh + r * 112 + c * 16, &g_xbh[slot][src]);
        cpb16(xl + r * 112 + c * 16, &g_xbl[slot][src]);
    }
    // W: 64 rows x 32 bf16; 256 chunks each for hi/lo
    {
        int r = tid >> 2, c = tid & 3;
        const size_t src = (size_t)(n0 + r) * E_ + kt * 32 + c * 8;
        cpb16(wh + r * 112 + c * 16, &g_wbh[slot][src]);
        cpb16(wl + r * 112 + c * 16, &g_wbl[slot][src]);
    }
    cp_commit();
}

__device__ __forceinline__ void gemm_core4(int slot, char* smb, int m0, int n0,
                                           float acc[2][4][4])
{
    const int tid = threadIdx.x;
    const int warp = tid >> 5, lane = tid & 31;
    const int g = lane >> 2, tg = lane & 3;
    const int wm = warp >> 1, wn = warp & 1;

    gemm_prefetch4(slot, smb, m0, n0, 0);

    for (int kt = 0; kt < GKT_; kt++) {
        if (kt + 1 < GKT_) {
            gemm_prefetch4(slot, smb + ((kt + 1) & 1) * GBUF4_, m0, n0, kt + 1);
            cp_wait<1>();
        } else {
            cp_wait<0>();
        }
        __syncthreads();
        const char* buf = smb + (kt & 1) * GBUF4_;
        const char* Xhs = buf;
        const char* Xls = buf + XTB_;
        const char* Whs = buf + 2 * XTB_;
        const char* Wls = Whs + WTB_;

        #pragma unroll
        for (int ks = 0; ks < 2; ks++) {
            const int k0 = ks * 16;
            uint32_t Ah[2][4], Al[2][4], Bh[4][2], Bl[4][2];
            #pragma unroll
            for (int mt = 0; mt < 2; mt++) {
                const int rb = wm * 32 + mt * 16;
                const int o0 = (rb + g) * 112 + (k0 + 2 * tg) * 2;
                const int o1 = (rb + g + 8) * 112 + (k0 + 2 * tg) * 2;
                Ah[mt][0] = *reinterpret_cast<const uint32_t*>(Xhs + o0);
                Ah[mt][1] = *reinterpret_cast<const uint32_t*>(Xhs + o1);
                Ah[mt][2] = *reinterpret_cast<const uint32_t*>(Xhs + o0 + 16);
                Ah[mt][3] = *reinterpret_cast<const uint32_t*>(Xhs + o1 + 16);
                Al[mt][0] = *reinterpret_cast<const uint32_t*>(Xls + o0);
                Al[mt][1] = *reinterpret_cast<const uint32_t*>(Xls + o1);
                Al[mt][2] = *reinterpret_cast<const uint32_t*>(Xls + o0 + 16);
                Al[mt][3] = *reinterpret_cast<const uint32_t*>(Xls + o1 + 16);
            }
            #pragma unroll
            for (int nt = 0; nt < 4; nt++) {
                const int r = wn * 32 + nt * 8 + g;
                const int boff = r * 112 + (k0 + 2 * tg) * 2;
                Bh[nt][0] = *reinterpret_cast<const uint32_t*>(Whs + boff);
                Bh[nt][1] = *reinterpret_cast<const uint32_t*>(Whs + boff + 16);
                Bl[nt][0] = *reinterpret_cast<const uint32_t*>(Wls + boff);
                Bl[nt][1] = *reinterpret_cast<const uint32_t*>(Wls + boff + 16);
            }
            #pragma unroll
            for (int mt = 0; mt < 2; mt++)
                #pragma unroll
                for (int nt = 0; nt < 4; nt++) {
                    mma16b(acc[mt][nt], Ah[mt], Bh[nt]);   // hi*hi
                    mma16b(acc[mt][nt], Ah[mt], Bl[nt]);   // hi*lo
                    mma16b(acc[mt][nt], Al[mt], Bh[nt]);   // lo*hi
                }
        }
        __syncthreads();
    }
}

// QKV projections fused; outputs fp16 formatted for the fp16 attention:
//  z=0: Q scaled by log2e/tau -> g_qh; z=1: K -> g_kh; z=2: V -> g_vt (transposed).
__global__ __launch_bounds__(256)
void gemm_qkv(const float* __restrict__ taup)
{
    extern __shared__ char smb[];
    const int z = blockIdx.z;
    const float scl = (z == 0) ? (1.4426950408889634f / __ldg(taup)) : 1.0f;

    const int m0 = blockIdx.y * 128, n0 = blockIdx.x * 64;
    float acc[2][4][4] = {};
    gemm_core4(z, smb, m0, n0, acc);

    const int tid = threadIdx.x;
    const int warp = tid >> 5, lane = tid & 31;
    const int g = lane >> 2, tg = lane & 3;
    const int wm = warp >> 1, wn = warp & 1;
    const int h = blockIdx.x;              // BN=64 == head dim

    if (z <= 1) {
        __half* Y = (z == 0) ? g_qh : g_kh;
        #pragma unroll
        for (int mt = 0; mt < 2; mt++) {
            #pragma unroll
            for (int nt = 0; nt < 4; nt++) {
                const int dd = wn * 32 + nt * 8 + 2 * tg;
                int m = m0 + wm * 32 + mt * 16 + g;
                int b = m >> 11, n = m & (N_ - 1);
                *reinterpret_cast<uint32_t*>(&Y[((size_t)((b * H_ + h) * N_ + n)) * D_ + dd]) =
                    packh(acc[mt][nt][1] * scl, acc[mt][nt][0] * scl);
                m += 8; b = m >> 11; n = m & (N_ - 1);
                *reinterpret_cast<uint32_t*>(&Y[((size_t)((b * H_ + h) * N_ + n)) * D_ + dd]) =
                    packh(acc[mt][nt][3] * scl, acc[mt][nt][2] * scl);
            }
        }
    } else {
        // V: transpose 128(m) x 64(d) tile through smem -> g_vt[b][h][d][n]
        __half* ts = reinterpret_cast<__half*>(smb);   // [64][136] halfs
        __syncthreads();
        #pragma unroll
        for (int mt = 0; mt < 2; mt++) {
            #pragma unroll
            for (int nt = 0; nt < 4; nt++) {
                const int dd = wn * 32 + nt * 8 + 2 * tg;
                const int ml = wm * 32 + mt * 16 + g;
                ts[dd * 136 + ml]           = __float2half(acc[mt][nt][0]);
                ts[(dd + 1) * 136 + ml]     = __float2half(acc[mt][nt][1]);
                ts[dd * 136 + ml + 8]       = __float2half(acc[mt][nt][2]);
                ts[(dd + 1) * 136 + ml + 8] = __float2half(acc[mt][nt][3]);
            }
        }
        __syncthreads();
        const int r = tid >> 2, c = tid & 3;
        const int bb = m0 >> 11, noff = m0 & (N_ - 1);
        __half* dst = g_vt + ((size_t)((bb * H_ + h) * D_ + r)) * N_ + noff + c * 32;
        #pragma unroll
        for (int i = 0; i < 4; i++)
            *reinterpret_cast<uint4*>(dst + i * 8) =
                *reinterpret_cast<const uint4*>(&ts[r * 136 + c * 32 + i * 8]);
    }
}

// Output projection: attn_out (slot 3, pre-split) @ Wo^T + bo -> out
__global__ __launch_bounds__(256)
void gemm_out(const float* __restrict__ bias, float* __restrict__ Yext)
{
    extern __shared__ char smb[];
    const int m0 = blockIdx.y * 128, n0 = blockIdx.x * 64;
    float acc[2][4][4] = {};
    gemm_core4(3, smb, m0, n0, acc);

    const int tid = threadIdx.x;
    const int warp = tid >> 5, lane = tid & 31;
    const int g = lane >> 2, tg = lane & 3;
    const int wm = warp >> 1, wn = warp & 1;
    #pragma unroll
    for (int mt = 0; mt < 2; mt++) {
        #pragma unroll
        for (int nt = 0; nt < 4; nt++) {
            const int o = n0 + wn * 32 + nt * 8 + 2 * tg;
            float2 bb = *reinterpret_cast<const float2*>(bias + o);
            const int m = m0 + wm * 32 + mt * 16 + g;
            *reinterpret_cast<float2*>(&Yext[(size_t)m * E_ + o]) =
                make_float2(acc[mt][nt][0] + bb.x, acc[mt][nt][1] + bb.y);
            *reinterpret_cast<float2*>(&Yext[(size_t)(m + 8) * E_ + o]) =
                make_float2(acc[mt][nt][2] + bb.x, acc[mt][nt][3] + bb.y);
        }
    }
}

// ---------------------------------------------------------------------------
// Flash attention v5 (R10, validated): fp16 m16n8k16, 128 q-rows/block,
// 4 warps x 32 rows; K/V fragments shared across both row groups; cp.async
// double buffer; log2 softmax. NEW: epilogue writes bf16 hi/lo split directly
// (feeds gemm_out slot 3; no fp32 g_att round trip).
// ---------------------------------------------------------------------------
__global__ __launch_bounds__(128, 2)
void attn_tc(const int* __restrict__ mask)
{
    __shared__ __align__(16) __half sm[2 * BUFH_];

    const int h = blockIdx.x, qt = blockIdx.y, b = blockIdx.z;
    const int tid = threadIdx.x;
    const int warp = tid >> 5, lane = tid & 31;
    const int g = lane >> 2, tg = lane & 3;
    const int q0 = qt * 128;

    const size_t bh = (size_t)(b * H_ + h) * N_ * D_;
    const __half* qbase = g_qh + bh;
    const __half* kbase = g_kh + bh;
    const __half* vtbase = g_vt + bh;
    const int* mbase = mask + (size_t)b * N_ * N_;
    const int* fb0 = g_mflag + (b * NT_ + 2 * qt) * NT_;
    const int* fb1 = fb0 + NT_;

    // Stage Q (128x64 fp16) into smem [128][72]
    {
        #pragma unroll
        for (int i = 0; i < 8; i++) {
            int idx = tid + i * 128;
            int r = idx >> 3, c = (idx & 7) * 8;
            cpb16(&sm[r * KST_ + c], qbase + (size_t)(q0 + r) * D_ + c);
        }
        cp_commit(); cp_wait<0>();
        __syncthreads();
    }

    uint32_t q_a[2][4][4];
    #pragma unroll
    for (int u = 0; u < 2; u++) {
        #pragma unroll
        for (int kc = 0; kc < 4; kc++) {
            const int row = warp * 32 + u * 16 + g;
            q_a[u][kc][0] = *reinterpret_cast<const uint32_t*>(&sm[row * KST_ + kc * 16 + 2 * tg]);
            q_a[u][kc][1] = *reinterpret_cast<const uint32_t*>(&sm[(row + 8) * KST_ + kc * 16 + 2 * tg]);
            q_a[u][kc][2] = *reinterpret_cast<const uint32_t*>(&sm[row * KST_ + kc * 16 + 8 + 2 * tg]);
            q_a[u][kc][3] = *reinterpret_cast<const uint32_t*>(&sm[(row + 8) * KST_ + kc * 16 + 8 + 2 * tg]);
        }
    }
    __syncthreads();

    // Prefetch kv tile 0 into buf 0
    {
        #pragma unroll
        for (int i = 0; i < 2; i++) {
            int idx = tid + i * 128;
            int r = idx >> 3, c = (idx & 7) * 8;
            cpb16(&sm[r * KST_ + c], kbase + (size_t)r * D_ + c);
        }
        #pragma unroll
        for (int i = 0; i < 2; i++) {
            int idx = tid + i * 128;
            int d = idx >> 2, c = (idx & 3) * 8;
            cpb16(&sm[32 * KST_ + d * VST_ + c], vtbase + (size_t)d * N_ + c);
        }
        cp_commit();
    }

    float o[2][8][4] = {};
    float mr[2][2] = {{neg_inf(), neg_inf()}, {neg_inf(), neg_inf()}};
    float lr[2][2] = {};
    int qrow[2];
    qrow[0] = q0 + warp * 32 + g;
    qrow[1] = qrow[0] + 16;

    for (int t = 0; t < NKT_; t++) {
        cp_wait<0>();
        __syncthreads();

        if (t + 1 < NKT_) {
            const __half* kb2 = kbase + (size_t)(t + 1) * KT_ * D_;
            const __half* vb2 = vtbase + (size_t)(t + 1) * KT_;
            __half* dst = sm + ((t + 1) & 1) * BUFH_;
            #pragma unroll
            for (int i = 0; i < 2; i++) {
                int idx = tid + i * 128;
                int r = idx >> 3, c = (idx & 7) * 8;
                cpb16(&dst[r * KST_ + c], kb2 + (size_t)r * D_ + c);
            }
            #pragma unroll
            for (int i = 0; i < 2; i++) {
                int idx = tid + i * 128;
                int d = idx >> 2, c = (idx & 3) * 8;
                cpb16(&dst[32 * KST_ + d * VST_ + c], vb2 + (size_t)d * N_ + c);
            }
            cp_commit();
        }

        const __half* Kc = sm + (t & 1) * BUFH_;
        const __half* Vc = Kc + 32 * KST_;
        const int kv0 = t * KT_;
        const int clean = __ldg(fb0 + (t >> 1)) & __ldg(fb1 + (t >> 1));

        float s[2][4][4] = {};
        #pragma unroll
        for (int kc = 0; kc < 4; kc++) {
            #pragma unroll
            for (int nt = 0; nt < 4; nt++) {
                uint32_t bfr[2];
                const int kb = (nt * 8 + g) * KST_ + kc * 16 + 2 * tg;
                bfr[0] = *reinterpret_cast<const uint32_t*>(&Kc[kb]);
                bfr[1] = *reinterpret_cast<const uint32_t*>(&Kc[kb + 8]);
                mma16h(s[0][nt], q_a[0][kc], bfr);
                mma16h(s[1][nt], q_a[1][kc], bfr);
            }
        }

        if (!clean) {
            #pragma unroll
            for (int u = 0; u < 2; u++) {
                #pragma unroll
                for (int nt = 0; nt < 4; nt++) {
                    const int col = kv0 + nt * 8 + 2 * tg;
                    int2 mA = *reinterpret_cast<const int2*>(mbase + (size_t)qrow[u] * N_ + col);
                    int2 mB = *reinterpret_cast<const int2*>(mbase + (size_t)(qrow[u] + 8) * N_ + col);
                    if (!mA.x) s[u][nt][0] = neg_inf();
                    if (!mA.y) s[u][nt][1] = neg_inf();
                    if (!mB.x) s[u][nt][2] = neg_inf();
                    if (!mB.y) s[u][nt][3] = neg_inf();
                }
            }
        }

        #pragma unroll
        for (int u = 0; u < 2; u++) {
            float mx0 = neg_inf(), mx1 = neg_inf();
            #pragma unroll
            for (int nt = 0; nt < 4; nt++) {
                mx0 = fmaxf(mx0, fmaxf(s[u][nt][0], s[u][nt][1]));
                mx1 = fmaxf(mx1, fmaxf(s[u][nt][2], s[u][nt][3]));
            }
            mx0 = fmaxf(mx0, __shfl_xor_sync(0xffffffffu, mx0, 1));
            mx0 = fmaxf(mx0, __shfl_xor_sync(0xffffffffu, mx0, 2));
            mx1 = fmaxf(mx1, __shfl_xor_sync(0xffffffffu, mx1, 1));
            mx1 = fmaxf(mx1, __shfl_xor_sync(0xffffffffu, mx1, 2));
            const float mn0 = fmaxf(mr[u][0], mx0), mn1 = fmaxf(mr[u][1], mx1);
            const float sc0 = fexp2(fmaxf(mr[u][0] - mn0, -120.0f));
            const float sc1 = fexp2(fmaxf(mr[u][1] - mn1, -120.0f));
            float sum0 = 0.0f, sum1 = 0.0f;
            #pragma unroll
            for (int nt = 0; nt < 4; nt++) {
                float p0 = fexp2(fmaxf(s[u][nt][0] - mn0, -120.0f));
                float p1 = fexp2(fmaxf(s[u][nt][1] - mn0, -120.0f));
                float p2 = fexp2(fmaxf(s[u][nt][2] - mn1, -120.0f));
                float p3 = fexp2(fmaxf(s[u][nt][3] - mn1, -120.0f));
                s[u][nt][0] = p0; s[u][nt][1] = p1; s[u][nt][2] = p2; s[u][nt][3] = p3;
                sum0 += p0 + p1; sum1 += p2 + p3;
            }
            sum0 += __shfl_xor_sync(0xffffffffu, sum0, 1);
            sum0 += __shfl_xor_sync(0xffffffffu, sum0, 2);
            sum1 += __shfl_xor_sync(0xffffffffu, sum1, 1);
            sum1 += __shfl_xor_sync(0xffffffffu, sum1, 2);
            lr[u][0] = lr[u][0] * sc0 + sum0; lr[u][1] = lr[u][1] * sc1 + sum1;
            mr[u][0] = mn0; mr[u][1] = mn1;

            #pragma unroll
            for (int dt = 0; dt < 8; dt++) {
                o[u][dt][0] *= sc0; o[u][dt][1] *= sc0;
                o[u][dt][2] *= sc1; o[u][dt][3] *= sc1;
            }
        }

        #pragma unroll
        for (int kc2 = 0; kc2 < 2; kc2++) {
            const int srcC = (g << 2) | tg;
            uint32_t a[2][4];
            #pragma unroll
            for (int u = 0; u < 2; u++) {
                float v0 = __shfl_sync(0xffffffffu, s[u][kc2 * 2][0], srcC);
                float v1 = __shfl_sync(0xffffffffu, s[u][kc2 * 2][1], srcC);
                float v2 = __shfl_sync(0xffffffffu, s[u][kc2 * 2][2], srcC);
                float v3 = __shfl_sync(0xffffffffu, s[u][kc2 * 2][3], srcC);
                float w0 = __shfl_sync(0xffffffffu, s[u][kc2 * 2 + 1][0], srcC);
                float w1 = __shfl_sync(0xffffffffu, s[u][kc2 * 2 + 1][1], srcC);
                float w2 = __shfl_sync(0xffffffffu, s[u][kc2 * 2 + 1][2], srcC);
                float w3 = __shfl_sync(0xffffffffu, s[u][kc2 * 2 + 1][3], srcC);
                a[u][0] = packh(v1, v0);
                a[u][1] = packh(v3, v2);
                a[u][2] = packh(w1, w0);
                a[u][3] = packh(w3, w2);
            }
            #pragma unroll
            for (int dt = 0; dt < 8; dt++) {
                uint32_t bfr[2];
                const int vb = (dt * 8 + g) * VST_ + kc2 * 16 + 2 * tg;
                bfr[0] = *reinterpret_cast<const uint32_t*>(&Vc[vb]);
                bfr[1] = *reinterpret_cast<const uint32_t*>(&Vc[vb + 8]);
                mma16h(o[0][dt], a[0], bfr);
                mma16h(o[1][dt], a[1], bfr);
            }
        }
    }

    // Epilogue: normalize, recombine heads, write bf16 hi/lo split (slot 3)
    #pragma unroll
    for (int u = 0; u < 2; u++) {
        const float il0 = 1.0f / lr[u][0], il1 = 1.0f / lr[u][1];
        #pragma unroll
        for (int dt = 0; dt < 8; dt++) {
            const int dd = h * 64 + dt * 8 + 2 * tg;
            uint32_t hi, lo;
            pack_split(o[u][dt][0] * il0, o[u][dt][1] * il0, hi, lo);
            const size_t ix0 = (size_t)(b * N_ + qrow[u]) * E_ + dd;
            *reinterpret_cast<uint32_t*>(&g_xbh[3][ix0]) = hi;
            *reinterpret_cast<uint32_t*>(&g_xbl[3][ix0]) = lo;
            pack_split(o[u][dt][2] * il1, o[u][dt][3] * il1, hi, lo);
            const size_t ix1 = (size_t)(b * N_ + qrow[u] + 8) * E_ + dd;
            *reinterpret_cast<uint32_t*>(&g_xbh[3][ix1]) = hi;
            *reinterpret_cast<uint32_t*>(&g_xbl[3][ix1]) = lo;
        }
    }
}

// ---------------------------------------------------------------------------
extern "C" void kernel_launch(void* const* d_in, const int* in_sizes, int n_in,
                              void* d_out, int out_size)
{
    const float* Q    = (const float*)d_in[0];
    const float* K    = (const float*)d_in[1];
    const float* V    = (const float*)d_in[2];
    const int*   mask = (const int*)  d_in[3];
    const float* Wq   = (const float*)d_in[4];
    const float* Wk   = (const float*)d_in[5];
    const float* Wv   = (const float*)d_in[6];
    const float* Wo   = (const float*)d_in[7];
    const float* bo   = (const float*)d_in[8];
    const float* tau  = (const float*)d_in[9];
    float* out = (float*)d_out;

    const int gemm_smem = 2 * GBUF4_;   // 86016

    cudaFuncSetAttribute(gemm_qkv, cudaFuncAttributeMaxDynamicSharedMemorySize, gemm_smem);
    cudaFuncSetAttribute(gemm_out, cudaFuncAttributeMaxDynamicSharedMemorySize, gemm_smem);

    split_w<<<dim3((int)(WBE_ / 1024), 4), 256>>>(Wq, Wk, Wv, Wo);
    split_acts<<<dim3((int)(ACT_ / 1024), 3), 256>>>(Q, K, V);
    mask_flags<<<dim3(NT_, NT_, B_), 256>>>(mask);

    gemm_qkv<<<dim3(E_ / 64, M_ / 128, 3), 256, gemm_smem>>>(tau);

    // grid.x = heads (fastest) so the 8 heads sharing a mask tile are adjacent -> L2 reuse
    attn_tc<<<dim3(H_, N_ / 128, B_), 128>>>(mask);

    gemm_out<<<dim3(E_ / 64, M_ / 128), 256, gemm_smem>>>(bo, out);
}

// round 12
// speedup vs baseline: 1.0370x; 1.0370x over previous
#include <cuda_runtime.h>
#include <cuda_bf16.h>
#include <cuda_fp16.h>
#include <cstdint>
#include <cstddef>

// Problem constants
constexpr int B_ = 8;
constexpr int N_ = 2048;
constexpr int E_ = 512;
constexpr int H_ = 8;
constexpr int D_ = 64;
constexpr int M_ = B_ * N_;   // 16384 rows
constexpr int NT_ = N_ / 64;  // 32 64-row tiles (mask-flag granularity)
constexpr int KT_ = 32;       // attention kv-tile rows
constexpr int NKT_ = N_ / KT_;// 64 kv tiles
constexpr int KST_ = 72;      // K/Q attention smem row stride (halfs)
constexpr int VST_ = 40;      // Vt attention smem row stride (halfs)
constexpr int BUFH_ = 32 * KST_ + 64 * VST_;   // 4864 halfs per KV buffer

constexpr size_t WBE_ = (size_t)E_ * E_;
constexpr size_t ACT_ = (size_t)M_ * E_;

// Scratch (device globals: allocation-free per harness rules)
__device__ __half g_qh[(size_t)B_ * H_ * N_ * D_];  // [b][h][n][d], pre-scaled log2e/tau, fp16
__device__ __half g_kh[(size_t)B_ * H_ * N_ * D_];  // [b][h][n][d] fp16
__device__ __half g_vt[(size_t)B_ * H_ * D_ * N_];  // [b][h][d][n] fp16 (V transposed)
__device__ int    g_mflag[B_ * NT_ * NT_];          // 1 = 64x64 tile all-nonzero
__device__ __nv_bfloat16 g_wbh[4][WBE_];            // bf16 hi parts of Wq,Wk,Wv,Wo
__device__ __nv_bfloat16 g_wbl[4][WBE_];            // bf16 lo parts
// activation hi/lo splits: slots 0..2 = Q,K,V inputs; slot 3 = attention output
__device__ __nv_bfloat16 g_xbh[4][ACT_];
__device__ __nv_bfloat16 g_xbl[4][ACT_];

__device__ __forceinline__ float neg_inf() { return __int_as_float(0xff800000); }

__device__ __forceinline__ float fexp2(float x) {
    float y;
    asm("ex2.approx.ftz.f32 %0, %1;" : "=f"(y) : "f"(x));
    return y;
}

// pack two floats into f16x2 (hi half = first arg)
__device__ __forceinline__ uint32_t packh(float hi, float lo) {
    uint32_t r;
    asm("cvt.rn.f16x2.f32 %0, %1, %2;" : "=r"(r) : "f"(hi), "f"(lo));
    return r;
}

// m16n8k16 bf16 mma (projections)
__device__ __forceinline__ void mma16b(float* c, const uint32_t* a, const uint32_t* b) {
    asm volatile(
        "mma.sync.aligned.m16n8k16.row.col.f32.bf16.bf16.f32 "
        "{%0,%1,%2,%3}, {%4,%5,%6,%7}, {%8,%9}, {%0,%1,%2,%3};\n"
        : "+f"(c[0]), "+f"(c[1]), "+f"(c[2]), "+f"(c[3])
        : "r"(a[0]), "r"(a[1]), "r"(a[2]), "r"(a[3]), "r"(b[0]), "r"(b[1]));
}

// m16n8k16 fp16 mma, fp32 accumulate (attention)
__device__ __forceinline__ void mma16h(float* c, const uint32_t* a, const uint32_t* b) {
    asm volatile(
        "mma.sync.aligned.m16n8k16.row.col.f32.f16.f16.f32 "
        "{%0,%1,%2,%3}, {%4,%5,%6,%7}, {%8,%9}, {%0,%1,%2,%3};\n"
        : "+f"(c[0]), "+f"(c[1]), "+f"(c[2]), "+f"(c[3])
        : "r"(a[0]), "r"(a[1]), "r"(a[2]), "r"(a[3]), "r"(b[0]), "r"(b[1]));
}

// pack two floats into bf16x2 hi + residual lo (memory order: low half = x0)
__device__ __forceinline__ void pack_split(float x0, float x1, uint32_t& hi, uint32_t& lo) {
    asm("cvt.rn.bf16x2.f32 %0, %1, %2;" : "=r"(hi) : "f"(x1), "f"(x0));
    float h0 = __uint_as_float(hi << 16);
    float h1 = __uint_as_float(hi & 0xffff0000u);
    asm("cvt.rn.bf16x2.f32 %0, %1, %2;" : "=r"(lo) : "f"(x1 - h1), "f"(x0 - h0));
}

// cp.async helpers
__device__ __forceinline__ void cpb16(const void* smem_dst, const void* gmem_src) {
    uint32_t s = (uint32_t)__cvta_generic_to_shared(smem_dst);
    asm volatile("cp.async.ca.shared.global [%0], [%1], 16;" :: "r"(s), "l"(gmem_src));
}
__device__ __forceinline__ void cp_commit() { asm volatile("cp.async.commit_group;"); }
template<int N>
__device__ __forceinline__ void cp_wait() { asm volatile("cp.async.wait_group %0;" :: "n"(N) : "memory"); }

// ---------------------------------------------------------------------------
// One-time splits: weights and activations -> (hi, lo) bf16 pairs.
// ---------------------------------------------------------------------------
__global__ __launch_bounds__(256)
void split_w(const float* __restrict__ Wq, const float* __restrict__ Wk,
             const float* __restrict__ Wv, const float* __restrict__ Wo)
{
    const int m = blockIdx.y;
    const float* W = (m == 0) ? Wq : (m == 1) ? Wk : (m == 2) ? Wv : Wo;
    const size_t i4 = ((size_t)blockIdx.x * 256 + threadIdx.x) * 4;
    float4 v = *reinterpret_cast<const float4*>(W + i4);
    uint32_t h01, l01, h23, l23;
    pack_split(v.x, v.y, h01, l01);
    pack_split(v.z, v.w, h23, l23);
    *reinterpret_cast<uint2*>(&g_wbh[m][i4]) = make_uint2(h01, h23);
    *reinterpret_cast<uint2*>(&g_wbl[m][i4]) = make_uint2(l01, l23);
}

__global__ __launch_bounds__(256)
void split_acts(const float* __restrict__ Q, const float* __restrict__ K,
                const float* __restrict__ V)
{
    const int z = blockIdx.y;
    const float* X = (z == 0) ? Q : (z == 1) ? K : V;
    const size_t i4 = ((size_t)blockIdx.x * 256 + threadIdx.x) * 4;
    float4 v = *reinterpret_cast<const float4*>(X + i4);
    uint32_t h01, l01, h23, l23;
    pack_split(v.x, v.y, h01, l01);
    pack_split(v.z, v.w, h23, l23);
    *reinterpret_cast<uint2*>(&g_xbh[z][i4]) = make_uint2(h01, h23);
    *reinterpret_cast<uint2*>(&g_xbl[z][i4]) = make_uint2(l01, l23);
}

// ---------------------------------------------------------------------------
// Mask preprocessing: one flag per (b, 64-row q tile, 64-col kv tile).
// ---------------------------------------------------------------------------
__global__ __launch_bounds__(256)
void mask_flags(const int* __restrict__ mask)
{
    const int kvt = blockIdx.x, qt = blockIdx.y, b = blockIdx.z;
    const int tid = threadIdx.x;
    const int r = tid >> 2, c0 = (tid & 3) * 16;
    const int* base = mask + (size_t)b * N_ * N_ + (size_t)(qt * 64 + r) * N_ + kvt * 64 + c0;
    bool ok = true;
    #pragma unroll
    for (int i = 0; i < 4; i++) {
        int4 m = *reinterpret_cast<const int4*>(base + i * 4);
        ok &= (m.x != 0) & (m.y != 0) & (m.z != 0) & (m.w != 0);
    }
    int all = __syncthreads_and((int)ok);
    if (tid == 0) g_mflag[(b * NT_ + qt) * NT_ + kvt] = all;
}

// ---------------------------------------------------------------------------
// GEMM core v4b: Y = (Xh+Xl) @ (Wh+Wl)^T, bf16 3-term, m16n8k16, all operands
// pre-split bf16 in smem. ROW STRIDE 40 halfs (32 data + 8 pad): frag LDS word
// = 20g + k0/2 + tg, all 32 lanes distinct -> conflict-free, and the buffer
// shrinks to 30720B -> 61440 total -> 3 CTAs/SM (24 warps; R11's stride-56
// buffers allowed only 2 CTAs and regressed).
// Block 128x64, BK=32, 256 thr = 8 warps (4m x 2n), warp 32x32.
// ---------------------------------------------------------------------------
constexpr int GST_ = 40;                    // gemm smem row stride (halfs)
constexpr int XTB_ = 128 * GST_ * 2;        // one X tile bytes (bf16)  = 10240
constexpr int WTB_ = 64 * GST_ * 2;         // one W tile bytes (bf16)  = 5120
constexpr int GBUF4_ = 2 * XTB_ + 2 * WTB_; // 30720 B per buffer
constexpr int GKT_ = E_ / 32;               // 16 k tiles

__device__ __forceinline__ void gemm_prefetch4(int slot, char* buf, int m0, int n0, int kt)
{
    const int tid = threadIdx.x;
    char* xh = buf;
    char* xl = buf + XTB_;
    char* wh = buf + 2 * XTB_;
    char* wl = wh + WTB_;
    // X: 128 rows x 32 bf16 = 64B/row = 4 chunks; 512 chunks each for hi/lo
    #pragma unroll
    for (int i = 0; i < 2; i++) {
        int idx = tid + i * 256;
        int r = idx >> 2, c = idx & 3;
        const size_t src = (size_t)(m0 + r) * E_ + kt * 32 + c * 8;
        cpb16(xh + r * 80 + c * 16, &g_xbh[slot][src]);
        cpb16(xl + r * 80 + c * 16, &g_xbl[slot][src]);
    }
    // W: 64 rows x 32 bf16; 256 chunks each for hi/lo
    {
        int r = tid >> 2, c = tid & 3;
        const size_t src = (size_t)(n0 + r) * E_ + kt * 32 + c * 8;
        cpb16(wh + r * 80 + c * 16, &g_wbh[slot][src]);
        cpb16(wl + r * 80 + c * 16, &g_wbl[slot][src]);
    }
    cp_commit();
}

__device__ __forceinline__ void gemm_core4(int slot, char* smb, int m0, int n0,
                                           float acc[2][4][4])
{
    const int tid = threadIdx.x;
    const int warp = tid >> 5, lane = tid & 31;
    const int g = lane >> 2, tg = lane & 3;
    const int wm = warp >> 1, wn = warp & 1;

    gemm_prefetch4(slot, smb, m0, n0, 0);

    for (int kt = 0; kt < GKT_; kt++) {
        if (kt + 1 < GKT_) {
            gemm_prefetch4(slot, smb + ((kt + 1) & 1) * GBUF4_, m0, n0, kt + 1);
            cp_wait<1>();
        } else {
            cp_wait<0>();
        }
        __syncthreads();
        const char* buf = smb + (kt & 1) * GBUF4_;
        const char* Xhs = buf;
        const char* Xls = buf + XTB_;
        const char* Whs = buf + 2 * XTB_;
        const char* Wls = Whs + WTB_;

        #pragma unroll
        for (int ks = 0; ks < 2; ks++) {
            const int k0 = ks * 16;
            uint32_t Ah[2][4], Al[2][4], Bh[4][2], Bl[4][2];
            #pragma unroll
            for (int mt = 0; mt < 2; mt++) {
                const int rb = wm * 32 + mt * 16;
                const int o0 = (rb + g) * 80 + (k0 + 2 * tg) * 2;
                const int o1 = (rb + g + 8) * 80 + (k0 + 2 * tg) * 2;
                Ah[mt][0] = *reinterpret_cast<const uint32_t*>(Xhs + o0);
                Ah[mt][1] = *reinterpret_cast<const uint32_t*>(Xhs + o1);
                Ah[mt][2] = *reinterpret_cast<const uint32_t*>(Xhs + o0 + 16);
                Ah[mt][3] = *reinterpret_cast<const uint32_t*>(Xhs + o1 + 16);
                Al[mt][0] = *reinterpret_cast<const uint32_t*>(Xls + o0);
                Al[mt][1] = *reinterpret_cast<const uint32_t*>(Xls + o1);
                Al[mt][2] = *reinterpret_cast<const uint32_t*>(Xls + o0 + 16);
                Al[mt][3] = *reinterpret_cast<const uint32_t*>(Xls + o1 + 16);
            }
            #pragma unroll
            for (int nt = 0; nt < 4; nt++) {
                const int r = wn * 32 + nt * 8 + g;
                const int boff = r * 80 + (k0 + 2 * tg) * 2;
                Bh[nt][0] = *reinterpret_cast<const uint32_t*>(Whs + boff);
                Bh[nt][1] = *reinterpret_cast<const uint32_t*>(Whs + boff + 16);
                Bl[nt][0] = *reinterpret_cast<const uint32_t*>(Wls + boff);
                Bl[nt][1] = *reinterpret_cast<const uint32_t*>(Wls + boff + 16);
            }
            #pragma unroll
            for (int mt = 0; mt < 2; mt++)
                #pragma unroll
                for (int nt = 0; nt < 4; nt++) {
                    mma16b(acc[mt][nt], Ah[mt], Bh[nt]);   // hi*hi
                    mma16b(acc[mt][nt], Ah[mt], Bl[nt]);   // hi*lo
                    mma16b(acc[mt][nt], Al[mt], Bh[nt]);   // lo*hi
                }
        }
        __syncthreads();
    }
}

// QKV projections fused; outputs fp16 formatted for the fp16 attention:
//  z=0: Q scaled by log2e/tau -> g_qh; z=1: K -> g_kh; z=2: V -> g_vt (transposed).
__global__ __launch_bounds__(256)
void gemm_qkv(const float* __restrict__ taup)
{
    extern __shared__ char smb[];
    const int z = blockIdx.z;
    const float scl = (z == 0) ? (1.4426950408889634f / __ldg(taup)) : 1.0f;

    const int m0 = blockIdx.y * 128, n0 = blockIdx.x * 64;
    float acc[2][4][4] = {};
    gemm_core4(z, smb, m0, n0, acc);

    const int tid = threadIdx.x;
    const int warp = tid >> 5, lane = tid & 31;
    const int g = lane >> 2, tg = lane & 3;
    const int wm = warp >> 1, wn = warp & 1;
    const int h = blockIdx.x;              // BN=64 == head dim

    if (z <= 1) {
        __half* Y = (z == 0) ? g_qh : g_kh;
        #pragma unroll
        for (int mt = 0; mt < 2; mt++) {
            #pragma unroll
            for (int nt = 0; nt < 4; nt++) {
                const int dd = wn * 32 + nt * 8 + 2 * tg;
                int m = m0 + wm * 32 + mt * 16 + g;
                int b = m >> 11, n = m & (N_ - 1);
                *reinterpret_cast<uint32_t*>(&Y[((size_t)((b * H_ + h) * N_ + n)) * D_ + dd]) =
                    packh(acc[mt][nt][1] * scl, acc[mt][nt][0] * scl);
                m += 8; b = m >> 11; n = m & (N_ - 1);
                *reinterpret_cast<uint32_t*>(&Y[((size_t)((b * H_ + h) * N_ + n)) * D_ + dd]) =
                    packh(acc[mt][nt][3] * scl, acc[mt][nt][2] * scl);
            }
        }
    } else {
        // V: transpose 128(m) x 64(d) tile through smem -> g_vt[b][h][d][n]
        __half* ts = reinterpret_cast<__half*>(smb);   // [64][136] halfs
        __syncthreads();
        #pragma unroll
        for (int mt = 0; mt < 2; mt++) {
            #pragma unroll
            for (int nt = 0; nt < 4; nt++) {
                const int dd = wn * 32 + nt * 8 + 2 * tg;
                const int ml = wm * 32 + mt * 16 + g;
                ts[dd * 136 + ml]           = __float2half(acc[mt][nt][0]);
                ts[(dd + 1) * 136 + ml]     = __float2half(acc[mt][nt][1]);
                ts[dd * 136 + ml + 8]       = __float2half(acc[mt][nt][2]);
                ts[(dd + 1) * 136 + ml + 8] = __float2half(acc[mt][nt][3]);
            }
        }
        __syncthreads();
        const int r = tid >> 2, c = tid & 3;
        const int bb = m0 >> 11, noff = m0 & (N_ - 1);
        __half* dst = g_vt + ((size_t)((bb * H_ + h) * D_ + r)) * N_ + noff + c * 32;
        #pragma unroll
        for (int i = 0; i < 4; i++)
            *reinterpret_cast<uint4*>(dst + i * 8) =
                *reinterpret_cast<const uint4*>(&ts[r * 136 + c * 32 + i * 8]);
    }
}

// Output projection: attn_out (slot 3, pre-split) @ Wo^T + bo -> out
__global__ __launch_bounds__(256)
void gemm_out(const float* __restrict__ bias, float* __restrict__ Yext)
{
    extern __shared__ char smb[];
    const int m0 = blockIdx.y * 128, n0 = blockIdx.x * 64;
    float acc[2][4][4] = {};
    gemm_core4(3, smb, m0, n0, acc);

    const int tid = threadIdx.x;
    const int warp = tid >> 5, lane = tid & 31;
    const int g = lane >> 2, tg = lane & 3;
    const int wm = warp >> 1, wn = warp & 1;
    #pragma unroll
    for (int mt = 0; mt < 2; mt++) {
        #pragma unroll
        for (int nt = 0; nt < 4; nt++) {
            const int o = n0 + wn * 32 + nt * 8 + 2 * tg;
            float2 bb = *reinterpret_cast<const float2*>(bias + o);
            const int m = m0 + wm * 32 + mt * 16 + g;
            *reinterpret_cast<float2*>(&Yext[(size_t)m * E_ + o]) =
                make_float2(acc[mt][nt][0] + bb.x, acc[mt][nt][1] + bb.y);
            *reinterpret_cast<float2*>(&Yext[(size_t)(m + 8) * E_ + o]) =
                make_float2(acc[mt][nt][2] + bb.x, acc[mt][nt][3] + bb.y);
        }
    }
}

// ---------------------------------------------------------------------------
// Flash attention v5 (validated): fp16 m16n8k16, 128 q-rows/block, 4 warps x
// 32 rows; K/V fragments shared across both row groups; cp.async double
// buffer; log2 softmax; epilogue writes bf16 hi/lo split (slot 3).
// ---------------------------------------------------------------------------
__global__ __launch_bounds__(128, 2)
void attn_tc(const int* __restrict__ mask)
{
    __shared__ __align__(16) __half sm[2 * BUFH_];

    const int h = blockIdx.x, qt = blockIdx.y, b = blockIdx.z;
    const int tid = threadIdx.x;
    const int warp = tid >> 5, lane = tid & 31;
    const int g = lane >> 2, tg = lane & 3;
    const int q0 = qt * 128;

    const size_t bh = (size_t)(b * H_ + h) * N_ * D_;
    const __half* qbase = g_qh + bh;
    const __half* kbase = g_kh + bh;
    const __half* vtbase = g_vt + bh;
    const int* mbase = mask + (size_t)b * N_ * N_;
    const int* fb0 = g_mflag + (b * NT_ + 2 * qt) * NT_;
    const int* fb1 = fb0 + NT_;

    // Stage Q (128x64 fp16) into smem [128][72]
    {
        #pragma unroll
        for (int i = 0; i < 8; i++) {
            int idx = tid + i * 128;
            int r = idx >> 3, c = (idx & 7) * 8;
            cpb16(&sm[r * KST_ + c], qbase + (size_t)(q0 + r) * D_ + c);
        }
        cp_commit(); cp_wait<0>();
        __syncthreads();
    }

    uint32_t q_a[2][4][4];
    #pragma unroll
    for (int u = 0; u < 2; u++) {
        #pragma unroll
        for (int kc = 0; kc < 4; kc++) {
            const int row = warp * 32 + u * 16 + g;
            q_a[u][kc][0] = *reinterpret_cast<const uint32_t*>(&sm[row * KST_ + kc * 16 + 2 * tg]);
            q_a[u][kc][1] = *reinterpret_cast<const uint32_t*>(&sm[(row + 8) * KST_ + kc * 16 + 2 * tg]);
            q_a[u][kc][2] = *reinterpret_cast<const uint32_t*>(&sm[row * KST_ + kc * 16 + 8 + 2 * tg]);
            q_a[u][kc][3] = *reinterpret_cast<const uint32_t*>(&sm[(row + 8) * KST_ + kc * 16 + 8 + 2 * tg]);
        }
    }
    __syncthreads();

    // Prefetch kv tile 0 into buf 0
    {
        #pragma unroll
        for (int i = 0; i < 2; i++) {
            int idx = tid + i * 128;
            int r = idx >> 3, c = (idx & 7) * 8;
            cpb16(&sm[r * KST_ + c], kbase + (size_t)r * D_ + c);
        }
        #pragma unroll
        for (int i = 0; i < 2; i++) {
            int idx = tid + i * 128;
            int d = idx >> 2, c = (idx & 3) * 8;
            cpb16(&sm[32 * KST_ + d * VST_ + c], vtbase + (size_t)d * N_ + c);
        }
        cp_commit();
    }

    float o[2][8][4] = {};
    float mr[2][2] = {{neg_inf(), neg_inf()}, {neg_inf(), neg_inf()}};
    float lr[2][2] = {};
    int qrow[2];
    qrow[0] = q0 + warp * 32 + g;
    qrow[1] = qrow[0] + 16;

    for (int t = 0; t < NKT_; t++) {
        cp_wait<0>();
        __syncthreads();

        if (t + 1 < NKT_) {
            const __half* kb2 = kbase + (size_t)(t + 1) * KT_ * D_;
            const __half* vb2 = vtbase + (size_t)(t + 1) * KT_;
            __half* dst = sm + ((t + 1) & 1) * BUFH_;
            #pragma unroll
            for (int i = 0; i < 2; i++) {
                int idx = tid + i * 128;
                int r = idx >> 3, c = (idx & 7) * 8;
                cpb16(&dst[r * KST_ + c], kb2 + (size_t)r * D_ + c);
            }
            #pragma unroll
            for (int i = 0; i < 2; i++) {
                int idx = tid + i * 128;
                int d = idx >> 2, c = (idx & 3) * 8;
                cpb16(&dst[32 * KST_ + d * VST_ + c], vb2 + (size_t)d * N_ + c);
            }
            cp_commit();
        }

        const __half* Kc = sm + (t & 1) * BUFH_;
        const __half* Vc = Kc + 32 * KST_;
        const int kv0 = t * KT_;
        const int clean = __ldg(fb0 + (t >> 1)) & __ldg(fb1 + (t >> 1));

        float s[2][4][4] = {};
        #pragma unroll
        for (int kc = 0; kc < 4; kc++) {
            #pragma unroll
            for (int nt = 0; nt < 4; nt++) {
                uint32_t bfr[2];
                const int kb = (nt * 8 + g) * KST_ + kc * 16 + 2 * tg;
                bfr[0] = *reinterpret_cast<const uint32_t*>(&Kc[kb]);
                bfr[1] = *reinterpret_cast<const uint32_t*>(&Kc[kb + 8]);
                mma16h(s[0][nt], q_a[0][kc], bfr);
                mma16h(s[1][nt], q_a[1][kc], bfr);
            }
        }

        if (!clean) {
            #pragma unroll
            for (int u = 0; u < 2; u++) {
                #pragma unroll
                for (int nt = 0; nt < 4; nt++) {
                    const int col = kv0 + nt * 8 + 2 * tg;
                    int2 mA = *reinterpret_cast<const int2*>(mbase + (size_t)qrow[u] * N_ + col);
                    int2 mB = *reinterpret_cast<const int2*>(mbase + (size_t)(qrow[u] + 8) * N_ + col);
                    if (!mA.x) s[u][nt][0] = neg_inf();
                    if (!mA.y) s[u][nt][1] = neg_inf();
                    if (!mB.x) s[u][nt][2] = neg_inf();
                    if (!mB.y) s[u][nt][3] = neg_inf();
                }
            }
        }

        #pragma unroll
        for (int u = 0; u < 2; u++) {
            float mx0 = neg_inf(), mx1 = neg_inf();
            #pragma unroll
            for (int nt = 0; nt < 4; nt++) {
                mx0 = fmaxf(mx0, fmaxf(s[u][nt][0], s[u][nt][1]));
                mx1 = fmaxf(mx1, fmaxf(s[u][nt][2], s[u][nt][3]));
            }
            mx0 = fmaxf(mx0, __shfl_xor_sync(0xffffffffu, mx0, 1));
            mx0 = fmaxf(mx0, __shfl_xor_sync(0xffffffffu, mx0, 2));
            mx1 = fmaxf(mx1, __shfl_xor_sync(0xffffffffu, mx1, 1));
            mx1 = fmaxf(mx1, __shfl_xor_sync(0xffffffffu, mx1, 2));
            const float mn0 = fmaxf(mr[u][0], mx0), mn1 = fmaxf(mr[u][1], mx1);
            const float sc0 = fexp2(fmaxf(mr[u][0] - mn0, -120.0f));
            const float sc1 = fexp2(fmaxf(mr[u][1] - mn1, -120.0f));
            float sum0 = 0.0f, sum1 = 0.0f;
            #pragma unroll
            for (int nt = 0; nt < 4; nt++) {
                float p0 = fexp2(fmaxf(s[u][nt][0] - mn0, -120.0f));
                float p1 = fexp2(fmaxf(s[u][nt][1] - mn0, -120.0f));
                float p2 = fexp2(fmaxf(s[u][nt][2] - mn1, -120.0f));
                float p3 = fexp2(fmaxf(s[u][nt][3] - mn1, -120.0f));
                s[u][nt][0] = p0; s[u][nt][1] = p1; s[u][nt][2] = p2; s[u][nt][3] = p3;
                sum0 += p0 + p1; sum1 += p2 + p3;
            }
            sum0 += __shfl_xor_sync(0xffffffffu, sum0, 1);
            sum0 += __shfl_xor_sync(0xffffffffu, sum0, 2);
            sum1 += __shfl_xor_sync(0xffffffffu, sum1, 1);
            sum1 += __shfl_xor_sync(0xffffffffu, sum1, 2);
            lr[u][0] = lr[u][0] * sc0 + sum0; lr[u][1] = lr[u][1] * sc1 + sum1;
            mr[u][0] = mn0; mr[u][1] = mn1;

            #pragma unroll
            for (int dt = 0; dt < 8; dt++) {
                o[u][dt][0] *= sc0; o[u][dt][1] *= sc0;
                o[u][dt][2] *= sc1; o[u][dt][3] *= sc1;
            }
        }

        #pragma unroll
        for (int kc2 = 0; kc2 < 2; kc2++) {
            const int srcC = (g << 2) | tg;
            uint32_t a[2][4];
            #pragma unroll
            for (int u = 0; u < 2; u++) {
                float v0 = __shfl_sync(0xffffffffu, s[u][kc2 * 2][0], srcC);
                float v1 = __shfl_sync(0xffffffffu, s[u][kc2 * 2][1], srcC);
                float v2 = __shfl_sync(0xffffffffu, s[u][kc2 * 2][2], srcC);
                float v3 = __shfl_sync(0xffffffffu, s[u][kc2 * 2][3], srcC);
                float w0 = __shfl_sync(0xffffffffu, s[u][kc2 * 2 + 1][0], srcC);
                float w1 = __shfl_sync(0xffffffffu, s[u][kc2 * 2 + 1][1], srcC);
                float w2 = __shfl_sync(0xffffffffu, s[u][kc2 * 2 + 1][2], srcC);
                float w3 = __shfl_sync(0xffffffffu, s[u][kc2 * 2 + 1][3], srcC);
                a[u][0] = packh(v1, v0);
                a[u][1] = packh(v3, v2);
                a[u][2] = packh(w1, w0);
                a[u][3] = packh(w3, w2);
            }
            #pragma unroll
            for (int dt = 0; dt < 8; dt++) {
                uint32_t bfr[2];
                const int vb = (dt * 8 + g) * VST_ + kc2 * 16 + 2 * tg;
                bfr[0] = *reinterpret_cast<const uint32_t*>(&Vc[vb]);
                bfr[1] = *reinterpret_cast<const uint32_t*>(&Vc[vb + 8]);
                mma16h(o[0][dt], a[0], bfr);
                mma16h(o[1][dt], a[1], bfr);
            }
        }
    }

    // Epilogue: normalize, recombine heads, write bf16 hi/lo split (slot 3)
    #pragma unroll
    for (int u = 0; u < 2; u++) {
        const float il0 = 1.0f / lr[u][0], il1 = 1.0f / lr[u][1];
        #pragma unroll
        for (int dt = 0; dt < 8; dt++) {
            const int dd = h * 64 + dt * 8 + 2 * tg;
            uint32_t hi, lo;
            pack_split(o[u][dt][0] * il0, o[u][dt][1] * il0, hi, lo);
            const size_t ix0 = (size_t)(b * N_ + qrow[u]) * E_ + dd;
            *reinterpret_cast<uint32_t*>(&g_xbh[3][ix0]) = hi;
            *reinterpret_cast<uint32_t*>(&g_xbl[3][ix0]) = lo;
            pack_split(o[u][dt][2] * il1, o[u][dt][3] * il1, hi, lo);
            const size_t ix1 = (size_t)(b * N_ + qrow[u] + 8) * E_ + dd;
            *reinterpret_cast<uint32_t*>(&g_xbh[3][ix1]) = hi;
            *reinterpret_cast<uint32_t*>(&g_xbl[3][ix1]) = lo;
        }
    }
}

// ---------------------------------------------------------------------------
extern "C" void kernel_launch(void* const* d_in, const int* in_sizes, int n_in,
                              void* d_out, int out_size)
{
    const float* Q    = (const float*)d_in[0];
    const float* K    = (const float*)d_in[1];
    const float* V    = (const float*)d_in[2];
    const int*   mask = (const int*)  d_in[3];
    const float* Wq   = (const float*)d_in[4];
    const float* Wk   = (const float*)d_in[5];
    const float* Wv   = (const float*)d_in[6];
    const float* Wo   = (const float*)d_in[7];
    const float* bo   = (const float*)d_in[8];
    const float* tau  = (const float*)d_in[9];
    float* out = (float*)d_out;

    const int gemm_smem = 2 * GBUF4_;   // 61440

    cudaFuncSetAttribute(gemm_qkv, cudaFuncAttributeMaxDynamicSharedMemorySize, gemm_smem);
    cudaFuncSetAttribute(gemm_out, cudaFuncAttributeMaxDynamicSharedMemorySize, gemm_smem);

    split_w<<<dim3((int)(WBE_ / 1024), 4), 256>>>(Wq, Wk, Wv, Wo);
    split_acts<<<dim3((int)(ACT_ / 1024), 3), 256>>>(Q, K, V);
    mask_flags<<<dim3(NT_, NT_, B_), 256>>>(mask);

    gemm_qkv<<<dim3(E_ / 64, M_ / 128, 3), 256, gemm_smem>>>(tau);

    // grid.x = heads (fastest) so the 8 heads sharing a mask tile are adjacent -> L2 reuse
    attn_tc<<<dim3(H_, N_ / 128, B_), 128>>>(mask);

    gemm_out<<<dim3(E_ / 64, M_ / 128), 256, gemm_smem>>>(bo, out);
}

// round 13
// speedup vs baseline: 1.0708x; 1.0326x over previous
#include <cuda_runtime.h>
#include <cuda_bf16.h>
#include <cuda_fp16.h>
#include <cstdint>
#include <cstddef>

// Problem constants
constexpr int B_ = 8;
constexpr int N_ = 2048;
constexpr int E_ = 512;
constexpr int H_ = 8;
constexpr int D_ = 64;
constexpr int M_ = B_ * N_;   // 16384 rows
constexpr int NT_ = N_ / 64;  // 32 64-row tiles (mask-flag granularity)
constexpr int KT_ = 32;       // attention kv-tile rows
constexpr int NKT_ = N_ / KT_;// 64 kv tiles
constexpr int KST_ = 72;      // K/Q attention smem row stride (halfs)
constexpr int VST_ = 40;      // Vt attention smem row stride (halfs)
constexpr int BUFH_ = 32 * KST_ + 64 * VST_;   // 4864 halfs per KV buffer

constexpr size_t WBE_ = (size_t)E_ * E_;
constexpr size_t ACT_ = (size_t)M_ * E_;

// Scratch (device globals: allocation-free per harness rules)
__device__ __half g_qh[(size_t)B_ * H_ * N_ * D_];  // [b][h][n][d], pre-scaled log2e/tau, fp16
__device__ __half g_kh[(size_t)B_ * H_ * N_ * D_];  // [b][h][n][d] fp16
__device__ __half g_vt[(size_t)B_ * H_ * D_ * N_];  // [b][h][d][n] fp16 (V transposed)
__device__ int    g_mflag[B_ * NT_ * NT_];          // 1 = 64x64 tile all-nonzero
__device__ __nv_bfloat16 g_wbh[4][WBE_];            // bf16 hi parts of Wq,Wk,Wv,Wo
__device__ __nv_bfloat16 g_wbl[4][WBE_];            // bf16 lo parts
// activation hi/lo splits: slots 0..2 = Q,K,V inputs; slot 3 = attention output
__device__ __nv_bfloat16 g_xbh[4][ACT_];
__device__ __nv_bfloat16 g_xbl[4][ACT_];

__device__ __forceinline__ float neg_inf() { return __int_as_float(0xff800000); }

__device__ __forceinline__ float fexp2(float x) {
    float y;
    asm("ex2.approx.ftz.f32 %0, %1;" : "=f"(y) : "f"(x));
    return y;
}

// pack two floats into f16x2 (hi half = first arg)
__device__ __forceinline__ uint32_t packh(float hi, float lo) {
    uint32_t r;
    asm("cvt.rn.f16x2.f32 %0, %1, %2;" : "=r"(r) : "f"(hi), "f"(lo));
    return r;
}

// m16n8k16 bf16 mma (projections)
__device__ __forceinline__ void mma16b(float* c, const uint32_t* a, const uint32_t* b) {
    asm volatile(
        "mma.sync.aligned.m16n8k16.row.col.f32.bf16.bf16.f32 "
        "{%0,%1,%2,%3}, {%4,%5,%6,%7}, {%8,%9}, {%0,%1,%2,%3};\n"
        : "+f"(c[0]), "+f"(c[1]), "+f"(c[2]), "+f"(c[3])
        : "r"(a[0]), "r"(a[1]), "r"(a[2]), "r"(a[3]), "r"(b[0]), "r"(b[1]));
}

// m16n8k16 fp16 mma, fp32 accumulate (attention)
__device__ __forceinline__ void mma16h(float* c, const uint32_t* a, const uint32_t* b) {
    asm volatile(
        "mma.sync.aligned.m16n8k16.row.col.f32.f16.f16.f32 "
        "{%0,%1,%2,%3}, {%4,%5,%6,%7}, {%8,%9}, {%0,%1,%2,%3};\n"
        : "+f"(c[0]), "+f"(c[1]), "+f"(c[2]), "+f"(c[3])
        : "r"(a[0]), "r"(a[1]), "r"(a[2]), "r"(a[3]), "r"(b[0]), "r"(b[1]));
}

// pack two floats into bf16x2 hi + residual lo (memory order: low half = x0)
__device__ __forceinline__ void pack_split(float x0, float x1, uint32_t& hi, uint32_t& lo) {
    asm("cvt.rn.bf16x2.f32 %0, %1, %2;" : "=r"(hi) : "f"(x1), "f"(x0));
    float h0 = __uint_as_float(hi << 16);
    float h1 = __uint_as_float(hi & 0xffff0000u);
    asm("cvt.rn.bf16x2.f32 %0, %1, %2;" : "=r"(lo) : "f"(x1 - h1), "f"(x0 - h0));
}

// cp.async helpers
__device__ __forceinline__ void cpb16(const void* smem_dst, const void* gmem_src) {
    uint32_t s = (uint32_t)__cvta_generic_to_shared(smem_dst);
    asm volatile("cp.async.ca.shared.global [%0], [%1], 16;" :: "r"(s), "l"(gmem_src));
}
__device__ __forceinline__ void cp_commit() { asm volatile("cp.async.commit_group;"); }
template<int N>
__device__ __forceinline__ void cp_wait() { asm volatile("cp.async.wait_group %0;" :: "n"(N) : "memory"); }

// ---------------------------------------------------------------------------
// One-time splits: weights and activations -> (hi, lo) bf16 pairs.
// ---------------------------------------------------------------------------
__global__ __launch_bounds__(256)
void split_w(const float* __restrict__ Wq, const float* __restrict__ Wk,
             const float* __restrict__ Wv, const float* __restrict__ Wo)
{
    const int m = blockIdx.y;
    const float* W = (m == 0) ? Wq : (m == 1) ? Wk : (m == 2) ? Wv : Wo;
    const size_t i4 = ((size_t)blockIdx.x * 256 + threadIdx.x) * 4;
    float4 v = *reinterpret_cast<const float4*>(W + i4);
    uint32_t h01, l01, h23, l23;
    pack_split(v.x, v.y, h01, l01);
    pack_split(v.z, v.w, h23, l23);
    *reinterpret_cast<uint2*>(&g_wbh[m][i4]) = make_uint2(h01, h23);
    *reinterpret_cast<uint2*>(&g_wbl[m][i4]) = make_uint2(l01, l23);
}

__global__ __launch_bounds__(256)
void split_acts(const float* __restrict__ Q, const float* __restrict__ K,
                const float* __restrict__ V)
{
    const int z = blockIdx.y;
    const float* X = (z == 0) ? Q : (z == 1) ? K : V;
    const size_t i4 = ((size_t)blockIdx.x * 256 + threadIdx.x) * 4;
    float4 v = *reinterpret_cast<const float4*>(X + i4);
    uint32_t h01, l01, h23, l23;
    pack_split(v.x, v.y, h01, l01);
    pack_split(v.z, v.w, h23, l23);
    *reinterpret_cast<uint2*>(&g_xbh[z][i4]) = make_uint2(h01, h23);
    *reinterpret_cast<uint2*>(&g_xbl[z][i4]) = make_uint2(l01, l23);
}

// ---------------------------------------------------------------------------
// Mask preprocessing: one flag per (b, 64-row q tile, 64-col kv tile).
// ---------------------------------------------------------------------------
__global__ __launch_bounds__(256)
void mask_flags(const int* __restrict__ mask)
{
    const int kvt = blockIdx.x, qt = blockIdx.y, b = blockIdx.z;
    const int tid = threadIdx.x;
    const int r = tid >> 2, c0 = (tid & 3) * 16;
    const int* base = mask + (size_t)b * N_ * N_ + (size_t)(qt * 64 + r) * N_ + kvt * 64 + c0;
    bool ok = true;
    #pragma unroll
    for (int i = 0; i < 4; i++) {
        int4 m = *reinterpret_cast<const int4*>(base + i * 4);
        ok &= (m.x != 0) & (m.y != 0) & (m.z != 0) & (m.w != 0);
    }
    int all = __syncthreads_and((int)ok);
    if (tid == 0) g_mflag[(b * NT_ + qt) * NT_ + kvt] = all;
}

// ---------------------------------------------------------------------------
// GEMM core v4c: Y = (Xh+Xl) @ (Wh+Wl)^T, bf16 3-term, m16n8k16, all operands
// pre-split bf16 in smem, stride 40 halfs (conflict-free frag LDS, 30720B/buf
// -> 3 CTAs/SM). ONE barrier per kt iteration (attention-loop structure):
//   wait<0> -> syncthreads -> prefetch(kt+1) -> compute(kt)
// Safe because buf[kt+1] == buf[kt-1] and all its readers passed the sync.
// Block 128x64, BK=32, 256 thr = 8 warps (4m x 2n), warp 32x32.
// ---------------------------------------------------------------------------
constexpr int GST_ = 40;                    // gemm smem row stride (halfs)
constexpr int XTB_ = 128 * GST_ * 2;        // one X tile bytes (bf16)  = 10240
constexpr int WTB_ = 64 * GST_ * 2;         // one W tile bytes (bf16)  = 5120
constexpr int GBUF4_ = 2 * XTB_ + 2 * WTB_; // 30720 B per buffer
constexpr int GKT_ = E_ / 32;               // 16 k tiles

__device__ __forceinline__ void gemm_prefetch4(int slot, char* buf, int m0, int n0, int kt)
{
    const int tid = threadIdx.x;
    char* xh = buf;
    char* xl = buf + XTB_;
    char* wh = buf + 2 * XTB_;
    char* wl = wh + WTB_;
    // X: 128 rows x 32 bf16 = 64B/row = 4 chunks; 512 chunks each for hi/lo
    #pragma unroll
    for (int i = 0; i < 2; i++) {
        int idx = tid + i * 256;
        int r = idx >> 2, c = idx & 3;
        const size_t src = (size_t)(m0 + r) * E_ + kt * 32 + c * 8;
        cpb16(xh + r * 80 + c * 16, &g_xbh[slot][src]);
        cpb16(xl + r * 80 + c * 16, &g_xbl[slot][src]);
    }
    // W: 64 rows x 32 bf16; 256 chunks each for hi/lo
    {
        int r = tid >> 2, c = tid & 3;
        const size_t src = (size_t)(n0 + r) * E_ + kt * 32 + c * 8;
        cpb16(wh + r * 80 + c * 16, &g_wbh[slot][src]);
        cpb16(wl + r * 80 + c * 16, &g_wbl[slot][src]);
    }
    cp_commit();
}

__device__ __forceinline__ void gemm_core4(int slot, char* smb, int m0, int n0,
                                           float acc[2][4][4])
{
    const int tid = threadIdx.x;
    const int warp = tid >> 5, lane = tid & 31;
    const int g = lane >> 2, tg = lane & 3;
    const int wm = warp >> 1, wn = warp & 1;

    gemm_prefetch4(slot, smb, m0, n0, 0);

    for (int kt = 0; kt < GKT_; kt++) {
        cp_wait<0>();        // buf[kt] resident (only its group was outstanding)
        __syncthreads();     // also: all warps done reading buf[kt-1] == buf[kt+1]
        if (kt + 1 < GKT_)
            gemm_prefetch4(slot, smb + ((kt + 1) & 1) * GBUF4_, m0, n0, kt + 1);

        const char* buf = smb + (kt & 1) * GBUF4_;
        const char* Xhs = buf;
        const char* Xls = buf + XTB_;
        const char* Whs = buf + 2 * XTB_;
        const char* Wls = Whs + WTB_;

        #pragma unroll
        for (int ks = 0; ks < 2; ks++) {
            const int k0 = ks * 16;
            uint32_t Ah[2][4], Al[2][4], Bh[4][2], Bl[4][2];
            #pragma unroll
            for (int mt = 0; mt < 2; mt++) {
                const int rb = wm * 32 + mt * 16;
                const int o0 = (rb + g) * 80 + (k0 + 2 * tg) * 2;
                const int o1 = (rb + g + 8) * 80 + (k0 + 2 * tg) * 2;
                Ah[mt][0] = *reinterpret_cast<const uint32_t*>(Xhs + o0);
                Ah[mt][1] = *reinterpret_cast<const uint32_t*>(Xhs + o1);
                Ah[mt][2] = *reinterpret_cast<const uint32_t*>(Xhs + o0 + 16);
                Ah[mt][3] = *reinterpret_cast<const uint32_t*>(Xhs + o1 + 16);
                Al[mt][0] = *reinterpret_cast<const uint32_t*>(Xls + o0);
                Al[mt][1] = *reinterpret_cast<const uint32_t*>(Xls + o1);
                Al[mt][2] = *reinterpret_cast<const uint32_t*>(Xls + o0 + 16);
                Al[mt][3] = *reinterpret_cast<const uint32_t*>(Xls + o1 + 16);
            }
            #pragma unroll
            for (int nt = 0; nt < 4; nt++) {
                const int r = wn * 32 + nt * 8 + g;
                const int boff = r * 80 + (k0 + 2 * tg) * 2;
                Bh[nt][0] = *reinterpret_cast<const uint32_t*>(Whs + boff);
                Bh[nt][1] = *reinterpret_cast<const uint32_t*>(Whs + boff + 16);
                Bl[nt][0] = *reinterpret_cast<const uint32_t*>(Wls + boff);
                Bl[nt][1] = *reinterpret_cast<const uint32_t*>(Wls + boff + 16);
            }
            #pragma unroll
            for (int mt = 0; mt < 2; mt++)
                #pragma unroll
                for (int nt = 0; nt < 4; nt++) {
                    mma16b(acc[mt][nt], Ah[mt], Bh[nt]);   // hi*hi
                    mma16b(acc[mt][nt], Ah[mt], Bl[nt]);   // hi*lo
                    mma16b(acc[mt][nt], Al[mt], Bh[nt]);   // lo*hi
                }
        }
    }
}

// QKV projections fused; outputs fp16 formatted for the fp16 attention:
//  z=0: Q scaled by log2e/tau -> g_qh; z=1: K -> g_kh; z=2: V -> g_vt (transposed).
__global__ __launch_bounds__(256)
void gemm_qkv(const float* __restrict__ taup)
{
    extern __shared__ char smb[];
    const int z = blockIdx.z;
    const float scl = (z == 0) ? (1.4426950408889634f / __ldg(taup)) : 1.0f;

    const int m0 = blockIdx.y * 128, n0 = blockIdx.x * 64;
    float acc[2][4][4] = {};
    gemm_core4(z, smb, m0, n0, acc);

    const int tid = threadIdx.x;
    const int warp = tid >> 5, lane = tid & 31;
    const int g = lane >> 2, tg = lane & 3;
    const int wm = warp >> 1, wn = warp & 1;
    const int h = blockIdx.x;              // BN=64 == head dim

    if (z <= 1) {
        __half* Y = (z == 0) ? g_qh : g_kh;
        #pragma unroll
        for (int mt = 0; mt < 2; mt++) {
            #pragma unroll
            for (int nt = 0; nt < 4; nt++) {
                const int dd = wn * 32 + nt * 8 + 2 * tg;
                int m = m0 + wm * 32 + mt * 16 + g;
                int b = m >> 11, n = m & (N_ - 1);
                *reinterpret_cast<uint32_t*>(&Y[((size_t)((b * H_ + h) * N_ + n)) * D_ + dd]) =
                    packh(acc[mt][nt][1] * scl, acc[mt][nt][0] * scl);
                m += 8; b = m >> 11; n = m & (N_ - 1);
                *reinterpret_cast<uint32_t*>(&Y[((size_t)((b * H_ + h) * N_ + n)) * D_ + dd]) =
                    packh(acc[mt][nt][3] * scl, acc[mt][nt][2] * scl);
            }
        }
    } else {
        // V: transpose 128(m) x 64(d) tile through smem -> g_vt[b][h][d][n]
        __half* ts = reinterpret_cast<__half*>(smb);   // [64][136] halfs
        __syncthreads();
        #pragma unroll
        for (int mt = 0; mt < 2; mt++) {
            #pragma unroll
            for (int nt = 0; nt < 4; nt++) {
                const int dd = wn * 32 + nt * 8 + 2 * tg;
                const int ml = wm * 32 + mt * 16 + g;
                ts[dd * 136 + ml]           = __float2half(acc[mt][nt][0]);
                ts[(dd + 1) * 136 + ml]     = __float2half(acc[mt][nt][1]);
                ts[dd * 136 + ml + 8]       = __float2half(acc[mt][nt][2]);
                ts[(dd + 1) * 136 + ml + 8] = __float2half(acc[mt][nt][3]);
            }
        }
        __syncthreads();
        const int r = tid >> 2, c = tid & 3;
        const int bb = m0 >> 11, noff = m0 & (N_ - 1);
        __half* dst = g_vt + ((size_t)((bb * H_ + h) * D_ + r)) * N_ + noff + c * 32;
        #pragma unroll
        for (int i = 0; i < 4; i++)
            *reinterpret_cast<uint4*>(dst + i * 8) =
                *reinterpret_cast<const uint4*>(&ts[r * 136 + c * 32 + i * 8]);
    }
}

// Output projection: attn_out (slot 3, pre-split) @ Wo^T + bo -> out
__global__ __launch_bounds__(256)
void gemm_out(const float* __restrict__ bias, float* __restrict__ Yext)
{
    extern __shared__ char smb[];
    const int m0 = blockIdx.y * 128, n0 = blockIdx.x * 64;
    float acc[2][4][4] = {};
    gemm_core4(3, smb, m0, n0, acc);

    const int tid = threadIdx.x;
    const int warp = tid >> 5, lane = tid & 31;
    const int g = lane >> 2, tg = lane & 3;
    const int wm = warp >> 1, wn = warp & 1;
    #pragma unroll
    for (int mt = 0; mt < 2; mt++) {
        #pragma unroll
        for (int nt = 0; nt < 4; nt++) {
            const int o = n0 + wn * 32 + nt * 8 + 2 * tg;
            float2 bb = *reinterpret_cast<const float2*>(bias + o);
            const int m = m0 + wm * 32 + mt * 16 + g;
            *reinterpret_cast<float2*>(&Yext[(size_t)m * E_ + o]) =
                make_float2(acc[mt][nt][0] + bb.x, acc[mt][nt][1] + bb.y);
            *reinterpret_cast<float2*>(&Yext[(size_t)(m + 8) * E_ + o]) =
                make_float2(acc[mt][nt][2] + bb.x, acc[mt][nt][3] + bb.y);
        }
    }
}

// ---------------------------------------------------------------------------
// Flash attention v5 (validated): fp16 m16n8k16, 128 q-rows/block, 4 warps x
// 32 rows; K/V fragments shared across both row groups; cp.async double
// buffer; log2 softmax; epilogue writes bf16 hi/lo split (slot 3).
// ---------------------------------------------------------------------------
__global__ __launch_bounds__(128, 2)
void attn_tc(const int* __restrict__ mask)
{
    __shared__ __align__(16) __half sm[2 * BUFH_];

    const int h = blockIdx.x, qt = blockIdx.y, b = blockIdx.z;
    const int tid = threadIdx.x;
    const int warp = tid >> 5, lane = tid & 31;
    const int g = lane >> 2, tg = lane & 3;
    const int q0 = qt * 128;

    const size_t bh = (size_t)(b * H_ + h) * N_ * D_;
    const __half* qbase = g_qh + bh;
    const __half* kbase = g_kh + bh;
    const __half* vtbase = g_vt + bh;
    const int* mbase = mask + (size_t)b * N_ * N_;
    const int* fb0 = g_mflag + (b * NT_ + 2 * qt) * NT_;
    const int* fb1 = fb0 + NT_;

    // Stage Q (128x64 fp16) into smem [128][72]
    {
        #pragma unroll
        for (int i = 0; i < 8; i++) {
            int idx = tid + i * 128;
            int r = idx >> 3, c = (idx & 7) * 8;
            cpb16(&sm[r * KST_ + c], qbase + (size_t)(q0 + r) * D_ + c);
        }
        cp_commit(); cp_wait<0>();
        __syncthreads();
    }

    uint32_t q_a[2][4][4];
    #pragma unroll
    for (int u = 0; u < 2; u++) {
        #pragma unroll
        for (int kc = 0; kc < 4; kc++) {
            const int row = warp * 32 + u * 16 + g;
            q_a[u][kc][0] = *reinterpret_cast<const uint32_t*>(&sm[row * KST_ + kc * 16 + 2 * tg]);
            q_a[u][kc][1] = *reinterpret_cast<const uint32_t*>(&sm[(row + 8) * KST_ + kc * 16 + 2 * tg]);
            q_a[u][kc][2] = *reinterpret_cast<const uint32_t*>(&sm[row * KST_ + kc * 16 + 8 + 2 * tg]);
            q_a[u][kc][3] = *reinterpret_cast<const uint32_t*>(&sm[(row + 8) * KST_ + kc * 16 + 8 + 2 * tg]);
        }
    }
    __syncthreads();

    // Prefetch kv tile 0 into buf 0
    {
        #pragma unroll
        for (int i = 0; i < 2; i++) {
            int idx = tid + i * 128;
            int r = idx >> 3, c = (idx & 7) * 8;
            cpb16(&sm[r * KST_ + c], kbase + (size_t)r * D_ + c);
        }
        #pragma unroll
        for (int i = 0; i < 2; i++) {
            int idx = tid + i * 128;
            int d = idx >> 2, c = (idx & 3) * 8;
            cpb16(&sm[32 * KST_ + d * VST_ + c], vtbase + (size_t)d * N_ + c);
        }
        cp_commit();
    }

    float o[2][8][4] = {};
    float mr[2][2] = {{neg_inf(), neg_inf()}, {neg_inf(), neg_inf()}};
    float lr[2][2] = {};
    int qrow[2];
    qrow[0] = q0 + warp * 32 + g;
    qrow[1] = qrow[0] + 16;

    for (int t = 0; t < NKT_; t++) {
        cp_wait<0>();
        __syncthreads();

        if (t + 1 < NKT_) {
            const __half* kb2 = kbase + (size_t)(t + 1) * KT_ * D_;
            const __half* vb2 = vtbase + (size_t)(t + 1) * KT_;
            __half* dst = sm + ((t + 1) & 1) * BUFH_;
            #pragma unroll
            for (int i = 0; i < 2; i++) {
                int idx = tid + i * 128;
                int r = idx >> 3, c = (idx & 7) * 8;
                cpb16(&dst[r * KST_ + c], kb2 + (size_t)r * D_ + c);
            }
            #pragma unroll
            for (int i = 0; i < 2; i++) {
                int idx = tid + i * 128;
                int d = idx >> 2, c = (idx & 3) * 8;
                cpb16(&dst[32 * KST_ + d * VST_ + c], vb2 + (size_t)d * N_ + c);
            }
            cp_commit();
        }

        const __half* Kc = sm + (t & 1) * BUFH_;
        const __half* Vc = Kc + 32 * KST_;
        const int kv0 = t * KT_;
        const int clean = __ldg(fb0 + (t >> 1)) & __ldg(fb1 + (t >> 1));

        float s[2][4][4] = {};
        #pragma unroll
        for (int kc = 0; kc < 4; kc++) {
            #pragma unroll
            for (int nt = 0; nt < 4; nt++) {
                uint32_t bfr[2];
                const int kb = (nt * 8 + g) * KST_ + kc * 16 + 2 * tg;
                bfr[0] = *reinterpret_cast<const uint32_t*>(&Kc[kb]);
                bfr[1] = *reinterpret_cast<const uint32_t*>(&Kc[kb + 8]);
                mma16h(s[0][nt], q_a[0][kc], bfr);
                mma16h(s[1][nt], q_a[1][kc], bfr);
            }
        }

        if (!clean) {
            #pragma unroll
            for (int u = 0; u < 2; u++) {
                #pragma unroll
                for (int nt = 0; nt < 4; nt++) {
                    const int col = kv0 + nt * 8 + 2 * tg;
                    int2 mA = *reinterpret_cast<const int2*>(mbase + (size_t)qrow[u] * N_ + col);
                    int2 mB = *reinterpret_cast<const int2*>(mbase + (size_t)(qrow[u] + 8) * N_ + col);
                    if (!mA.x) s[u][nt][0] = neg_inf();
                    if (!mA.y) s[u][nt][1] = neg_inf();
                    if (!mB.x) s[u][nt][2] = neg_inf();
                    if (!mB.y) s[u][nt][3] = neg_inf();
                }
            }
        }

        #pragma unroll
        for (int u = 0; u < 2; u++) {
            float mx0 = neg_inf(), mx1 = neg_inf();
            #pragma unroll
            for (int nt = 0; nt < 4; nt++) {
                mx0 = fmaxf(mx0, fmaxf(s[u][nt][0], s[u][nt][1]));
                mx1 = fmaxf(mx1, fmaxf(s[u][nt][2], s[u][nt][3]));
            }
            mx0 = fmaxf(mx0, __shfl_xor_sync(0xffffffffu, mx0, 1));
            mx0 = fmaxf(mx0, __shfl_xor_sync(0xffffffffu, mx0, 2));
            mx1 = fmaxf(mx1, __shfl_xor_sync(0xffffffffu, mx1, 1));
            mx1 = fmaxf(mx1, __shfl_xor_sync(0xffffffffu, mx1, 2));
            const float mn0 = fmaxf(mr[u][0], mx0), mn1 = fmaxf(mr[u][1], mx1);
            const float sc0 = fexp2(fmaxf(mr[u][0] - mn0, -120.0f));
            const float sc1 = fexp2(fmaxf(mr[u][1] - mn1, -120.0f));
            float sum0 = 0.0f, sum1 = 0.0f;
            #pragma unroll
            for (int nt = 0; nt < 4; nt++) {
                float p0 = fexp2(fmaxf(s[u][nt][0] - mn0, -120.0f));
                float p1 = fexp2(fmaxf(s[u][nt][1] - mn0, -120.0f));
                float p2 = fexp2(fmaxf(s[u][nt][2] - mn1, -120.0f));
                float p3 = fexp2(fmaxf(s[u][nt][3] - mn1, -120.0f));
                s[u][nt][0] = p0; s[u][nt][1] = p1; s[u][nt][2] = p2; s[u][nt][3] = p3;
                sum0 += p0 + p1; sum1 += p2 + p3;
            }
            sum0 += __shfl_xor_sync(0xffffffffu, sum0, 1);
            sum0 += __shfl_xor_sync(0xffffffffu, sum0, 2);
            sum1 += __shfl_xor_sync(0xffffffffu, sum1, 1);
            sum1 += __shfl_xor_sync(0xffffffffu, sum1, 2);
            lr[u][0] = lr[u][0] * sc0 + sum0; lr[u][1] = lr[u][1] * sc1 + sum1;
            mr[u][0] = mn0; mr[u][1] = mn1;

            #pragma unroll
            for (int dt = 0; dt < 8; dt++) {
                o[u][dt][0] *= sc0; o[u][dt][1] *= sc0;
                o[u][dt][2] *= sc1; o[u][dt][3] *= sc1;
            }
        }

        #pragma unroll
        for (int kc2 = 0; kc2 < 2; kc2++) {
            const int srcC = (g << 2) | tg;
            uint32_t a[2][4];
            #pragma unroll
            for (int u = 0; u < 2; u++) {
                float v0 = __shfl_sync(0xffffffffu, s[u][kc2 * 2][0], srcC);
                float v1 = __shfl_sync(0xffffffffu, s[u][kc2 * 2][1], srcC);
                float v2 = __shfl_sync(0xffffffffu, s[u][kc2 * 2][2], srcC);
                float v3 = __shfl_sync(0xffffffffu, s[u][kc2 * 2][3], srcC);
                float w0 = __shfl_sync(0xffffffffu, s[u][kc2 * 2 + 1][0], srcC);
                float w1 = __shfl_sync(0xffffffffu, s[u][kc2 * 2 + 1][1], srcC);
                float w2 = __shfl_sync(0xffffffffu, s[u][kc2 * 2 + 1][2], srcC);
                float w3 = __shfl_sync(0xffffffffu, s[u][kc2 * 2 + 1][3], srcC);
                a[u][0] = packh(v1, v0);
                a[u][1] = packh(v3, v2);
                a[u][2] = packh(w1, w0);
                a[u][3] = packh(w3, w2);
            }
            #pragma unroll
            for (int dt = 0; dt < 8; dt++) {
                uint32_t bfr[2];
                const int vb = (dt * 8 + g) * VST_ + kc2 * 16 + 2 * tg;
                bfr[0] = *reinterpret_cast<const uint32_t*>(&Vc[vb]);
                bfr[1] = *reinterpret_cast<const uint32_t*>(&Vc[vb + 8]);
                mma16h(o[0][dt], a[0], bfr);
                mma16h(o[1][dt], a[1], bfr);
            }
        }
    }

    // Epilogue: normalize, recombine heads, write bf16 hi/lo split (slot 3)
    #pragma unroll
    for (int u = 0; u < 2; u++) {
        const float il0 = 1.0f / lr[u][0], il1 = 1.0f / lr[u][1];
        #pragma unroll
        for (int dt = 0; dt < 8; dt++) {
            const int dd = h * 64 + dt * 8 + 2 * tg;
            uint32_t hi, lo;
            pack_split(o[u][dt][0] * il0, o[u][dt][1] * il0, hi, lo);
            const size_t ix0 = (size_t)(b * N_ + qrow[u]) * E_ + dd;
            *reinterpret_cast<uint32_t*>(&g_xbh[3][ix0]) = hi;
            *reinterpret_cast<uint32_t*>(&g_xbl[3][ix0]) = lo;
            pack_split(o[u][dt][2] * il1, o[u][dt][3] * il1, hi, lo);
            const size_t ix1 = (size_t)(b * N_ + qrow[u] + 8) * E_ + dd;
            *reinterpret_cast<uint32_t*>(&g_xbh[3][ix1]) = hi;
            *reinterpret_cast<uint32_t*>(&g_xbl[3][ix1]) = lo;
        }
    }
}

// ---------------------------------------------------------------------------
extern "C" void kernel_launch(void* const* d_in, const int* in_sizes, int n_in,
                              void* d_out, int out_size)
{
    const float* Q    = (const float*)d_in[0];
    const float* K    = (const float*)d_in[1];
    const float* V    = (const float*)d_in[2];
    const int*   mask = (const int*)  d_in[3];
    const float* Wq   = (const float*)d_in[4];
    const float* Wk   = (const float*)d_in[5];
    const float* Wv   = (const float*)d_in[6];
    const float* Wo   = (const float*)d_in[7];
    const float* bo   = (const float*)d_in[8];
    const float* tau  = (const float*)d_in[9];
    float* out = (float*)d_out;

    const int gemm_smem = 2 * GBUF4_;   // 61440

    cudaFuncSetAttribute(gemm_qkv, cudaFuncAttributeMaxDynamicSharedMemorySize, gemm_smem);
    cudaFuncSetAttribute(gemm_out, cudaFuncAttributeMaxDynamicSharedMemorySize, gemm_smem);

    split_w<<<dim3((int)(WBE_ / 1024), 4), 256>>>(Wq, Wk, Wv, Wo);
    split_acts<<<dim3((int)(ACT_ / 1024), 3), 256>>>(Q, K, V);
    mask_flags<<<dim3(NT_, NT_, B_), 256>>>(mask);

    gemm_qkv<<<dim3(E_ / 64, M_ / 128, 3), 256, gemm_smem>>>(tau);

    // grid.x = heads (fastest) so the 8 heads sharing a mask tile are adjacent -> L2 reuse
    attn_tc<<<dim3(H_, N_ / 128, B_), 128>>>(mask);

    gemm_out<<<dim3(E_ / 64, M_ / 128), 256, gemm_smem>>>(bo, out);
}

// round 14
// speedup vs baseline: 1.1728x; 1.0952x over previous
#include <cuda_runtime.h>
#include <cuda_bf16.h>
#include <cuda_fp16.h>
#include <cstdint>
#include <cstddef>

// Problem constants
constexpr int B_ = 8;
constexpr int N_ = 2048;
constexpr int E_ = 512;
constexpr int H_ = 8;
constexpr int D_ = 64;
constexpr int M_ = B_ * N_;   // 16384 rows
constexpr int NT_ = N_ / 64;  // 32 64-row tiles (mask-flag granularity)
constexpr int KT_ = 64;       // attention kv-tile rows (doubled vs R10)
constexpr int NKT_ = N_ / KT_;// 32 kv tiles
constexpr int KST_ = 72;      // K/Q attention smem row stride (halfs), conflict-free
constexpr int VST_ = 72;      // Vt attention smem row stride (halfs), conflict-free
constexpr int BUFH_ = KT_ * KST_ + 64 * VST_;  // 9216 halfs per KV buffer

constexpr size_t WBE_ = (size_t)E_ * E_;

// Scratch (device globals: allocation-free per harness rules)
__device__ __half g_qh[(size_t)B_ * H_ * N_ * D_];  // [b][h][n][d], pre-scaled log2e/tau, fp16
__device__ __half g_kh[(size_t)B_ * H_ * N_ * D_];  // [b][h][n][d] fp16
__device__ __half g_vt[(size_t)B_ * H_ * D_ * N_];  // [b][h][d][n] fp16 (V transposed)
__device__ float  g_att[(size_t)M_ * E_];           // [b*n][h*d] recombined heads (fp32)
__device__ int    g_mflag[B_ * NT_ * NT_];          // 1 = 64x64 tile all-nonzero
__device__ __nv_bfloat16 g_wbh[4][WBE_];            // bf16 hi parts of Wq,Wk,Wv,Wo
__device__ __nv_bfloat16 g_wbl[4][WBE_];            // bf16 lo parts

__device__ __forceinline__ float neg_inf() { return __int_as_float(0xff800000); }

__device__ __forceinline__ float fexp2(float x) {
    float y;
    asm("ex2.approx.ftz.f32 %0, %1;" : "=f"(y) : "f"(x));
    return y;
}

// pack two floats into f16x2 (hi half = first arg)
__device__ __forceinline__ uint32_t packh(float hi, float lo) {
    uint32_t r;
    asm("cvt.rn.f16x2.f32 %0, %1, %2;" : "=r"(r) : "f"(hi), "f"(lo));
    return r;
}

// m16n8k16 bf16 mma (projections)
__device__ __forceinline__ void mma16b(float* c, const uint32_t* a, const uint32_t* b) {
    asm volatile(
        "mma.sync.aligned.m16n8k16.row.col.f32.bf16.bf16.f32 "
        "{%0,%1,%2,%3}, {%4,%5,%6,%7}, {%8,%9}, {%0,%1,%2,%3};\n"
        : "+f"(c[0]), "+f"(c[1]), "+f"(c[2]), "+f"(c[3])
        : "r"(a[0]), "r"(a[1]), "r"(a[2]), "r"(a[3]), "r"(b[0]), "r"(b[1]));
}

// m16n8k16 fp16 mma, fp32 accumulate (attention)
__device__ __forceinline__ void mma16h(float* c, const uint32_t* a, const uint32_t* b) {
    asm volatile(
        "mma.sync.aligned.m16n8k16.row.col.f32.f16.f16.f32 "
        "{%0,%1,%2,%3}, {%4,%5,%6,%7}, {%8,%9}, {%0,%1,%2,%3};\n"
        : "+f"(c[0]), "+f"(c[1]), "+f"(c[2]), "+f"(c[3])
        : "r"(a[0]), "r"(a[1]), "r"(a[2]), "r"(a[3]), "r"(b[0]), "r"(b[1]));
}

// pack two floats into bf16x2 hi + residual lo (memory order: low half = x0)
__device__ __forceinline__ void pack_split(float x0, float x1, uint32_t& hi, uint32_t& lo) {
    asm("cvt.rn.bf16x2.f32 %0, %1, %2;" : "=r"(hi) : "f"(x1), "f"(x0));
    float h0 = __uint_as_float(hi << 16);
    float h1 = __uint_as_float(hi & 0xffff0000u);
    asm("cvt.rn.bf16x2.f32 %0, %1, %2;" : "=r"(lo) : "f"(x1 - h1), "f"(x0 - h0));
}

// cp.async helpers
__device__ __forceinline__ void cpb16(const void* smem_dst, const void* gmem_src) {
    uint32_t s = (uint32_t)__cvta_generic_to_shared(smem_dst);
    asm volatile("cp.async.ca.shared.global [%0], [%1], 16;" :: "r"(s), "l"(gmem_src));
}
__device__ __forceinline__ void cp_commit() { asm volatile("cp.async.commit_group;"); }
template<int N>
__device__ __forceinline__ void cp_wait() { asm volatile("cp.async.wait_group %0;" :: "n"(N) : "memory"); }

// ---------------------------------------------------------------------------
// One-time weight split: W -> (hi, lo) bf16 pair. blockIdx.y selects matrix.
// ---------------------------------------------------------------------------
__global__ __launch_bounds__(256)
void split_w(const float* __restrict__ Wq, const float* __restrict__ Wk,
             const float* __restrict__ Wv, const float* __restrict__ Wo)
{
    const int m = blockIdx.y;
    const float* W = (m == 0) ? Wq : (m == 1) ? Wk : (m == 2) ? Wv : Wo;
    const size_t i4 = ((size_t)blockIdx.x * 256 + threadIdx.x) * 4;
    float4 v = *reinterpret_cast<const float4*>(W + i4);
    uint32_t h01, l01, h23, l23;
    pack_split(v.x, v.y, h01, l01);
    pack_split(v.z, v.w, h23, l23);
    *reinterpret_cast<uint2*>(&g_wbh[m][i4]) = make_uint2(h01, h23);
    *reinterpret_cast<uint2*>(&g_wbl[m][i4]) = make_uint2(l01, l23);
}

// ---------------------------------------------------------------------------
// Mask preprocessing: one flag per (b, 64-row q tile, 64-col kv tile).
// ---------------------------------------------------------------------------
__global__ __launch_bounds__(256)
void mask_flags(const int* __restrict__ mask)
{
    const int kvt = blockIdx.x, qt = blockIdx.y, b = blockIdx.z;
    const int tid = threadIdx.x;
    const int r = tid >> 2, c0 = (tid & 3) * 16;
    const int* base = mask + (size_t)b * N_ * N_ + (size_t)(qt * 64 + r) * N_ + kvt * 64 + c0;
    bool ok = true;
    #pragma unroll
    for (int i = 0; i < 4; i++) {
        int4 m = *reinterpret_cast<const int4*>(base + i * 4);
        ok &= (m.x != 0) & (m.y != 0) & (m.z != 0) & (m.w != 0);
    }
    int all = __syncthreads_and((int)ok);
    if (tid == 0) g_mflag[(b * NT_ + qt) * NT_ + kvt] = all;
}

// ---------------------------------------------------------------------------
// GEMM core (R10 champion config): Y = (Xh+Xl)@(Wh+Wl)^T, bf16 3-term,
// m16n8k16. X fp32 in smem (stride 36, split in regs); W pre-split bf16
// (stride 56, conflict-free). cp.async double buffer, 2 barriers/kt.
// Block 128x64, BK=32, 256 thr = 8 warps (4m x 2n), warp 32x32.
// ---------------------------------------------------------------------------
constexpr int GXB_ = 128 * 36 * 4;          // X tile bytes (fp32)
constexpr int GWB_ = 64 * 56 * 2;           // one W tile bytes (bf16, stride 56)
constexpr int GBUFB_ = GXB_ + 2 * GWB_;     // 32768 B per buffer
constexpr int GKT_ = E_ / 32;               // 16 k tiles

__device__ __forceinline__ void cp16f(const float* smem_dst, const float* gmem_src) {
    cpb16((const void*)smem_dst, (const void*)gmem_src);
}

__device__ __forceinline__ void gemm_prefetch(const float* __restrict__ X, int widx,
                                              char* buf, int m0, int n0, int kt)
{
    const int tid = threadIdx.x;
    float* xs = reinterpret_cast<float*>(buf);
    char* whs = buf + GXB_;
    char* wls = whs + GWB_;
    #pragma unroll
    for (int i = 0; i < 4; i++) {
        int idx = tid + i * 256;
        int r = idx >> 3, c = (idx & 7) * 4;
        cp16f(&xs[r * 36 + c], X + (size_t)(m0 + r) * E_ + kt * 32 + c);
    }
    {
        int r = tid >> 2, c = tid & 3;
        const __nv_bfloat16* srch = g_wbh[widx] + (size_t)(n0 + r) * E_ + kt * 32 + c * 8;
        const __nv_bfloat16* srcl = g_wbl[widx] + (size_t)(n0 + r) * E_ + kt * 32 + c * 8;
        cpb16(whs + r * 112 + c * 16, srch);
        cpb16(wls + r * 112 + c * 16, srcl);
    }
    cp_commit();
}

__device__ __forceinline__ void gemm_core3(const float* __restrict__ X, int widx,
                                           char* smb, int m0, int n0,
                                           float acc[2][4][4])
{
    const int tid = threadIdx.x;
    const int warp = tid >> 5, lane = tid & 31;
    const int g = lane >> 2, tg = lane & 3;
    const int wm = warp >> 1, wn = warp & 1;

    gemm_prefetch(X, widx, smb, m0, n0, 0);

    for (int kt = 0; kt < GKT_; kt++) {
        if (kt + 1 < GKT_) {
            gemm_prefetch(X, widx, smb + ((kt + 1) & 1) * GBUFB_, m0, n0, kt + 1);
            cp_wait<1>();
        } else {
            cp_wait<0>();
        }
        __syncthreads();
        char* buf = smb + (kt & 1) * GBUFB_;
        const float* Xs = reinterpret_cast<const float*>(buf);
        const char* Whs = buf + GXB_;
        const char* Wls = Whs + GWB_;

        #pragma unroll
        for (int ks = 0; ks < 2; ks++) {
            const int k0 = ks * 16;
            uint32_t Ah[2][4], Al[2][4], Bh[4][2], Bl[4][2];
            #pragma unroll
            for (int mt = 0; mt < 2; mt++) {
                const int rb = (wm * 32 + mt * 16) * 36 + k0;
                float2 p0 = *reinterpret_cast<const float2*>(&Xs[rb + g * 36 + 2 * tg]);
                float2 p1 = *reinterpret_cast<const float2*>(&Xs[rb + (g + 8) * 36 + 2 * tg]);
                float2 p2 = *reinterpret_cast<const float2*>(&Xs[rb + g * 36 + 8 + 2 * tg]);
                float2 p3 = *reinterpret_cast<const float2*>(&Xs[rb + (g + 8) * 36 + 8 + 2 * tg]);
                pack_split(p0.x, p0.y, Ah[mt][0], Al[mt][0]);
                pack_split(p1.x, p1.y, Ah[mt][1], Al[mt][1]);
                pack_split(p2.x, p2.y, Ah[mt][2], Al[mt][2]);
                pack_split(p3.x, p3.y, Ah[mt][3], Al[mt][3]);
            }
            #pragma unroll
            for (int nt = 0; nt < 4; nt++) {
                const int r = wn * 32 + nt * 8 + g;
                const int boff = r * 112 + (k0 + 2 * tg) * 2;
                Bh[nt][0] = *reinterpret_cast<const uint32_t*>(Whs + boff);
                Bh[nt][1] = *reinterpret_cast<const uint32_t*>(Whs + boff + 16);
                Bl[nt][0] = *reinterpret_cast<const uint32_t*>(Wls + boff);
                Bl[nt][1] = *reinterpret_cast<const uint32_t*>(Wls + boff + 16);
            }
            #pragma unroll
            for (int mt = 0; mt < 2; mt++)
                #pragma unroll
                for (int nt = 0; nt < 4; nt++) {
                    mma16b(acc[mt][nt], Ah[mt], Bh[nt]);
                    mma16b(acc[mt][nt], Ah[mt], Bl[nt]);
                    mma16b(acc[mt][nt], Al[mt], Bh[nt]);
                }
        }
        __syncthreads();
    }
}

// QKV projections fused; outputs fp16 formatted for the fp16 attention:
//  z=0: Q scaled by log2e/tau -> g_qh; z=1: K -> g_kh; z=2: V -> g_vt (transposed).
__global__ __launch_bounds__(256)
void gemm_qkv(const float* __restrict__ Qi, const float* __restrict__ Ki,
              const float* __restrict__ Vi, const float* __restrict__ taup)
{
    extern __shared__ char smb[];
    const int z = blockIdx.z;
    const float* X = (z == 0) ? Qi : (z == 1) ? Ki : Vi;
    const float scl = (z == 0) ? (1.4426950408889634f / __ldg(taup)) : 1.0f;

    const int m0 = blockIdx.y * 128, n0 = blockIdx.x * 64;
    float acc[2][4][4] = {};
    gemm_core3(X, z, smb, m0, n0, acc);

    const int tid = threadIdx.x;
    const int warp = tid >> 5, lane = tid & 31;
    const int g = lane >> 2, tg = lane & 3;
    const int wm = warp >> 1, wn = warp & 1;
    const int h = blockIdx.x;              // BN=64 == head dim

    if (z <= 1) {
        __half* Y = (z == 0) ? g_qh : g_kh;
        #pragma unroll
        for (int mt = 0; mt < 2; mt++) {
            #pragma unroll
            for (int nt = 0; nt < 4; nt++) {
                const int dd = wn * 32 + nt * 8 + 2 * tg;
                int m = m0 + wm * 32 + mt * 16 + g;
                int b = m >> 11, n = m & (N_ - 1);
                *reinterpret_cast<uint32_t*>(&Y[((size_t)((b * H_ + h) * N_ + n)) * D_ + dd]) =
                    packh(acc[mt][nt][1] * scl, acc[mt][nt][0] * scl);
                m += 8; b = m >> 11; n = m & (N_ - 1);
                *reinterpret_cast<uint32_t*>(&Y[((size_t)((b * H_ + h) * N_ + n)) * D_ + dd]) =
                    packh(acc[mt][nt][3] * scl, acc[mt][nt][2] * scl);
            }
        }
    } else {
        // V: transpose 128(m) x 64(d) tile through smem -> g_vt[b][h][d][n]
        __half* ts = reinterpret_cast<__half*>(smb);   // [64][136] halfs
        __syncthreads();   // gemm buffers done
        #pragma unroll
        for (int mt = 0; mt < 2; mt++) {
            #pragma unroll
            for (int nt = 0; nt < 4; nt++) {
                const int dd = wn * 32 + nt * 8 + 2 * tg;
                const int ml = wm * 32 + mt * 16 + g;
                ts[dd * 136 + ml]           = __float2half(acc[mt][nt][0]);
                ts[(dd + 1) * 136 + ml]     = __float2half(acc[mt][nt][1]);
                ts[dd * 136 + ml + 8]       = __float2half(acc[mt][nt][2]);
                ts[(dd + 1) * 136 + ml + 8] = __float2half(acc[mt][nt][3]);
            }
        }
        __syncthreads();
        const int r = tid >> 2, c = tid & 3;
        const int bb = m0 >> 11, noff = m0 & (N_ - 1);
        __half* dst = g_vt + ((size_t)((bb * H_ + h) * D_ + r)) * N_ + noff + c * 32;
        #pragma unroll
        for (int i = 0; i < 4; i++)
            *reinterpret_cast<uint4*>(dst + i * 8) =
                *reinterpret_cast<const uint4*>(&ts[r * 136 + c * 32 + i * 8]);
    }
}

// Output projection: g_att @ Wo^T + bo -> out
__global__ __launch_bounds__(256)
void gemm_out(const float* __restrict__ bias, float* __restrict__ Yext)
{
    extern __shared__ char smb[];
    const int m0 = blockIdx.y * 128, n0 = blockIdx.x * 64;
    float acc[2][4][4] = {};
    gemm_core3(g_att, 3, smb, m0, n0, acc);

    const int tid = threadIdx.x;
    const int warp = tid >> 5, lane = tid & 31;
    const int g = lane >> 2, tg = lane & 3;
    const int wm = warp >> 1, wn = warp & 1;
    #pragma unroll
    for (int mt = 0; mt < 2; mt++) {
        #pragma unroll
        for (int nt = 0; nt < 4; nt++) {
            const int o = n0 + wn * 32 + nt * 8 + 2 * tg;
            float2 bb = *reinterpret_cast<const float2*>(bias + o);
            const int m = m0 + wm * 32 + mt * 16 + g;
            *reinterpret_cast<float2*>(&Yext[(size_t)m * E_ + o]) =
                make_float2(acc[mt][nt][0] + bb.x, acc[mt][nt][1] + bb.y);
            *reinterpret_cast<float2*>(&Yext[(size_t)(m + 8) * E_ + o]) =
                make_float2(acc[mt][nt][2] + bb.x, acc[mt][nt][3] + bb.y);
        }
    }
}

// ---------------------------------------------------------------------------
// Flash attention v6: fp16 m16n8k16, kv-tile 64 (halves per-tile softmax /
// rescale / barrier / loop overhead vs KT=32). 128 q-rows per block, 4 warps
// x 32 rows (u=0,1 groups); K/V fragments loaded once, feed both groups.
// K [kv][d] stride 72; Vt [d][kv] stride 72 (bank = 4g+tg+const: conflict-
// free). cp.async double buffer; log2 softmax; fp32 g_att epilogue.
// ---------------------------------------------------------------------------
__global__ __launch_bounds__(128, 2)
void attn_tc(const int* __restrict__ mask)
{
    __shared__ __align__(16) __half sm[2 * BUFH_];   // 36864 B; Q staged here first

    const int h = blockIdx.x, qt = blockIdx.y, b = blockIdx.z;
    const int tid = threadIdx.x;
    const int warp = tid >> 5, lane = tid & 31;
    const int g = lane >> 2, tg = lane & 3;
    const int q0 = qt * 128;

    const size_t bh = (size_t)(b * H_ + h) * N_ * D_;
    const __half* qbase = g_qh + bh;
    const __half* kbase = g_kh + bh;
    const __half* vtbase = g_vt + bh;      // [d][n] layout
    const int* mbase = mask + (size_t)b * N_ * N_;
    const int* fb0 = g_mflag + (b * NT_ + 2 * qt) * NT_;
    const int* fb1 = fb0 + NT_;

    // Stage Q (128x64 fp16) into smem [128][72]
    {
        #pragma unroll
        for (int i = 0; i < 8; i++) {
            int idx = tid + i * 128;
            int r = idx >> 3, c = (idx & 7) * 8;
            cpb16(&sm[r * KST_ + c], qbase + (size_t)(q0 + r) * D_ + c);
        }
        cp_commit(); cp_wait<0>();
        __syncthreads();
    }

    uint32_t q_a[2][4][4];
    #pragma unroll
    for (int u = 0; u < 2; u++) {
        #pragma unroll
        for (int kc = 0; kc < 4; kc++) {
            const int row = warp * 32 + u * 16 + g;
            q_a[u][kc][0] = *reinterpret_cast<const uint32_t*>(&sm[row * KST_ + kc * 16 + 2 * tg]);
            q_a[u][kc][1] = *reinterpret_cast<const uint32_t*>(&sm[(row + 8) * KST_ + kc * 16 + 2 * tg]);
            q_a[u][kc][2] = *reinterpret_cast<const uint32_t*>(&sm[row * KST_ + kc * 16 + 8 + 2 * tg]);
            q_a[u][kc][3] = *reinterpret_cast<const uint32_t*>(&sm[(row + 8) * KST_ + kc * 16 + 8 + 2 * tg]);
        }
    }
    __syncthreads();   // Q staging region free for kv buffers

    // Prefetch kv tile 0 into buf 0: K 64x64 (512 chunks), Vt 64x64 (512 chunks)
    {
        #pragma unroll
        for (int i = 0; i < 4; i++) {
            int idx = tid + i * 128;
            int r = idx >> 3, c = (idx & 7) * 8;
            cpb16(&sm[r * KST_ + c], kbase + (size_t)r * D_ + c);
        }
        #pragma unroll
        for (int i = 0; i < 4; i++) {
            int idx = tid + i * 128;
            int d = idx >> 3, c = (idx & 7) * 8;
            cpb16(&sm[KT_ * KST_ + d * VST_ + c], vtbase + (size_t)d * N_ + c);
        }
        cp_commit();
    }

    float o[2][8][4] = {};
    float mr[2][2] = {{neg_inf(), neg_inf()}, {neg_inf(), neg_inf()}};
    float lr[2][2] = {};
    int qrow[2];
    qrow[0] = q0 + warp * 32 + g;
    qrow[1] = qrow[0] + 16;

    for (int t = 0; t < NKT_; t++) {
        cp_wait<0>();
        __syncthreads();

        if (t + 1 < NKT_) {
            const __half* kb2 = kbase + (size_t)(t + 1) * KT_ * D_;
            const __half* vb2 = vtbase + (size_t)(t + 1) * KT_;
            __half* dst = sm + ((t + 1) & 1) * BUFH_;
            #pragma unroll
            for (int i = 0; i < 4; i++) {
                int idx = tid + i * 128;
                int r = idx >> 3, c = (idx & 7) * 8;
                cpb16(&dst[r * KST_ + c], kb2 + (size_t)r * D_ + c);
            }
            #pragma unroll
            for (int i = 0; i < 4; i++) {
                int idx = tid + i * 128;
                int d = idx >> 3, c = (idx & 7) * 8;
                cpb16(&dst[KT_ * KST_ + d * VST_ + c], vb2 + (size_t)d * N_ + c);
            }
            cp_commit();
        }

        const __half* Kc = sm + (t & 1) * BUFH_;
        const __half* Vc = Kc + KT_ * KST_;
        const int kv0 = t * KT_;
        const int clean = __ldg(fb0 + t) & __ldg(fb1 + t);

        // S = Q @ K^T (log2 units): 4 k16 chunks x 8 n-tiles, frags shared by u
        float s[2][8][4] = {};
        #pragma unroll
        for (int kc = 0; kc < 4; kc++) {
            #pragma unroll
            for (int nt = 0; nt < 8; nt++) {
                uint32_t bfr[2];
                const int kb = (nt * 8 + g) * KST_ + kc * 16 + 2 * tg;
                bfr[0] = *reinterpret_cast<const uint32_t*>(&Kc[kb]);
                bfr[1] = *reinterpret_cast<const uint32_t*>(&Kc[kb + 8]);
                mma16h(s[0][nt], q_a[0][kc], bfr);
                mma16h(s[1][nt], q_a[1][kc], bfr);
            }
        }

        if (!clean) {
            #pragma unroll
            for (int u = 0; u < 2; u++) {
                #pragma unroll
                for (int nt = 0; nt < 8; nt++) {
                    const int col = kv0 + nt * 8 + 2 * tg;
                    int2 mA = *reinterpret_cast<const int2*>(mbase + (size_t)qrow[u] * N_ + col);
                    int2 mB = *reinterpret_cast<const int2*>(mbase + (size_t)(qrow[u] + 8) * N_ + col);
                    if (!mA.x) s[u][nt][0] = neg_inf();
                    if (!mA.y) s[u][nt][1] = neg_inf();
                    if (!mB.x) s[u][nt][2] = neg_inf();
                    if (!mB.y) s[u][nt][3] = neg_inf();
                }
            }
        }

        // Online softmax (log2 domain), per group u, rows g and g+8
        #pragma unroll
        for (int u = 0; u < 2; u++) {
            float mx0 = neg_inf(), mx1 = neg_inf();
            #pragma unroll
            for (int nt = 0; nt < 8; nt++) {
                mx0 = fmaxf(mx0, fmaxf(s[u][nt][0], s[u][nt][1]));
                mx1 = fmaxf(mx1, fmaxf(s[u][nt][2], s[u][nt][3]));
            }
            mx0 = fmaxf(mx0, __shfl_xor_sync(0xffffffffu, mx0, 1));
            mx0 = fmaxf(mx0, __shfl_xor_sync(0xffffffffu, mx0, 2));
            mx1 = fmaxf(mx1, __shfl_xor_sync(0xffffffffu, mx1, 1));
            mx1 = fmaxf(mx1, __shfl_xor_sync(0xffffffffu, mx1, 2));
            const float mn0 = fmaxf(mr[u][0], mx0), mn1 = fmaxf(mr[u][1], mx1);
            const float sc0 = fexp2(fmaxf(mr[u][0] - mn0, -120.0f));
            const float sc1 = fexp2(fmaxf(mr[u][1] - mn1, -120.0f));
            float sum0 = 0.0f, sum1 = 0.0f;
            #pragma unroll
            for (int nt = 0; nt < 8; nt++) {
                float p0 = fexp2(fmaxf(s[u][nt][0] - mn0, -120.0f));
                float p1 = fexp2(fmaxf(s[u][nt][1] - mn0, -120.0f));
                float p2 = fexp2(fmaxf(s[u][nt][2] - mn1, -120.0f));
                float p3 = fexp2(fmaxf(s[u][nt][3] - mn1, -120.0f));
                s[u][nt][0] = p0; s[u][nt][1] = p1; s[u][nt][2] = p2; s[u][nt][3] = p3;
                sum0 += p0 + p1; sum1 += p2 + p3;
            }
            sum0 += __shfl_xor_sync(0xffffffffu, sum0, 1);
            sum0 += __shfl_xor_sync(0xffffffffu, sum0, 2);
            sum1 += __shfl_xor_sync(0xffffffffu, sum1, 1);
            sum1 += __shfl_xor_sync(0xffffffffu, sum1, 2);
            lr[u][0] = lr[u][0] * sc0 + sum0; lr[u][1] = lr[u][1] * sc1 + sum1;
            mr[u][0] = mn0; mr[u][1] = mn1;

            #pragma unroll
            for (int dt = 0; dt < 8; dt++) {
                o[u][dt][0] *= sc0; o[u][dt][1] *= sc0;
                o[u][dt][2] *= sc1; o[u][dt][3] *= sc1;
            }
        }

        // O += P @ V : fp16 k16, 4 kv chunks. P a-frags via quad shfls + f16x2
        // packs; V fragments from transposed smem, loaded once (feed both u).
        #pragma unroll
        for (int kc2 = 0; kc2 < 4; kc2++) {
            const int srcC = (g << 2) | tg;
            uint32_t a[2][4];
            #pragma unroll
            for (int u = 0; u < 2; u++) {
                float v0 = __shfl_sync(0xffffffffu, s[u][kc2 * 2][0], srcC);
                float v1 = __shfl_sync(0xffffffffu, s[u][kc2 * 2][1], srcC);
                float v2 = __shfl_sync(0xffffffffu, s[u][kc2 * 2][2], srcC);
                float v3 = __shfl_sync(0xffffffffu, s[u][kc2 * 2][3], srcC);
                float w0 = __shfl_sync(0xffffffffu, s[u][kc2 * 2 + 1][0], srcC);
                float w1 = __shfl_sync(0xffffffffu, s[u][kc2 * 2 + 1][1], srcC);
                float w2 = __shfl_sync(0xffffffffu, s[u][kc2 * 2 + 1][2], srcC);
                float w3 = __shfl_sync(0xffffffffu, s[u][kc2 * 2 + 1][3], srcC);
                a[u][0] = packh(v1, v0);   // row g,   k = 2tg, 2tg+1
                a[u][1] = packh(v3, v2);   // row g+8, k = 2tg, 2tg+1
                a[u][2] = packh(w1, w0);   // row g,   k = 8+2tg, 8+2tg+1
                a[u][3] = packh(w3, w2);   // row g+8, k = 8+2tg
            }
            #pragma unroll
            for (int dt = 0; dt < 8; dt++) {
                uint32_t bfr[2];
                const int vb = (dt * 8 + g) * VST_ + kc2 * 16 + 2 * tg;
                bfr[0] = *reinterpret_cast<const uint32_t*>(&Vc[vb]);
                bfr[1] = *reinterpret_cast<const uint32_t*>(&Vc[vb + 8]);
                mma16h(o[0][dt], a[0], bfr);
                mma16h(o[1][dt], a[1], bfr);
            }
        }
    }

    // Epilogue: normalize and recombine heads (fp32 g_att, R10 style)
    #pragma unroll
    for (int u = 0; u < 2; u++) {
        const float il0 = 1.0f / lr[u][0], il1 = 1.0f / lr[u][1];
        #pragma unroll
        for (int dt = 0; dt < 8; dt++) {
            const int dd = h * 64 + dt * 8 + 2 * tg;
            *reinterpret_cast<float2*>(&g_att[(size_t)(b * N_ + qrow[u]) * E_ + dd]) =
                make_float2(o[u][dt][0] * il0, o[u][dt][1] * il0);
            *reinterpret_cast<float2*>(&g_att[(size_t)(b * N_ + qrow[u] + 8) * E_ + dd]) =
                make_float2(o[u][dt][2] * il1, o[u][dt][3] * il1);
        }
    }
}

// ---------------------------------------------------------------------------
extern "C" void kernel_launch(void* const* d_in, const int* in_sizes, int n_in,
                              void* d_out, int out_size)
{
    const float* Q    = (const float*)d_in[0];
    const float* K    = (const float*)d_in[1];
    const float* V    = (const float*)d_in[2];
    const int*   mask = (const int*)  d_in[3];
    const float* Wq   = (const float*)d_in[4];
    const float* Wk   = (const float*)d_in[5];
    const float* Wv   = (const float*)d_in[6];
    const float* Wo   = (const float*)d_in[7];
    const float* bo   = (const float*)d_in[8];
    const float* tau  = (const float*)d_in[9];
    float* out = (float*)d_out;

    const int gemm_smem = 2 * GBUFB_;   // 65536

    cudaFuncSetAttribute(gemm_qkv, cudaFuncAttributeMaxDynamicSharedMemorySize, gemm_smem);
    cudaFuncSetAttribute(gemm_out, cudaFuncAttributeMaxDynamicSharedMemorySize, gemm_smem);

    split_w<<<dim3((int)(WBE_ / 1024), 4), 256>>>(Wq, Wk, Wv, Wo);
    mask_flags<<<dim3(NT_, NT_, B_), 256>>>(mask);

    gemm_qkv<<<dim3(E_ / 64, M_ / 128, 3), 256, gemm_smem>>>(Q, K, V, tau);

    // grid.x = heads (fastest) so the 8 heads sharing a mask tile are adjacent -> L2 reuse
    attn_tc<<<dim3(H_, N_ / 128, B_), 128>>>(mask);

    gemm_out<<<dim3(E_ / 64, M_ / 128), 256, gemm_smem>>>(bo, out);
}

// round 15
// speedup vs baseline: 1.2752x; 1.0874x over previous
#include <cuda_runtime.h>
#include <cuda_bf16.h>
#include <cuda_fp16.h>
#include <cstdint>
#include <cstddef>

// Problem constants
constexpr int B_ = 8;
constexpr int N_ = 2048;
constexpr int E_ = 512;
constexpr int H_ = 8;
constexpr int D_ = 64;
constexpr int M_ = B_ * N_;   // 16384 rows
constexpr int NT_ = N_ / 64;  // 32 64-row tiles (mask-flag granularity)
constexpr int KT_ = 64;       // attention kv-tile rows
constexpr int NKT_ = N_ / KT_;// 32 kv tiles
constexpr int KST_ = 72;      // K/Q attention smem row stride (halfs), conflict-free
constexpr int VST_ = 72;      // Vt attention smem row stride (halfs), conflict-free
constexpr int BUFH_ = KT_ * KST_ + 64 * VST_;  // 9216 halfs per KV buffer

constexpr size_t WBE_ = (size_t)E_ * E_;

// Scratch (device globals: allocation-free per harness rules)
__device__ __half g_qh[(size_t)B_ * H_ * N_ * D_];  // [b][h][n][d], pre-scaled log2e/tau, fp16
__device__ __half g_kh[(size_t)B_ * H_ * N_ * D_];  // [b][h][n][d] fp16
__device__ __half g_vt[(size_t)B_ * H_ * D_ * N_];  // [b][h][d][n] fp16 (V transposed)
__device__ float  g_att[(size_t)M_ * E_];           // [b*n][h*d] recombined heads (fp32)
__device__ int    g_mflag[B_ * NT_ * NT_];          // 1 = 64x64 tile all-nonzero
__device__ __half g_wfh[4][WBE_];                   // fp16 hi parts of Wq,Wk,Wv,Wo
__device__ __half g_wfl[4][WBE_];                   // fp16 lo (residual) parts

__device__ __forceinline__ float neg_inf() { return __int_as_float(0xff800000); }

__device__ __forceinline__ float fexp2(float x) {
    float y;
    asm("ex2.approx.ftz.f32 %0, %1;" : "=f"(y) : "f"(x));
    return y;
}

// pack two floats into f16x2 (low half = second arg)
__device__ __forceinline__ uint32_t packh(float hi, float lo) {
    uint32_t r;
    asm("cvt.rn.f16x2.f32 %0, %1, %2;" : "=r"(r) : "f"(hi), "f"(lo));
    return r;
}

// m16n8k16 fp16 mma, fp32 accumulate (projections AND attention)
__device__ __forceinline__ void mma16h(float* c, const uint32_t* a, const uint32_t* b) {
    asm volatile(
        "mma.sync.aligned.m16n8k16.row.col.f32.f16.f16.f32 "
        "{%0,%1,%2,%3}, {%4,%5,%6,%7}, {%8,%9}, {%0,%1,%2,%3};\n"
        : "+f"(c[0]), "+f"(c[1]), "+f"(c[2]), "+f"(c[3])
        : "r"(a[0]), "r"(a[1]), "r"(a[2]), "r"(a[3]), "r"(b[0]), "r"(b[1]));
}

// cp.async helpers
__device__ __forceinline__ void cpb16(const void* smem_dst, const void* gmem_src) {
    uint32_t s = (uint32_t)__cvta_generic_to_shared(smem_dst);
    asm volatile("cp.async.ca.shared.global [%0], [%1], 16;" :: "r"(s), "l"(gmem_src));
}
__device__ __forceinline__ void cp_commit() { asm volatile("cp.async.commit_group;"); }
template<int N>
__device__ __forceinline__ void cp_wait() { asm volatile("cp.async.wait_group %0;" :: "n"(N) : "memory"); }

// ---------------------------------------------------------------------------
// One-time weight split: W -> (hi, lo) fp16 pair. W entries ~U(+-0.076);
// residuals ~2e-5 land in fp16 subnormal range with ~8 effective bits (ample:
// hL term contributes ~2^-22 relative). blockIdx.y selects matrix.
// ---------------------------------------------------------------------------
__global__ __launch_bounds__(256)
void split_w(const float* __restrict__ Wq, const float* __restrict__ Wk,
             const float* __restrict__ Wv, const float* __restrict__ Wo)
{
    const int m = blockIdx.y;
    const float* W = (m == 0) ? Wq : (m == 1) ? Wk : (m == 2) ? Wv : Wo;
    const size_t i4 = ((size_t)blockIdx.x * 256 + threadIdx.x) * 4;
    float4 v = *reinterpret_cast<const float4*>(W + i4);
    uint32_t h01 = packh(v.y, v.x);
    uint32_t h23 = packh(v.w, v.z);
    __half2 hh01 = *reinterpret_cast<__half2*>(&h01);
    __half2 hh23 = *reinterpret_cast<__half2*>(&h23);
    uint32_t l01 = packh(v.y - __high2float(hh01), v.x - __low2float(hh01));
    uint32_t l23 = packh(v.w - __high2float(hh23), v.z - __low2float(hh23));
    *reinterpret_cast<uint2*>(&g_wfh[m][i4]) = make_uint2(h01, h23);
    *reinterpret_cast<uint2*>(&g_wfl[m][i4]) = make_uint2(l01, l23);
}

// ---------------------------------------------------------------------------
// Mask preprocessing: one flag per (b, 64-row q tile, 64-col kv tile).
// ---------------------------------------------------------------------------
__global__ __launch_bounds__(256)
void mask_flags(const int* __restrict__ mask)
{
    const int kvt = blockIdx.x, qt = blockIdx.y, b = blockIdx.z;
    const int tid = threadIdx.x;
    const int r = tid >> 2, c0 = (tid & 3) * 16;
    const int* base = mask + (size_t)b * N_ * N_ + (size_t)(qt * 64 + r) * N_ + kvt * 64 + c0;
    bool ok = true;
    #pragma unroll
    for (int i = 0; i < 4; i++) {
        int4 m = *reinterpret_cast<const int4*>(base + i * 4);
        ok &= (m.x != 0) & (m.y != 0) & (m.z != 0) & (m.w != 0);
    }
    int all = __syncthreads_and((int)ok);
    if (tid == 0) g_mflag[(b * NT_ + qt) * NT_ + kvt] = all;
}

// ---------------------------------------------------------------------------
// GEMM core v5: Y = fp16(X) @ (Wh + Wl)^T, fp16 2-TERM (mma count 2/3 of the
// bf16 3-term version; both kernel families are at the mma.sync dispatch
// ceiling, so duration tracks mma count). X fp32 in smem (stride 36); A-frags
// fp16-converted in regs (1 cvt per 2 values); W pre-split fp16 (stride 56,
// conflict-free). cp.async double buffer.
// Block 128x64, BK=32, 256 thr = 8 warps (4m x 2n), warp 32x32.
// ---------------------------------------------------------------------------
constexpr int GXB_ = 128 * 36 * 4;          // X tile bytes (fp32)
constexpr int GWB_ = 64 * 56 * 2;           // one W tile bytes (fp16, stride 56)
constexpr int GBUFB_ = GXB_ + 2 * GWB_;     // 32768 B per buffer
constexpr int GKT_ = E_ / 32;               // 16 k tiles

__device__ __forceinline__ void cp16f(const float* smem_dst, const float* gmem_src) {
    cpb16((const void*)smem_dst, (const void*)gmem_src);
}

__device__ __forceinline__ void gemm_prefetch(const float* __restrict__ X, int widx,
                                              char* buf, int m0, int n0, int kt)
{
    const int tid = threadIdx.x;
    float* xs = reinterpret_cast<float*>(buf);
    char* whs = buf + GXB_;
    char* wls = whs + GWB_;
    #pragma unroll
    for (int i = 0; i < 4; i++) {
        int idx = tid + i * 256;
        int r = idx >> 3, c = (idx & 7) * 4;
        cp16f(&xs[r * 36 + c], X + (size_t)(m0 + r) * E_ + kt * 32 + c);
    }
    {
        int r = tid >> 2, c = tid & 3;
        const __half* srch = g_wfh[widx] + (size_t)(n0 + r) * E_ + kt * 32 + c * 8;
        const __half* srcl = g_wfl[widx] + (size_t)(n0 + r) * E_ + kt * 32 + c * 8;
        cpb16(whs + r * 112 + c * 16, srch);
        cpb16(wls + r * 112 + c * 16, srcl);
    }
    cp_commit();
}

__device__ __forceinline__ void gemm_core5(const float* __restrict__ X, int widx,
                                           char* smb, int m0, int n0,
                                           float acc[2][4][4])
{
    const int tid = threadIdx.x;
    const int warp = tid >> 5, lane = tid & 31;
    const int g = lane >> 2, tg = lane & 3;
    const int wm = warp >> 1, wn = warp & 1;

    gemm_prefetch(X, widx, smb, m0, n0, 0);

    for (int kt = 0; kt < GKT_; kt++) {
        if (kt + 1 < GKT_) {
            gemm_prefetch(X, widx, smb + ((kt + 1) & 1) * GBUFB_, m0, n0, kt + 1);
            cp_wait<1>();
        } else {
            cp_wait<0>();
        }
        __syncthreads();
        char* buf = smb + (kt & 1) * GBUFB_;
        const float* Xs = reinterpret_cast<const float*>(buf);
        const char* Whs = buf + GXB_;
        const char* Wls = Whs + GWB_;

        #pragma unroll
        for (int ks = 0; ks < 2; ks++) {
            const int k0 = ks * 16;
            uint32_t Ah[2][4], Bh[4][2], Bl[4][2];
            #pragma unroll
            for (int mt = 0; mt < 2; mt++) {
                const int rb = (wm * 32 + mt * 16) * 36 + k0;
                float2 p0 = *reinterpret_cast<const float2*>(&Xs[rb + g * 36 + 2 * tg]);
                float2 p1 = *reinterpret_cast<const float2*>(&Xs[rb + (g + 8) * 36 + 2 * tg]);
                float2 p2 = *reinterpret_cast<const float2*>(&Xs[rb + g * 36 + 8 + 2 * tg]);
                float2 p3 = *reinterpret_cast<const float2*>(&Xs[rb + (g + 8) * 36 + 8 + 2 * tg]);
                Ah[mt][0] = packh(p0.y, p0.x);
                Ah[mt][1] = packh(p1.y, p1.x);
                Ah[mt][2] = packh(p2.y, p2.x);
                Ah[mt][3] = packh(p3.y, p3.x);
            }
            #pragma unroll
            for (int nt = 0; nt < 4; nt++) {
                const int r = wn * 32 + nt * 8 + g;
                const int boff = r * 112 + (k0 + 2 * tg) * 2;
                Bh[nt][0] = *reinterpret_cast<const uint32_t*>(Whs + boff);
                Bh[nt][1] = *reinterpret_cast<const uint32_t*>(Whs + boff + 16);
                Bl[nt][0] = *reinterpret_cast<const uint32_t*>(Wls + boff);
                Bl[nt][1] = *reinterpret_cast<const uint32_t*>(Wls + boff + 16);
            }
            #pragma unroll
            for (int mt = 0; mt < 2; mt++)
                #pragma unroll
                for (int nt = 0; nt < 4; nt++) {
                    mma16h(acc[mt][nt], Ah[mt], Bh[nt]);   // h*H
                    mma16h(acc[mt][nt], Ah[mt], Bl[nt]);   // h*L
                }
        }
        __syncthreads();
    }
}

// QKV projections fused; outputs fp16 formatted for the fp16 attention:
//  z=0: Q scaled by log2e/tau -> g_qh; z=1: K -> g_kh; z=2: V -> g_vt (transposed).
__global__ __launch_bounds__(256)
void gemm_qkv(const float* __restrict__ Qi, const float* __restrict__ Ki,
              const float* __restrict__ Vi, const float* __restrict__ taup)
{
    extern __shared__ char smb[];
    const int z = blockIdx.z;
    const float* X = (z == 0) ? Qi : (z == 1) ? Ki : Vi;
    const float scl = (z == 0) ? (1.4426950408889634f / __ldg(taup)) : 1.0f;

    const int m0 = blockIdx.y * 128, n0 = blockIdx.x * 64;
    float acc[2][4][4] = {};
    gemm_core5(X, z, smb, m0, n0, acc);

    const int tid = threadIdx.x;
    const int warp = tid >> 5, lane = tid & 31;
    const int g = lane >> 2, tg = lane & 3;
    const int wm = warp >> 1, wn = warp & 1;
    const int h = blockIdx.x;              // BN=64 == head dim

    if (z <= 1) {
        __half* Y = (z == 0) ? g_qh : g_kh;
        #pragma unroll
        for (int mt = 0; mt < 2; mt++) {
            #pragma unroll
            for (int nt = 0; nt < 4; nt++) {
                const int dd = wn * 32 + nt * 8 + 2 * tg;
                int m = m0 + wm * 32 + mt * 16 + g;
                int b = m >> 11, n = m & (N_ - 1);
                *reinterpret_cast<uint32_t*>(&Y[((size_t)((b * H_ + h) * N_ + n)) * D_ + dd]) =
                    packh(acc[mt][nt][1] * scl, acc[mt][nt][0] * scl);
                m += 8; b = m >> 11; n = m & (N_ - 1);
                *reinterpret_cast<uint32_t*>(&Y[((size_t)((b * H_ + h) * N_ + n)) * D_ + dd]) =
                    packh(acc[mt][nt][3] * scl, acc[mt][nt][2] * scl);
            }
        }
    } else {
        // V: transpose 128(m) x 64(d) tile through smem -> g_vt[b][h][d][n]
        __half* ts = reinterpret_cast<__half*>(smb);   // [64][136] halfs
        __syncthreads();   // gemm buffers done
        #pragma unroll
        for (int mt = 0; mt < 2; mt++) {
            #pragma unroll
            for (int nt = 0; nt < 4; nt++) {
                const int dd = wn * 32 + nt * 8 + 2 * tg;
                const int ml = wm * 32 + mt * 16 + g;
                ts[dd * 136 + ml]           = __float2half(acc[mt][nt][0]);
                ts[(dd + 1) * 136 + ml]     = __float2half(acc[mt][nt][1]);
                ts[dd * 136 + ml + 8]       = __float2half(acc[mt][nt][2]);
                ts[(dd + 1) * 136 + ml + 8] = __float2half(acc[mt][nt][3]);
            }
        }
        __syncthreads();
        const int r = tid >> 2, c = tid & 3;
        const int bb = m0 >> 11, noff = m0 & (N_ - 1);
        __half* dst = g_vt + ((size_t)((bb * H_ + h) * D_ + r)) * N_ + noff + c * 32;
        #pragma unroll
        for (int i = 0; i < 4; i++)
            *reinterpret_cast<uint4*>(dst + i * 8) =
                *reinterpret_cast<const uint4*>(&ts[r * 136 + c * 32 + i * 8]);
    }
}

// Output projection: g_att @ Wo^T + bo -> out
__global__ __launch_bounds__(256)
void gemm_out(const float* __restrict__ bias, float* __restrict__ Yext)
{
    extern __shared__ char smb[];
    const int m0 = blockIdx.y * 128, n0 = blockIdx.x * 64;
    float acc[2][4][4] = {};
    gemm_core5(g_att, 3, smb, m0, n0, acc);

    const int tid = threadIdx.x;
    const int warp = tid >> 5, lane = tid & 31;
    const int g = lane >> 2, tg = lane & 3;
    const int wm = warp >> 1, wn = warp & 1;
    #pragma unroll
    for (int mt = 0; mt < 2; mt++) {
        #pragma unroll
        for (int nt = 0; nt < 4; nt++) {
            const int o = n0 + wn * 32 + nt * 8 + 2 * tg;
            float2 bb = *reinterpret_cast<const float2*>(bias + o);
            const int m = m0 + wm * 32 + mt * 16 + g;
            *reinterpret_cast<float2*>(&Yext[(size_t)m * E_ + o]) =
                make_float2(acc[mt][nt][0] + bb.x, acc[mt][nt][1] + bb.y);
            *reinterpret_cast<float2*>(&Yext[(size_t)(m + 8) * E_ + o]) =
                make_float2(acc[mt][nt][2] + bb.x, acc[mt][nt][3] + bb.y);
        }
    }
}

// ---------------------------------------------------------------------------
// Flash attention v6 (R14, validated): fp16 m16n8k16, kv-tile 64, 128 q-rows
// per block, 4 warps x 32 rows; K/V fragments shared across both row groups;
// cp.async double buffer; log2 softmax; fp32 g_att epilogue.
// ---------------------------------------------------------------------------
__global__ __launch_bounds__(128, 2)
void attn_tc(const int* __restrict__ mask)
{
    __shared__ __align__(16) __half sm[2 * BUFH_];   // 36864 B; Q staged here first

    const int h = blockIdx.x, qt = blockIdx.y, b = blockIdx.z;
    const int tid = threadIdx.x;
    const int warp = tid >> 5, lane = tid & 31;
    const int g = lane >> 2, tg = lane & 3;
    const int q0 = qt * 128;

    const size_t bh = (size_t)(b * H_ + h) * N_ * D_;
    const __half* qbase = g_qh + bh;
    const __half* kbase = g_kh + bh;
    const __half* vtbase = g_vt + bh;      // [d][n] layout
    const int* mbase = mask + (size_t)b * N_ * N_;
    const int* fb0 = g_mflag + (b * NT_ + 2 * qt) * NT_;
    const int* fb1 = fb0 + NT_;

    // Stage Q (128x64 fp16) into smem [128][72]
    {
        #pragma unroll
        for (int i = 0; i < 8; i++) {
            int idx = tid + i * 128;
            int r = idx >> 3, c = (idx & 7) * 8;
            cpb16(&sm[r * KST_ + c], qbase + (size_t)(q0 + r) * D_ + c);
        }
        cp_commit(); cp_wait<0>();
        __syncthreads();
    }

    uint32_t q_a[2][4][4];
    #pragma unroll
    for (int u = 0; u < 2; u++) {
        #pragma unroll
        for (int kc = 0; kc < 4; kc++) {
            const int row = warp * 32 + u * 16 + g;
            q_a[u][kc][0] = *reinterpret_cast<const uint32_t*>(&sm[row * KST_ + kc * 16 + 2 * tg]);
            q_a[u][kc][1] = *reinterpret_cast<const uint32_t*>(&sm[(row + 8) * KST_ + kc * 16 + 2 * tg]);
            q_a[u][kc][2] = *reinterpret_cast<const uint32_t*>(&sm[row * KST_ + kc * 16 + 8 + 2 * tg]);
            q_a[u][kc][3] = *reinterpret_cast<const uint32_t*>(&sm[(row + 8) * KST_ + kc * 16 + 8 + 2 * tg]);
        }
    }
    __syncthreads();   // Q staging region free for kv buffers

    // Prefetch kv tile 0 into buf 0: K 64x64 (512 chunks), Vt 64x64 (512 chunks)
    {
        #pragma unroll
        for (int i = 0; i < 4; i++) {
            int idx = tid + i * 128;
            int r = idx >> 3, c = (idx & 7) * 8;
            cpb16(&sm[r * KST_ + c], kbase + (size_t)r * D_ + c);
        }
        #pragma unroll
        for (int i = 0; i < 4; i++) {
            int idx = tid + i * 128;
            int d = idx >> 3, c = (idx & 7) * 8;
            cpb16(&sm[KT_ * KST_ + d * VST_ + c], vtbase + (size_t)d * N_ + c);
        }
        cp_commit();
    }

    float o[2][8][4] = {};
    float mr[2][2] = {{neg_inf(), neg_inf()}, {neg_inf(), neg_inf()}};
    float lr[2][2] = {};
    int qrow[2];
    qrow[0] = q0 + warp * 32 + g;
    qrow[1] = qrow[0] + 16;

    for (int t = 0; t < NKT_; t++) {
        cp_wait<0>();
        __syncthreads();

        if (t + 1 < NKT_) {
            const __half* kb2 = kbase + (size_t)(t + 1) * KT_ * D_;
            const __half* vb2 = vtbase + (size_t)(t + 1) * KT_;
            __half* dst = sm + ((t + 1) & 1) * BUFH_;
            #pragma unroll
            for (int i = 0; i < 4; i++) {
                int idx = tid + i * 128;
                int r = idx >> 3, c = (idx & 7) * 8;
                cpb16(&dst[r * KST_ + c], kb2 + (size_t)r * D_ + c);
            }
            #pragma unroll
            for (int i = 0; i < 4; i++) {
                int idx = tid + i * 128;
                int d = idx >> 3, c = (idx & 7) * 8;
                cpb16(&dst[KT_ * KST_ + d * VST_ + c], vb2 + (size_t)d * N_ + c);
            }
            cp_commit();
        }

        const __half* Kc = sm + (t & 1) * BUFH_;
        const __half* Vc = Kc + KT_ * KST_;
        const int kv0 = t * KT_;
        const int clean = __ldg(fb0 + t) & __ldg(fb1 + t);

        // S = Q @ K^T (log2 units): 4 k16 chunks x 8 n-tiles, frags shared by u
        float s[2][8][4] = {};
        #pragma unroll
        for (int kc = 0; kc < 4; kc++) {
            #pragma unroll
            for (int nt = 0; nt < 8; nt++) {
                uint32_t bfr[2];
                const int kb = (nt * 8 + g) * KST_ + kc * 16 + 2 * tg;
                bfr[0] = *reinterpret_cast<const uint32_t*>(&Kc[kb]);
                bfr[1] = *reinterpret_cast<const uint32_t*>(&Kc[kb + 8]);
                mma16h(s[0][nt], q_a[0][kc], bfr);
                mma16h(s[1][nt], q_a[1][kc], bfr);
            }
        }

        if (!clean) {
            #pragma unroll
            for (int u = 0; u < 2; u++) {
                #pragma unroll
                for (int nt = 0; nt < 8; nt++) {
                    const int col = kv0 + nt * 8 + 2 * tg;
                    int2 mA = *reinterpret_cast<const int2*>(mbase + (size_t)qrow[u] * N_ + col);
                    int2 mB = *reinterpret_cast<const int2*>(mbase + (size_t)(qrow[u] + 8) * N_ + col);
                    if (!mA.x) s[u][nt][0] = neg_inf();
                    if (!mA.y) s[u][nt][1] = neg_inf();
                    if (!mB.x) s[u][nt][2] = neg_inf();
                    if (!mB.y) s[u][nt][3] = neg_inf();
                }
            }
        }

        // Online softmax (log2 domain), per group u, rows g and g+8
        #pragma unroll
        for (int u = 0; u < 2; u++) {
            float mx0 = neg_inf(), mx1 = neg_inf();
            #pragma unroll
            for (int nt = 0; nt < 8; nt++) {
                mx0 = fmaxf(mx0, fmaxf(s[u][nt][0], s[u][nt][1]));
                mx1 = fmaxf(mx1, fmaxf(s[u][nt][2], s[u][nt][3]));
            }
            mx0 = fmaxf(mx0, __shfl_xor_sync(0xffffffffu, mx0, 1));
            mx0 = fmaxf(mx0, __shfl_xor_sync(0xffffffffu, mx0, 2));
            mx1 = fmaxf(mx1, __shfl_xor_sync(0xffffffffu, mx1, 1));
            mx1 = fmaxf(mx1, __shfl_xor_sync(0xffffffffu, mx1, 2));
            const float mn0 = fmaxf(mr[u][0], mx0), mn1 = fmaxf(mr[u][1], mx1);
            const float sc0 = fexp2(fmaxf(mr[u][0] - mn0, -120.0f));
            const float sc1 = fexp2(fmaxf(mr[u][1] - mn1, -120.0f));
            float sum0 = 0.0f, sum1 = 0.0f;
            #pragma unroll
            for (int nt = 0; nt < 8; nt++) {
                float p0 = fexp2(fmaxf(s[u][nt][0] - mn0, -120.0f));
                float p1 = fexp2(fmaxf(s[u][nt][1] - mn0, -120.0f));
                float p2 = fexp2(fmaxf(s[u][nt][2] - mn1, -120.0f));
                float p3 = fexp2(fmaxf(s[u][nt][3] - mn1, -120.0f));
                s[u][nt][0] = p0; s[u][nt][1] = p1; s[u][nt][2] = p2; s[u][nt][3] = p3;
                sum0 += p0 + p1; sum1 += p2 + p3;
            }
            sum0 += __shfl_xor_sync(0xffffffffu, sum0, 1);
            sum0 += __shfl_xor_sync(0xffffffffu, sum0, 2);
            sum1 += __shfl_xor_sync(0xffffffffu, sum1, 1);
            sum1 += __shfl_xor_sync(0xffffffffu, sum1, 2);
            lr[u][0] = lr[u][0] * sc0 + sum0; lr[u][1] = lr[u][1] * sc1 + sum1;
            mr[u][0] = mn0; mr[u][1] = mn1;

            #pragma unroll
            for (int dt = 0; dt < 8; dt++) {
                o[u][dt][0] *= sc0; o[u][dt][1] *= sc0;
                o[u][dt][2] *= sc1; o[u][dt][3] *= sc1;
            }
        }

        // O += P @ V : fp16 k16, 4 kv chunks. P a-frags via quad shfls + f16x2
        // packs; V fragments from transposed smem, loaded once (feed both u).
        #pragma unroll
        for (int kc2 = 0; kc2 < 4; kc2++) {
            const int srcC = (g << 2) | tg;
            uint32_t a[2][4];
            #pragma unroll
            for (int u = 0; u < 2; u++) {
                float v0 = __shfl_sync(0xffffffffu, s[u][kc2 * 2][0], srcC);
                float v1 = __shfl_sync(0xffffffffu, s[u][kc2 * 2][1], srcC);
                float v2 = __shfl_sync(0xffffffffu, s[u][kc2 * 2][2], srcC);
                float v3 = __shfl_sync(0xffffffffu, s[u][kc2 * 2][3], srcC);
                float w0 = __shfl_sync(0xffffffffu, s[u][kc2 * 2 + 1][0], srcC);
                float w1 = __shfl_sync(0xffffffffu, s[u][kc2 * 2 + 1][1], srcC);
                float w2 = __shfl_sync(0xffffffffu, s[u][kc2 * 2 + 1][2], srcC);
                float w3 = __shfl_sync(0xffffffffu, s[u][kc2 * 2 + 1][3], srcC);
                a[u][0] = packh(v1, v0);   // row g,   k = 2tg, 2tg+1
                a[u][1] = packh(v3, v2);   // row g+8, k = 2tg, 2tg+1
                a[u][2] = packh(w1, w0);   // row g,   k = 8+2tg, 8+2tg+1
                a[u][3] = packh(w3, w2);   // row g+8, k = 8+2tg
            }
            #pragma unroll
            for (int dt = 0; dt < 8; dt++) {
                uint32_t bfr[2];
                const int vb = (dt * 8 + g) * VST_ + kc2 * 16 + 2 * tg;
                bfr[0] = *reinterpret_cast<const uint32_t*>(&Vc[vb]);
                bfr[1] = *reinterpret_cast<const uint32_t*>(&Vc[vb + 8]);
                mma16h(o[0][dt], a[0], bfr);
                mma16h(o[1][dt], a[1], bfr);
            }
        }
    }

    // Epilogue: normalize and recombine heads (fp32 g_att)
    #pragma unroll
    for (int u = 0; u < 2; u++) {
        const float il0 = 1.0f / lr[u][0], il1 = 1.0f / lr[u][1];
        #pragma unroll
        for (int dt = 0; dt < 8; dt++) {
            const int dd = h * 64 + dt * 8 + 2 * tg;
            *reinterpret_cast<float2*>(&g_att[(size_t)(b * N_ + qrow[u]) * E_ + dd]) =
                make_float2(o[u][dt][0] * il0, o[u][dt][1] * il0);
            *reinterpret_cast<float2*>(&g_att[(size_t)(b * N_ + qrow[u] + 8) * E_ + dd]) =
                make_float2(o[u][dt][2] * il1, o[u][dt][3] * il1);
        }
    }
}

// ---------------------------------------------------------------------------
extern "C" void kernel_launch(void* const* d_in, const int* in_sizes, int n_in,
                              void* d_out, int out_size)
{
    const float* Q    = (const float*)d_in[0];
    const float* K    = (const float*)d_in[1];
    const float* V    = (const float*)d_in[2];
    const int*   mask = (const int*)  d_in[3];
    const float* Wq   = (const float*)d_in[4];
    const float* Wk   = (const float*)d_in[5];
    const float* Wv   = (const float*)d_in[6];
    const float* Wo   = (const float*)d_in[7];
    const float* bo   = (const float*)d_in[8];
    const float* tau  = (const float*)d_in[9];
    float* out = (float*)d_out;

    const int gemm_smem = 2 * GBUFB_;   // 65536

    cudaFuncSetAttribute(gemm_qkv, cudaFuncAttributeMaxDynamicSharedMemorySize, gemm_smem);
    cudaFuncSetAttribute(gemm_out, cudaFuncAttributeMaxDynamicSharedMemorySize, gemm_smem);

    split_w<<<dim3((int)(WBE_ / 1024), 4), 256>>>(Wq, Wk, Wv, Wo);
    mask_flags<<<dim3(NT_, NT_, B_), 256>>>(mask);

    gemm_qkv<<<dim3(E_ / 64, M_ / 128, 3), 256, gemm_smem>>>(Q, K, V, tau);

    // grid.x = heads (fastest) so the 8 heads sharing a mask tile are adjacent -> L2 reuse
    attn_tc<<<dim3(H_, N_ / 128, B_), 128>>>(mask);

    gemm_out<<<dim3(E_ / 64, M_ / 128), 256, gemm_smem>>>(bo, out);
}

// round 16
// speedup vs baseline: 1.3589x; 1.0656x over previous
#include <cuda_runtime.h>
#include <cuda_bf16.h>
#include <cuda_fp16.h>
#include <cstdint>
#include <cstddef>

// Problem constants
constexpr int B_ = 8;
constexpr int N_ = 2048;
constexpr int E_ = 512;
constexpr int H_ = 8;
constexpr int D_ = 64;
constexpr int M_ = B_ * N_;   // 16384 rows
constexpr int NT_ = N_ / 64;  // 32 64-row tiles (mask-flag granularity)
constexpr int KT_ = 64;       // attention kv-tile rows
constexpr int NKT_ = N_ / KT_;// 32 kv tiles
constexpr int KST_ = 72;      // K/Q attention smem row stride (halfs), conflict-free
constexpr int VST_ = 72;      // Vt attention smem row stride (halfs), conflict-free
constexpr int BUFH_ = KT_ * KST_ + 64 * VST_;  // 9216 halfs per KV buffer

constexpr size_t WBE_ = (size_t)E_ * E_;

// Scratch (device globals: allocation-free per harness rules)
__device__ __half g_qh[(size_t)B_ * H_ * N_ * D_];  // [b][h][n][d], pre-scaled log2e/tau, fp16
__device__ __half g_kh[(size_t)B_ * H_ * N_ * D_];  // [b][h][n][d] fp16
__device__ __half g_vt[(size_t)B_ * H_ * D_ * N_];  // [b][h][d][n] fp16 (V transposed)
__device__ float  g_att[(size_t)M_ * E_];           // [b*n][h*d] recombined heads (fp32)
__device__ int    g_mflag[B_ * NT_ * NT_];          // 1 = 64x64 tile all-nonzero
__device__ __half g_wfh[4][WBE_];                   // fp16 hi parts of Wq,Wk,Wv,Wo
__device__ __half g_wfl[4][WBE_];                   // fp16 lo (residual) parts

__device__ __forceinline__ float neg_inf() { return __int_as_float(0xff800000); }

__device__ __forceinline__ float fexp2(float x) {
    float y;
    asm("ex2.approx.ftz.f32 %0, %1;" : "=f"(y) : "f"(x));
    return y;
}

// pack two floats into f16x2 (low half = second arg)
__device__ __forceinline__ uint32_t packh(float hi, float lo) {
    uint32_t r;
    asm("cvt.rn.f16x2.f32 %0, %1, %2;" : "=r"(r) : "f"(hi), "f"(lo));
    return r;
}

// m16n8k16 fp16 mma, fp32 accumulate (projections AND attention)
__device__ __forceinline__ void mma16h(float* c, const uint32_t* a, const uint32_t* b) {
    asm volatile(
        "mma.sync.aligned.m16n8k16.row.col.f32.f16.f16.f32 "
        "{%0,%1,%2,%3}, {%4,%5,%6,%7}, {%8,%9}, {%0,%1,%2,%3};\n"
        : "+f"(c[0]), "+f"(c[1]), "+f"(c[2]), "+f"(c[3])
        : "r"(a[0]), "r"(a[1]), "r"(a[2]), "r"(a[3]), "r"(b[0]), "r"(b[1]));
}

// cp.async helpers
__device__ __forceinline__ void cpb16(const void* smem_dst, const void* gmem_src) {
    uint32_t s = (uint32_t)__cvta_generic_to_shared(smem_dst);
    asm volatile("cp.async.ca.shared.global [%0], [%1], 16;" :: "r"(s), "l"(gmem_src));
}
__device__ __forceinline__ void cp_commit() { asm volatile("cp.async.commit_group;"); }
template<int N>
__device__ __forceinline__ void cp_wait() { asm volatile("cp.async.wait_group %0;" :: "n"(N) : "memory"); }

// ---------------------------------------------------------------------------
// One-time weight split: W -> (hi, lo) fp16 pair. blockIdx.y selects matrix.
// (lo parts of Wv/Wo are written but unused: those GEMMs run 1-term.)
// ---------------------------------------------------------------------------
__global__ __launch_bounds__(256)
void split_w(const float* __restrict__ Wq, const float* __restrict__ Wk,
             const float* __restrict__ Wv, const float* __restrict__ Wo)
{
    const int m = blockIdx.y;
    const float* W = (m == 0) ? Wq : (m == 1) ? Wk : (m == 2) ? Wv : Wo;
    const size_t i4 = ((size_t)blockIdx.x * 256 + threadIdx.x) * 4;
    float4 v = *reinterpret_cast<const float4*>(W + i4);
    uint32_t h01 = packh(v.y, v.x);
    uint32_t h23 = packh(v.w, v.z);
    __half2 hh01 = *reinterpret_cast<__half2*>(&h01);
    __half2 hh23 = *reinterpret_cast<__half2*>(&h23);
    uint32_t l01 = packh(v.y - __high2float(hh01), v.x - __low2float(hh01));
    uint32_t l23 = packh(v.w - __high2float(hh23), v.z - __low2float(hh23));
    *reinterpret_cast<uint2*>(&g_wfh[m][i4]) = make_uint2(h01, h23);
    *reinterpret_cast<uint2*>(&g_wfl[m][i4]) = make_uint2(l01, l23);
}

// ---------------------------------------------------------------------------
// Mask preprocessing: one flag per (b, 64-row q tile, 64-col kv tile).
// ---------------------------------------------------------------------------
__global__ __launch_bounds__(256)
void mask_flags(const int* __restrict__ mask)
{
    const int kvt = blockIdx.x, qt = blockIdx.y, b = blockIdx.z;
    const int tid = threadIdx.x;
    const int r = tid >> 2, c0 = (tid & 3) * 16;
    const int* base = mask + (size_t)b * N_ * N_ + (size_t)(qt * 64 + r) * N_ + kvt * 64 + c0;
    bool ok = true;
    #pragma unroll
    for (int i = 0; i < 4; i++) {
        int4 m = *reinterpret_cast<const int4*>(base + i * 4);
        ok &= (m.x != 0) & (m.y != 0) & (m.z != 0) & (m.w != 0);
    }
    int all = __syncthreads_and((int)ok);
    if (tid == 0) g_mflag[(b * NT_ + qt) * NT_ + kvt] = all;
}

// ---------------------------------------------------------------------------
// GEMM core v5b: Y = fp16(X) @ (Wh [+ Wl])^T, fp16, 2-term when wlo else
// 1-term (mma count halves; pipeline is at the mma.sync dispatch ceiling so
// duration tracks mma count). X fp32 in smem (stride 36), A-frags converted
// in regs; W pre-split fp16 (stride 56, conflict-free). cp.async dbl buffer.
// Block 128x64, BK=32, 256 thr = 8 warps (4m x 2n), warp 32x32.
// ---------------------------------------------------------------------------
constexpr int GXB_ = 128 * 36 * 4;          // X tile bytes (fp32)
constexpr int GWB_ = 64 * 56 * 2;           // one W tile bytes (fp16, stride 56)
constexpr int GBUFB_ = GXB_ + 2 * GWB_;     // 32768 B per buffer
constexpr int GKT_ = E_ / 32;               // 16 k tiles

__device__ __forceinline__ void cp16f(const float* smem_dst, const float* gmem_src) {
    cpb16((const void*)smem_dst, (const void*)gmem_src);
}

__device__ __forceinline__ void gemm_prefetch(const float* __restrict__ X, int widx,
                                              char* buf, int m0, int n0, int kt, bool wlo)
{
    const int tid = threadIdx.x;
    float* xs = reinterpret_cast<float*>(buf);
    char* whs = buf + GXB_;
    char* wls = whs + GWB_;
    #pragma unroll
    for (int i = 0; i < 4; i++) {
        int idx = tid + i * 256;
        int r = idx >> 3, c = (idx & 7) * 4;
        cp16f(&xs[r * 36 + c], X + (size_t)(m0 + r) * E_ + kt * 32 + c);
    }
    {
        int r = tid >> 2, c = tid & 3;
        const __half* srch = g_wfh[widx] + (size_t)(n0 + r) * E_ + kt * 32 + c * 8;
        cpb16(whs + r * 112 + c * 16, srch);
        if (wlo) {
            const __half* srcl = g_wfl[widx] + (size_t)(n0 + r) * E_ + kt * 32 + c * 8;
            cpb16(wls + r * 112 + c * 16, srcl);
        }
    }
    cp_commit();
}

__device__ __forceinline__ void gemm_core5(const float* __restrict__ X, int widx,
                                           char* smb, int m0, int n0,
                                           float acc[2][4][4], bool wlo)
{
    const int tid = threadIdx.x;
    const int warp = tid >> 5, lane = tid & 31;
    const int g = lane >> 2, tg = lane & 3;
    const int wm = warp >> 1, wn = warp & 1;

    gemm_prefetch(X, widx, smb, m0, n0, 0, wlo);

    for (int kt = 0; kt < GKT_; kt++) {
        if (kt + 1 < GKT_) {
            gemm_prefetch(X, widx, smb + ((kt + 1) & 1) * GBUFB_, m0, n0, kt + 1, wlo);
            cp_wait<1>();
        } else {
            cp_wait<0>();
        }
        __syncthreads();
        char* buf = smb + (kt & 1) * GBUFB_;
        const float* Xs = reinterpret_cast<const float*>(buf);
        const char* Whs = buf + GXB_;
        const char* Wls = Whs + GWB_;

        #pragma unroll
        for (int ks = 0; ks < 2; ks++) {
            const int k0 = ks * 16;
            uint32_t Ah[2][4], Bh[4][2];
            #pragma unroll
            for (int mt = 0; mt < 2; mt++) {
                const int rb = (wm * 32 + mt * 16) * 36 + k0;
                float2 p0 = *reinterpret_cast<const float2*>(&Xs[rb + g * 36 + 2 * tg]);
                float2 p1 = *reinterpret_cast<const float2*>(&Xs[rb + (g + 8) * 36 + 2 * tg]);
                float2 p2 = *reinterpret_cast<const float2*>(&Xs[rb + g * 36 + 8 + 2 * tg]);
                float2 p3 = *reinterpret_cast<const float2*>(&Xs[rb + (g + 8) * 36 + 8 + 2 * tg]);
                Ah[mt][0] = packh(p0.y, p0.x);
                Ah[mt][1] = packh(p1.y, p1.x);
                Ah[mt][2] = packh(p2.y, p2.x);
                Ah[mt][3] = packh(p3.y, p3.x);
            }
            #pragma unroll
            for (int nt = 0; nt < 4; nt++) {
                const int r = wn * 32 + nt * 8 + g;
                const int boff = r * 112 + (k0 + 2 * tg) * 2;
                Bh[nt][0] = *reinterpret_cast<const uint32_t*>(Whs + boff);
                Bh[nt][1] = *reinterpret_cast<const uint32_t*>(Whs + boff + 16);
            }
            #pragma unroll
            for (int mt = 0; mt < 2; mt++)
                #pragma unroll
                for (int nt = 0; nt < 4; nt++)
                    mma16h(acc[mt][nt], Ah[mt], Bh[nt]);   // h*H
            if (wlo) {
                uint32_t Bl[4][2];
                #pragma unroll
                for (int nt = 0; nt < 4; nt++) {
                    const int r = wn * 32 + nt * 8 + g;
                    const int boff = r * 112 + (k0 + 2 * tg) * 2;
                    Bl[nt][0] = *reinterpret_cast<const uint32_t*>(Wls + boff);
                    Bl[nt][1] = *reinterpret_cast<const uint32_t*>(Wls + boff + 16);
                }
                #pragma unroll
                for (int mt = 0; mt < 2; mt++)
                    #pragma unroll
                    for (int nt = 0; nt < 4; nt++)
                        mma16h(acc[mt][nt], Ah[mt], Bl[nt]);   // h*L
            }
        }
        __syncthreads();
    }
}

// QKV projections fused; outputs fp16 formatted for the fp16 attention:
//  z=0: Q scaled by log2e/tau -> g_qh; z=1: K -> g_kh; z=2: V -> g_vt (transposed).
//  Q,K use 2-term W (score path); V uses 1-term (linear path, error budget ok).
__global__ __launch_bounds__(256)
void gemm_qkv(const float* __restrict__ Qi, const float* __restrict__ Ki,
              const float* __restrict__ Vi, const float* __restrict__ taup)
{
    extern __shared__ char smb[];
    const int z = blockIdx.z;
    const float* X = (z == 0) ? Qi : (z == 1) ? Ki : Vi;
    const float scl = (z == 0) ? (1.4426950408889634f / __ldg(taup)) : 1.0f;

    const int m0 = blockIdx.y * 128, n0 = blockIdx.x * 64;
    float acc[2][4][4] = {};
    gemm_core5(X, z, smb, m0, n0, acc, z <= 1);

    const int tid = threadIdx.x;
    const int warp = tid >> 5, lane = tid & 31;
    const int g = lane >> 2, tg = lane & 3;
    const int wm = warp >> 1, wn = warp & 1;
    const int h = blockIdx.x;              // BN=64 == head dim

    if (z <= 1) {
        __half* Y = (z == 0) ? g_qh : g_kh;
        #pragma unroll
        for (int mt = 0; mt < 2; mt++) {
            #pragma unroll
            for (int nt = 0; nt < 4; nt++) {
                const int dd = wn * 32 + nt * 8 + 2 * tg;
                int m = m0 + wm * 32 + mt * 16 + g;
                int b = m >> 11, n = m & (N_ - 1);
                *reinterpret_cast<uint32_t*>(&Y[((size_t)((b * H_ + h) * N_ + n)) * D_ + dd]) =
                    packh(acc[mt][nt][1] * scl, acc[mt][nt][0] * scl);
                m += 8; b = m >> 11; n = m & (N_ - 1);
                *reinterpret_cast<uint32_t*>(&Y[((size_t)((b * H_ + h) * N_ + n)) * D_ + dd]) =
                    packh(acc[mt][nt][3] * scl, acc[mt][nt][2] * scl);
            }
        }
    } else {
        // V: transpose 128(m) x 64(d) tile through smem -> g_vt[b][h][d][n]
        __half* ts = reinterpret_cast<__half*>(smb);   // [64][136] halfs
        __syncthreads();   // gemm buffers done
        #pragma unroll
        for (int mt = 0; mt < 2; mt++) {
            #pragma unroll
            for (int nt = 0; nt < 4; nt++) {
                const int dd = wn * 32 + nt * 8 + 2 * tg;
                const int ml = wm * 32 + mt * 16 + g;
                ts[dd * 136 + ml]           = __float2half(acc[mt][nt][0]);
                ts[(dd + 1) * 136 + ml]     = __float2half(acc[mt][nt][1]);
                ts[dd * 136 + ml + 8]       = __float2half(acc[mt][nt][2]);
                ts[(dd + 1) * 136 + ml + 8] = __float2half(acc[mt][nt][3]);
            }
        }
        __syncthreads();
        const int r = tid >> 2, c = tid & 3;
        const int bb = m0 >> 11, noff = m0 & (N_ - 1);
        __half* dst = g_vt + ((size_t)((bb * H_ + h) * D_ + r)) * N_ + noff + c * 32;
        #pragma unroll
        for (int i = 0; i < 4; i++)
            *reinterpret_cast<uint4*>(dst + i * 8) =
                *reinterpret_cast<const uint4*>(&ts[r * 136 + c * 32 + i * 8]);
    }
}

// Output projection: g_att @ Wo^T + bo -> out  (1-term W)
__global__ __launch_bounds__(256)
void gemm_out(const float* __restrict__ bias, float* __restrict__ Yext)
{
    extern __shared__ char smb[];
    const int m0 = blockIdx.y * 128, n0 = blockIdx.x * 64;
    float acc[2][4][4] = {};
    gemm_core5(g_att, 3, smb, m0, n0, acc, false);

    const int tid = threadIdx.x;
    const int warp = tid >> 5, lane = tid & 31;
    const int g = lane >> 2, tg = lane & 3;
    const int wm = warp >> 1, wn = warp & 1;
    #pragma unroll
    for (int mt = 0; mt < 2; mt++) {
        #pragma unroll
        for (int nt = 0; nt < 4; nt++) {
            const int o = n0 + wn * 32 + nt * 8 + 2 * tg;
            float2 bb = *reinterpret_cast<const float2*>(bias + o);
            const int m = m0 + wm * 32 + mt * 16 + g;
            *reinterpret_cast<float2*>(&Yext[(size_t)m * E_ + o]) =
                make_float2(acc[mt][nt][0] + bb.x, acc[mt][nt][1] + bb.y);
            *reinterpret_cast<float2*>(&Yext[(size_t)(m + 8) * E_ + o]) =
                make_float2(acc[mt][nt][2] + bb.x, acc[mt][nt][3] + bb.y);
        }
    }
}

// ---------------------------------------------------------------------------
// Flash attention v6 (R14/15, validated): fp16 m16n8k16, kv-tile 64, 128
// q-rows/block, 4 warps x 32 rows; K/V fragments shared across both row
// groups; cp.async double buffer; log2 softmax; fp32 g_att epilogue.
// ---------------------------------------------------------------------------
__global__ __launch_bounds__(128, 2)
void attn_tc(const int* __restrict__ mask)
{
    __shared__ __align__(16) __half sm[2 * BUFH_];   // 36864 B; Q staged here first

    const int h = blockIdx.x, qt = blockIdx.y, b = blockIdx.z;
    const int tid = threadIdx.x;
    const int warp = tid >> 5, lane = tid & 31;
    const int g = lane >> 2, tg = lane & 3;
    const int q0 = qt * 128;

    const size_t bh = (size_t)(b * H_ + h) * N_ * D_;
    const __half* qbase = g_qh + bh;
    const __half* kbase = g_kh + bh;
    const __half* vtbase = g_vt + bh;      // [d][n] layout
    const int* mbase = mask + (size_t)b * N_ * N_;
    const int* fb0 = g_mflag + (b * NT_ + 2 * qt) * NT_;
    const int* fb1 = fb0 + NT_;

    // Stage Q (128x64 fp16) into smem [128][72]
    {
        #pragma unroll
        for (int i = 0; i < 8; i++) {
            int idx = tid + i * 128;
            int r = idx >> 3, c = (idx & 7) * 8;
            cpb16(&sm[r * KST_ + c], qbase + (size_t)(q0 + r) * D_ + c);
        }
        cp_commit(); cp_wait<0>();
        __syncthreads();
    }

    uint32_t q_a[2][4][4];
    #pragma unroll
    for (int u = 0; u < 2; u++) {
        #pragma unroll
        for (int kc = 0; kc < 4; kc++) {
            const int row = warp * 32 + u * 16 + g;
            q_a[u][kc][0] = *reinterpret_cast<const uint32_t*>(&sm[row * KST_ + kc * 16 + 2 * tg]);
            q_a[u][kc][1] = *reinterpret_cast<const uint32_t*>(&sm[(row + 8) * KST_ + kc * 16 + 2 * tg]);
            q_a[u][kc][2] = *reinterpret_cast<const uint32_t*>(&sm[row * KST_ + kc * 16 + 8 + 2 * tg]);
            q_a[u][kc][3] = *reinterpret_cast<const uint32_t*>(&sm[(row + 8) * KST_ + kc * 16 + 8 + 2 * tg]);
        }
    }
    __syncthreads();   // Q staging region free for kv buffers

    // Prefetch kv tile 0 into buf 0
    {
        #pragma unroll
        for (int i = 0; i < 4; i++) {
            int idx = tid + i * 128;
            int r = idx >> 3, c = (idx & 7) * 8;
            cpb16(&sm[r * KST_ + c], kbase + (size_t)r * D_ + c);
        }
        #pragma unroll
        for (int i = 0; i < 4; i++) {
            int idx = tid + i * 128;
            int d = idx >> 3, c = (idx & 7) * 8;
            cpb16(&sm[KT_ * KST_ + d * VST_ + c], vtbase + (size_t)d * N_ + c);
        }
        cp_commit();
    }

    float o[2][8][4] = {};
    float mr[2][2] = {{neg_inf(), neg_inf()}, {neg_inf(), neg_inf()}};
    float lr[2][2] = {};
    int qrow[2];
    qrow[0] = q0 + warp * 32 + g;
    qrow[1] = qrow[0] + 16;

    for (int t = 0; t < NKT_; t++) {
        cp_wait<0>();
        __syncthreads();

        if (t + 1 < NKT_) {
            const __half* kb2 = kbase + (size_t)(t + 1) * KT_ * D_;
            const __half* vb2 = vtbase + (size_t)(t + 1) * KT_;
            __half* dst = sm + ((t + 1) & 1) * BUFH_;
            #pragma unroll
            for (int i = 0; i < 4; i++) {
                int idx = tid + i * 128;
                int r = idx >> 3, c = (idx & 7) * 8;
                cpb16(&dst[r * KST_ + c], kb2 + (size_t)r * D_ + c);
            }
            #pragma unroll
            for (int i = 0; i < 4; i++) {
                int idx = tid + i * 128;
                int d = idx >> 3, c = (idx & 7) * 8;
                cpb16(&dst[KT_ * KST_ + d * VST_ + c], vb2 + (size_t)d * N_ + c);
            }
            cp_commit();
        }

        const __half* Kc = sm + (t & 1) * BUFH_;
        const __half* Vc = Kc + KT_ * KST_;
        const int kv0 = t * KT_;
        const int clean = __ldg(fb0 + t) & __ldg(fb1 + t);

        // S = Q @ K^T (log2 units): 4 k16 chunks x 8 n-tiles, frags shared by u
        float s[2][8][4] = {};
        #pragma unroll
        for (int kc = 0; kc < 4; kc++) {
            #pragma unroll
            for (int nt = 0; nt < 8; nt++) {
                uint32_t bfr[2];
                const int kb = (nt * 8 + g) * KST_ + kc * 16 + 2 * tg;
                bfr[0] = *reinterpret_cast<const uint32_t*>(&Kc[kb]);
                bfr[1] = *reinterpret_cast<const uint32_t*>(&Kc[kb + 8]);
                mma16h(s[0][nt], q_a[0][kc], bfr);
                mma16h(s[1][nt], q_a[1][kc], bfr);
            }
        }

        if (!clean) {
            #pragma unroll
            for (int u = 0; u < 2; u++) {
                #pragma unroll
                for (int nt = 0; nt < 8; nt++) {
                    const int col = kv0 + nt * 8 + 2 * tg;
                    int2 mA = *reinterpret_cast<const int2*>(mbase + (size_t)qrow[u] * N_ + col);
                    int2 mB = *reinterpret_cast<const int2*>(mbase + (size_t)(qrow[u] + 8) * N_ + col);
                    if (!mA.x) s[u][nt][0] = neg_inf();
                    if (!mA.y) s[u][nt][1] = neg_inf();
                    if (!mB.x) s[u][nt][2] = neg_inf();
                    if (!mB.y) s[u][nt][3] = neg_inf();
                }
            }
        }

        // Online softmax (log2 domain), per group u, rows g and g+8
        #pragma unroll
        for (int u = 0; u < 2; u++) {
            float mx0 = neg_inf(), mx1 = neg_inf();
            #pragma unroll
            for (int nt = 0; nt < 8; nt++) {
                mx0 = fmaxf(mx0, fmaxf(s[u][nt][0], s[u][nt][1]));
                mx1 = fmaxf(mx1, fmaxf(s[u][nt][2], s[u][nt][3]));
            }
            mx0 = fmaxf(mx0, __shfl_xor_sync(0xffffffffu, mx0, 1));
            mx0 = fmaxf(mx0, __shfl_xor_sync(0xffffffffu, mx0, 2));
            mx1 = fmaxf(mx1, __shfl_xor_sync(0xffffffffu, mx1, 1));
            mx1 = fmaxf(mx1, __shfl_xor_sync(0xffffffffu, mx1, 2));
            const float mn0 = fmaxf(mr[u][0], mx0), mn1 = fmaxf(mr[u][1], mx1);
            const float sc0 = fexp2(fmaxf(mr[u][0] - mn0, -120.0f));
            const float sc1 = fexp2(fmaxf(mr[u][1] - mn1, -120.0f));
            float sum0 = 0.0f, sum1 = 0.0f;
            #pragma unroll
            for (int nt = 0; nt < 8; nt++) {
                float p0 = fexp2(fmaxf(s[u][nt][0] - mn0, -120.0f));
                float p1 = fexp2(fmaxf(s[u][nt][1] - mn0, -120.0f));
                float p2 = fexp2(fmaxf(s[u][nt][2] - mn1, -120.0f));
                float p3 = fexp2(fmaxf(s[u][nt][3] - mn1, -120.0f));
                s[u][nt][0] = p0; s[u][nt][1] = p1; s[u][nt][2] = p2; s[u][nt][3] = p3;
                sum0 += p0 + p1; sum1 += p2 + p3;
            }
            sum0 += __shfl_xor_sync(0xffffffffu, sum0, 1);
            sum0 += __shfl_xor_sync(0xffffffffu, sum0, 2);
            sum1 += __shfl_xor_sync(0xffffffffu, sum1, 1);
            sum1 += __shfl_xor_sync(0xffffffffu, sum1, 2);
            lr[u][0] = lr[u][0] * sc0 + sum0; lr[u][1] = lr[u][1] * sc1 + sum1;
            mr[u][0] = mn0; mr[u][1] = mn1;

            #pragma unroll
            for (int dt = 0; dt < 8; dt++) {
                o[u][dt][0] *= sc0; o[u][dt][1] *= sc0;
                o[u][dt][2] *= sc1; o[u][dt][3] *= sc1;
            }
        }

        // O += P @ V : fp16 k16, 4 kv chunks. P a-frags via quad shfls + f16x2
        // packs; V fragments from transposed smem, loaded once (feed both u).
        #pragma unroll
        for (int kc2 = 0; kc2 < 4; kc2++) {
            const int srcC = (g << 2) | tg;
            uint32_t a[2][4];
            #pragma unroll
            for (int u = 0; u < 2; u++) {
                float v0 = __shfl_sync(0xffffffffu, s[u][kc2 * 2][0], srcC);
                float v1 = __shfl_sync(0xffffffffu, s[u][kc2 * 2][1], srcC);
                float v2 = __shfl_sync(0xffffffffu, s[u][kc2 * 2][2], srcC);
                float v3 = __shfl_sync(0xffffffffu, s[u][kc2 * 2][3], srcC);
                float w0 = __shfl_sync(0xffffffffu, s[u][kc2 * 2 + 1][0], srcC);
                float w1 = __shfl_sync(0xffffffffu, s[u][kc2 * 2 + 1][1], srcC);
                float w2 = __shfl_sync(0xffffffffu, s[u][kc2 * 2 + 1][2], srcC);
                float w3 = __shfl_sync(0xffffffffu, s[u][kc2 * 2 + 1][3], srcC);
                a[u][0] = packh(v1, v0);   // row g,   k = 2tg, 2tg+1
                a[u][1] = packh(v3, v2);   // row g+8, k = 2tg, 2tg+1
                a[u][2] = packh(w1, w0);   // row g,   k = 8+2tg, 8+2tg+1
                a[u][3] = packh(w3, w2);   // row g+8, k = 8+2tg
            }
            #pragma unroll
            for (int dt = 0; dt < 8; dt++) {
                uint32_t bfr[2];
                const int vb = (dt * 8 + g) * VST_ + kc2 * 16 + 2 * tg;
                bfr[0] = *reinterpret_cast<const uint32_t*>(&Vc[vb]);
                bfr[1] = *reinterpret_cast<const uint32_t*>(&Vc[vb + 8]);
                mma16h(o[0][dt], a[0], bfr);
                mma16h(o[1][dt], a[1], bfr);
            }
        }
    }

    // Epilogue: normalize and recombine heads (fp32 g_att)
    #pragma unroll
    for (int u = 0; u < 2; u++) {
        const float il0 = 1.0f / lr[u][0], il1 = 1.0f / lr[u][1];
        #pragma unroll
        for (int dt = 0; dt < 8; dt++) {
            const int dd = h * 64 + dt * 8 + 2 * tg;
            *reinterpret_cast<float2*>(&g_att[(size_t)(b * N_ + qrow[u]) * E_ + dd]) =
                make_float2(o[u][dt][0] * il0, o[u][dt][1] * il0);
            *reinterpret_cast<float2*>(&g_att[(size_t)(b * N_ + qrow[u] + 8) * E_ + dd]) =
                make_float2(o[u][dt][2] * il1, o[u][dt][3] * il1);
        }
    }
}

// ---------------------------------------------------------------------------
extern "C" void kernel_launch(void* const* d_in, const int* in_sizes, int n_in,
                              void* d_out, int out_size)
{
    const float* Q    = (const float*)d_in[0];
    const float* K    = (const float*)d_in[1];
    const float* V    = (const float*)d_in[2];
    const int*   mask = (const int*)  d_in[3];
    const float* Wq   = (const float*)d_in[4];
    const float* Wk   = (const float*)d_in[5];
    const float* Wv   = (const float*)d_in[6];
    const float* Wo   = (const float*)d_in[7];
    const float* bo   = (const float*)d_in[8];
    const float* tau  = (const float*)d_in[9];
    float* out = (float*)d_out;

    const int gemm_smem = 2 * GBUFB_;   // 65536

    cudaFuncSetAttribute(gemm_qkv, cudaFuncAttributeMaxDynamicSharedMemorySize, gemm_smem);
    cudaFuncSetAttribute(gemm_out, cudaFuncAttributeMaxDynamicSharedMemorySize, gemm_smem);

    split_w<<<dim3((int)(WBE_ / 1024), 4), 256>>>(Wq, Wk, Wv, Wo);
    mask_flags<<<dim3(NT_, NT_, B_), 256>>>(mask);

    gemm_qkv<<<dim3(E_ / 64, M_ / 128, 3), 256, gemm_smem>>>(Q, K, V, tau);

    // grid.x = heads (fastest) so the 8 heads sharing a mask tile are adjacent -> L2 reuse
    attn_tc<<<dim3(H_, N_ / 128, B_), 128>>>(mask);

    gemm_out<<<dim3(E_ / 64, M_ / 128), 256, gemm_smem>>>(bo, out);
}

// round 17
// speedup vs baseline: 1.4732x; 1.0842x over previous
#include <cuda_runtime.h>
#include <cuda_bf16.h>
#include <cuda_fp16.h>
#include <cstdint>
#include <cstddef>

// Problem constants
constexpr int B_ = 8;
constexpr int N_ = 2048;
constexpr int E_ = 512;
constexpr int H_ = 8;
constexpr int D_ = 64;
constexpr int M_ = B_ * N_;   // 16384 rows
constexpr int NT_ = N_ / 64;  // 32 64-row tiles (mask-flag granularity)
constexpr int KT_ = 64;       // attention kv-tile rows
constexpr int NKT_ = N_ / KT_;// 32 kv tiles
constexpr int KST_ = 72;      // K/Q attention smem row stride (halfs), conflict-free
constexpr int VST_ = 72;      // Vt attention smem row stride (halfs), conflict-free
constexpr int BUFH_ = KT_ * KST_ + 64 * VST_;  // 9216 halfs per KV buffer

constexpr size_t WBE_ = (size_t)E_ * E_;

// Scratch (device globals: allocation-free per harness rules)
__device__ __half g_qh[(size_t)B_ * H_ * N_ * D_];  // [b][h][n][d], pre-scaled log2e/tau, fp16
__device__ __half g_kh[(size_t)B_ * H_ * N_ * D_];  // [b][h][n][d] fp16
__device__ __half g_vt[(size_t)B_ * H_ * D_ * N_];  // [b][h][d][n] fp16 (V transposed)
__device__ float  g_att[(size_t)M_ * E_];           // [b*n][h*d] recombined heads (fp32)
__device__ int    g_mflag[B_ * NT_ * NT_];          // 1 = 64x64 tile all-nonzero
__device__ __half g_wfh[4][WBE_];                   // fp16 hi parts of Wq,Wk,Wv,Wo
__device__ __half g_wfl[4][WBE_];                   // fp16 lo parts (unused: all GEMMs 1-term)

__device__ __forceinline__ float neg_inf() { return __int_as_float(0xff800000); }

__device__ __forceinline__ float fexp2(float x) {
    float y;
    asm("ex2.approx.ftz.f32 %0, %1;" : "=f"(y) : "f"(x));
    return y;
}

// pack two floats into f16x2 (low half = second arg)
__device__ __forceinline__ uint32_t packh(float hi, float lo) {
    uint32_t r;
    asm("cvt.rn.f16x2.f32 %0, %1, %2;" : "=r"(r) : "f"(hi), "f"(lo));
    return r;
}

// m16n8k16 fp16 mma, fp32 accumulate (projections AND attention)
__device__ __forceinline__ void mma16h(float* c, const uint32_t* a, const uint32_t* b) {
    asm volatile(
        "mma.sync.aligned.m16n8k16.row.col.f32.f16.f16.f32 "
        "{%0,%1,%2,%3}, {%4,%5,%6,%7}, {%8,%9}, {%0,%1,%2,%3};\n"
        : "+f"(c[0]), "+f"(c[1]), "+f"(c[2]), "+f"(c[3])
        : "r"(a[0]), "r"(a[1]), "r"(a[2]), "r"(a[3]), "r"(b[0]), "r"(b[1]));
}

// cp.async helpers
__device__ __forceinline__ void cpb16(const void* smem_dst, const void* gmem_src) {
    uint32_t s = (uint32_t)__cvta_generic_to_shared(smem_dst);
    asm volatile("cp.async.ca.shared.global [%0], [%1], 16;" :: "r"(s), "l"(gmem_src));
}
__device__ __forceinline__ void cp_commit() { asm volatile("cp.async.commit_group;"); }
template<int N>
__device__ __forceinline__ void cp_wait() { asm volatile("cp.async.wait_group %0;" :: "n"(N) : "memory"); }

// ---------------------------------------------------------------------------
// One-time weight split: W -> (hi, lo) fp16 pair. blockIdx.y selects matrix.
// (lo parts currently unused — all projection GEMMs run 1-term — kept for
// cheap fallback to 2-term per matrix.)
// ---------------------------------------------------------------------------
__global__ __launch_bounds__(256)
void split_w(const float* __restrict__ Wq, const float* __restrict__ Wk,
             const float* __restrict__ Wv, const float* __restrict__ Wo)
{
    const int m = blockIdx.y;
    const float* W = (m == 0) ? Wq : (m == 1) ? Wk : (m == 2) ? Wv : Wo;
    const size_t i4 = ((size_t)blockIdx.x * 256 + threadIdx.x) * 4;
    float4 v = *reinterpret_cast<const float4*>(W + i4);
    uint32_t h01 = packh(v.y, v.x);
    uint32_t h23 = packh(v.w, v.z);
    __half2 hh01 = *reinterpret_cast<__half2*>(&h01);
    __half2 hh23 = *reinterpret_cast<__half2*>(&h23);
    uint32_t l01 = packh(v.y - __high2float(hh01), v.x - __low2float(hh01));
    uint32_t l23 = packh(v.w - __high2float(hh23), v.z - __low2float(hh23));
    *reinterpret_cast<uint2*>(&g_wfh[m][i4]) = make_uint2(h01, h23);
    *reinterpret_cast<uint2*>(&g_wfl[m][i4]) = make_uint2(l01, l23);
}

// ---------------------------------------------------------------------------
// Mask preprocessing: one flag per (b, 64-row q tile, 64-col kv tile).
// ---------------------------------------------------------------------------
__global__ __launch_bounds__(256)
void mask_flags(const int* __restrict__ mask)
{
    const int kvt = blockIdx.x, qt = blockIdx.y, b = blockIdx.z;
    const int tid = threadIdx.x;
    const int r = tid >> 2, c0 = (tid & 3) * 16;
    const int* base = mask + (size_t)b * N_ * N_ + (size_t)(qt * 64 + r) * N_ + kvt * 64 + c0;
    bool ok = true;
    #pragma unroll
    for (int i = 0; i < 4; i++) {
        int4 m = *reinterpret_cast<const int4*>(base + i * 4);
        ok &= (m.x != 0) & (m.y != 0) & (m.z != 0) & (m.w != 0);
    }
    int all = __syncthreads_and((int)ok);
    if (tid == 0) g_mflag[(b * NT_ + qt) * NT_ + kvt] = all;
}

// ---------------------------------------------------------------------------
// GEMM core v5b: Y = fp16(X) @ (Wh [+ Wl])^T, fp16, 1-term everywhere now
// (mma count is the binding resource: both kernel families sit at the
// mma.sync dispatch ceiling, so duration tracks mma count). X fp32 in smem
// (stride 36), A-frags converted in regs; W fp16 (stride 56, conflict-free).
// cp.async double buffer. Block 128x64, BK=32, 8 warps (4m x 2n), warp 32x32.
// ---------------------------------------------------------------------------
constexpr int GXB_ = 128 * 36 * 4;          // X tile bytes (fp32)
constexpr int GWB_ = 64 * 56 * 2;           // one W tile bytes (fp16, stride 56)
constexpr int GBUFB_ = GXB_ + 2 * GWB_;     // 32768 B per buffer
constexpr int GKT_ = E_ / 32;               // 16 k tiles

__device__ __forceinline__ void cp16f(const float* smem_dst, const float* gmem_src) {
    cpb16((const void*)smem_dst, (const void*)gmem_src);
}

__device__ __forceinline__ void gemm_prefetch(const float* __restrict__ X, int widx,
                                              char* buf, int m0, int n0, int kt, bool wlo)
{
    const int tid = threadIdx.x;
    float* xs = reinterpret_cast<float*>(buf);
    char* whs = buf + GXB_;
    char* wls = whs + GWB_;
    #pragma unroll
    for (int i = 0; i < 4; i++) {
        int idx = tid + i * 256;
        int r = idx >> 3, c = (idx & 7) * 4;
        cp16f(&xs[r * 36 + c], X + (size_t)(m0 + r) * E_ + kt * 32 + c);
    }
    {
        int r = tid >> 2, c = tid & 3;
        const __half* srch = g_wfh[widx] + (size_t)(n0 + r) * E_ + kt * 32 + c * 8;
        cpb16(whs + r * 112 + c * 16, srch);
        if (wlo) {
            const __half* srcl = g_wfl[widx] + (size_t)(n0 + r) * E_ + kt * 32 + c * 8;
            cpb16(wls + r * 112 + c * 16, srcl);
        }
    }
    cp_commit();
}

__device__ __forceinline__ void gemm_core5(const float* __restrict__ X, int widx,
                                           char* smb, int m0, int n0,
                                           float acc[2][4][4], bool wlo)
{
    const int tid = threadIdx.x;
    const int warp = tid >> 5, lane = tid & 31;
    const int g = lane >> 2, tg = lane & 3;
    const int wm = warp >> 1, wn = warp & 1;

    gemm_prefetch(X, widx, smb, m0, n0, 0, wlo);

    for (int kt = 0; kt < GKT_; kt++) {
        if (kt + 1 < GKT_) {
            gemm_prefetch(X, widx, smb + ((kt + 1) & 1) * GBUFB_, m0, n0, kt + 1, wlo);
            cp_wait<1>();
        } else {
            cp_wait<0>();
        }
        __syncthreads();
        char* buf = smb + (kt & 1) * GBUFB_;
        const float* Xs = reinterpret_cast<const float*>(buf);
        const char* Whs = buf + GXB_;
        const char* Wls = Whs + GWB_;

        #pragma unroll
        for (int ks = 0; ks < 2; ks++) {
            const int k0 = ks * 16;
            uint32_t Ah[2][4], Bh[4][2];
            #pragma unroll
            for (int mt = 0; mt < 2; mt++) {
                const int rb = (wm * 32 + mt * 16) * 36 + k0;
                float2 p0 = *reinterpret_cast<const float2*>(&Xs[rb + g * 36 + 2 * tg]);
                float2 p1 = *reinterpret_cast<const float2*>(&Xs[rb + (g + 8) * 36 + 2 * tg]);
                float2 p2 = *reinterpret_cast<const float2*>(&Xs[rb + g * 36 + 8 + 2 * tg]);
                float2 p3 = *reinterpret_cast<const float2*>(&Xs[rb + (g + 8) * 36 + 8 + 2 * tg]);
                Ah[mt][0] = packh(p0.y, p0.x);
                Ah[mt][1] = packh(p1.y, p1.x);
                Ah[mt][2] = packh(p2.y, p2.x);
                Ah[mt][3] = packh(p3.y, p3.x);
            }
            #pragma unroll
            for (int nt = 0; nt < 4; nt++) {
                const int r = wn * 32 + nt * 8 + g;
                const int boff = r * 112 + (k0 + 2 * tg) * 2;
                Bh[nt][0] = *reinterpret_cast<const uint32_t*>(Whs + boff);
                Bh[nt][1] = *reinterpret_cast<const uint32_t*>(Whs + boff + 16);
            }
            #pragma unroll
            for (int mt = 0; mt < 2; mt++)
                #pragma unroll
                for (int nt = 0; nt < 4; nt++)
                    mma16h(acc[mt][nt], Ah[mt], Bh[nt]);   // h*H
            if (wlo) {
                uint32_t Bl[4][2];
                #pragma unroll
                for (int nt = 0; nt < 4; nt++) {
                    const int r = wn * 32 + nt * 8 + g;
                    const int boff = r * 112 + (k0 + 2 * tg) * 2;
                    Bl[nt][0] = *reinterpret_cast<const uint32_t*>(Wls + boff);
                    Bl[nt][1] = *reinterpret_cast<const uint32_t*>(Wls + boff + 16);
                }
                #pragma unroll
                for (int mt = 0; mt < 2; mt++)
                    #pragma unroll
                    for (int nt = 0; nt < 4; nt++)
                        mma16h(acc[mt][nt], Ah[mt], Bl[nt]);   // h*L
            }
        }
        __syncthreads();
    }
}

// QKV projections fused; outputs fp16 formatted for the fp16 attention:
//  z=0: Q scaled by log2e/tau -> g_qh; z=1: K -> g_kh; z=2: V -> g_vt (transposed).
//  All 1-term fp16 W (error budget verified: measured +2.2e-4 per transition).
__global__ __launch_bounds__(256)
void gemm_qkv(const float* __restrict__ Qi, const float* __restrict__ Ki,
              const float* __restrict__ Vi, const float* __restrict__ taup)
{
    extern __shared__ char smb[];
    const int z = blockIdx.z;
    const float* X = (z == 0) ? Qi : (z == 1) ? Ki : Vi;
    const float scl = (z == 0) ? (1.4426950408889634f / __ldg(taup)) : 1.0f;

    const int m0 = blockIdx.y * 128, n0 = blockIdx.x * 64;
    float acc[2][4][4] = {};
    gemm_core5(X, z, smb, m0, n0, acc, false);

    const int tid = threadIdx.x;
    const int warp = tid >> 5, lane = tid & 31;
    const int g = lane >> 2, tg = lane & 3;
    const int wm = warp >> 1, wn = warp & 1;
    const int h = blockIdx.x;              // BN=64 == head dim

    if (z <= 1) {
        __half* Y = (z == 0) ? g_qh : g_kh;
        #pragma unroll
        for (int mt = 0; mt < 2; mt++) {
            #pragma unroll
            for (int nt = 0; nt < 4; nt++) {
                const int dd = wn * 32 + nt * 8 + 2 * tg;
                int m = m0 + wm * 32 + mt * 16 + g;
                int b = m >> 11, n = m & (N_ - 1);
                *reinterpret_cast<uint32_t*>(&Y[((size_t)((b * H_ + h) * N_ + n)) * D_ + dd]) =
                    packh(acc[mt][nt][1] * scl, acc[mt][nt][0] * scl);
                m += 8; b = m >> 11; n = m & (N_ - 1);
                *reinterpret_cast<uint32_t*>(&Y[((size_t)((b * H_ + h) * N_ + n)) * D_ + dd]) =
                    packh(acc[mt][nt][3] * scl, acc[mt][nt][2] * scl);
            }
        }
    } else {
        // V: transpose 128(m) x 64(d) tile through smem -> g_vt[b][h][d][n]
        __half* ts = reinterpret_cast<__half*>(smb);   // [64][136] halfs
        __syncthreads();   // gemm buffers done
        #pragma unroll
        for (int mt = 0; mt < 2; mt++) {
            #pragma unroll
            for (int nt = 0; nt < 4; nt++) {
                const int dd = wn * 32 + nt * 8 + 2 * tg;
                const int ml = wm * 32 + mt * 16 + g;
                ts[dd * 136 + ml]           = __float2half(acc[mt][nt][0]);
                ts[(dd + 1) * 136 + ml]     = __float2half(acc[mt][nt][1]);
                ts[dd * 136 + ml + 8]       = __float2half(acc[mt][nt][2]);
                ts[(dd + 1) * 136 + ml + 8] = __float2half(acc[mt][nt][3]);
            }
        }
        __syncthreads();
        const int r = tid >> 2, c = tid & 3;
        const int bb = m0 >> 11, noff = m0 & (N_ - 1);
        __half* dst = g_vt + ((size_t)((bb * H_ + h) * D_ + r)) * N_ + noff + c * 32;
        #pragma unroll
        for (int i = 0; i < 4; i++)
            *reinterpret_cast<uint4*>(dst + i * 8) =
                *reinterpret_cast<const uint4*>(&ts[r * 136 + c * 32 + i * 8]);
    }
}

// Output projection: g_att @ Wo^T + bo -> out  (1-term W)
__global__ __launch_bounds__(256)
void gemm_out(const float* __restrict__ bias, float* __restrict__ Yext)
{
    extern __shared__ char smb[];
    const int m0 = blockIdx.y * 128, n0 = blockIdx.x * 64;
    float acc[2][4][4] = {};
    gemm_core5(g_att, 3, smb, m0, n0, acc, false);

    const int tid = threadIdx.x;
    const int warp = tid >> 5, lane = tid & 31;
    const int g = lane >> 2, tg = lane & 3;
    const int wm = warp >> 1, wn = warp & 1;
    #pragma unroll
    for (int mt = 0; mt < 2; mt++) {
        #pragma unroll
        for (int nt = 0; nt < 4; nt++) {
            const int o = n0 + wn * 32 + nt * 8 + 2 * tg;
            float2 bb = *reinterpret_cast<const float2*>(bias + o);
            const int m = m0 + wm * 32 + mt * 16 + g;
            *reinterpret_cast<float2*>(&Yext[(size_t)m * E_ + o]) =
                make_float2(acc[mt][nt][0] + bb.x, acc[mt][nt][1] + bb.y);
            *reinterpret_cast<float2*>(&Yext[(size_t)(m + 8) * E_ + o]) =
                make_float2(acc[mt][nt][2] + bb.x, acc[mt][nt][3] + bb.y);
        }
    }
}

// ---------------------------------------------------------------------------
// Flash attention v6 (validated): fp16 m16n8k16, kv-tile 64, 128 q-rows per
// block, 4 warps x 32 rows; K/V fragments shared across both row groups;
// cp.async double buffer; log2 softmax; fp32 g_att epilogue.
// ---------------------------------------------------------------------------
__global__ __launch_bounds__(128, 2)
void attn_tc(const int* __restrict__ mask)
{
    __shared__ __align__(16) __half sm[2 * BUFH_];   // 36864 B; Q staged here first

    const int h = blockIdx.x, qt = blockIdx.y, b = blockIdx.z;
    const int tid = threadIdx.x;
    const int warp = tid >> 5, lane = tid & 31;
    const int g = lane >> 2, tg = lane & 3;
    const int q0 = qt * 128;

    const size_t bh = (size_t)(b * H_ + h) * N_ * D_;
    const __half* qbase = g_qh + bh;
    const __half* kbase = g_kh + bh;
    const __half* vtbase = g_vt + bh;      // [d][n] layout
    const int* mbase = mask + (size_t)b * N_ * N_;
    const int* fb0 = g_mflag + (b * NT_ + 2 * qt) * NT_;
    const int* fb1 = fb0 + NT_;

    // Stage Q (128x64 fp16) into smem [128][72]
    {
        #pragma unroll
        for (int i = 0; i < 8; i++) {
            int idx = tid + i * 128;
            int r = idx >> 3, c = (idx & 7) * 8;
            cpb16(&sm[r * KST_ + c], qbase + (size_t)(q0 + r) * D_ + c);
        }
        cp_commit(); cp_wait<0>();
        __syncthreads();
    }

    uint32_t q_a[2][4][4];
    #pragma unroll
    for (int u = 0; u < 2; u++) {
        #pragma unroll
        for (int kc = 0; kc < 4; kc++) {
            const int row = warp * 32 + u * 16 + g;
            q_a[u][kc][0] = *reinterpret_cast<const uint32_t*>(&sm[row * KST_ + kc * 16 + 2 * tg]);
            q_a[u][kc][1] = *reinterpret_cast<const uint32_t*>(&sm[(row + 8) * KST_ + kc * 16 + 2 * tg]);
            q_a[u][kc][2] = *reinterpret_cast<const uint32_t*>(&sm[row * KST_ + kc * 16 + 8 + 2 * tg]);
            q_a[u][kc][3] = *reinterpret_cast<const uint32_t*>(&sm[(row + 8) * KST_ + kc * 16 + 8 + 2 * tg]);
        }
    }
    __syncthreads();   // Q staging region free for kv buffers

    // Prefetch kv tile 0 into buf 0
    {
        #pragma unroll
        for (int i = 0; i < 4; i++) {
            int idx = tid + i * 128;
            int r = idx >> 3, c = (idx & 7) * 8;
            cpb16(&sm[r * KST_ + c], kbase + (size_t)r * D_ + c);
        }
        #pragma unroll
        for (int i = 0; i < 4; i++) {
            int idx = tid + i * 128;
            int d = idx >> 3, c = (idx & 7) * 8;
            cpb16(&sm[KT_ * KST_ + d * VST_ + c], vtbase + (size_t)d * N_ + c);
        }
        cp_commit();
    }

    float o[2][8][4] = {};
    float mr[2][2] = {{neg_inf(), neg_inf()}, {neg_inf(), neg_inf()}};
    float lr[2][2] = {};
    int qrow[2];
    qrow[0] = q0 + warp * 32 + g;
    qrow[1] = qrow[0] + 16;

    for (int t = 0; t < NKT_; t++) {
        cp_wait<0>();
        __syncthreads();

        if (t + 1 < NKT_) {
            const __half* kb2 = kbase + (size_t)(t + 1) * KT_ * D_;
            const __half* vb2 = vtbase + (size_t)(t + 1) * KT_;
            __half* dst = sm + ((t + 1) & 1) * BUFH_;
            #pragma unroll
            for (int i = 0; i < 4; i++) {
                int idx = tid + i * 128;
                int r = idx >> 3, c = (idx & 7) * 8;
                cpb16(&dst[r * KST_ + c], kb2 + (size_t)r * D_ + c);
            }
            #pragma unroll
            for (int i = 0; i < 4; i++) {
                int idx = tid + i * 128;
                int d = idx >> 3, c = (idx & 7) * 8;
                cpb16(&dst[KT_ * KST_ + d * VST_ + c], vb2 + (size_t)d * N_ + c);
            }
            cp_commit();
        }

        const __half* Kc = sm + (t & 1) * BUFH_;
        const __half* Vc = Kc + KT_ * KST_;
        const int kv0 = t * KT_;
        const int clean = __ldg(fb0 + t) & __ldg(fb1 + t);

        // S = Q @ K^T (log2 units): 4 k16 chunks x 8 n-tiles, frags shared by u
        float s[2][8][4] = {};
        #pragma unroll
        for (int kc = 0; kc < 4; kc++) {
            #pragma unroll
            for (int nt = 0; nt < 8; nt++) {
                uint32_t bfr[2];
                const int kb = (nt * 8 + g) * KST_ + kc * 16 + 2 * tg;
                bfr[0] = *reinterpret_cast<const uint32_t*>(&Kc[kb]);
                bfr[1] = *reinterpret_cast<const uint32_t*>(&Kc[kb + 8]);
                mma16h(s[0][nt], q_a[0][kc], bfr);
                mma16h(s[1][nt], q_a[1][kc], bfr);
            }
        }

        if (!clean) {
            #pragma unroll
            for (int u = 0; u < 2; u++) {
                #pragma unroll
                for (int nt = 0; nt < 8; nt++) {
                    const int col = kv0 + nt * 8 + 2 * tg;
                    int2 mA = *reinterpret_cast<const int2*>(mbase + (size_t)qrow[u] * N_ + col);
                    int2 mB = *reinterpret_cast<const int2*>(mbase + (size_t)(qrow[u] + 8) * N_ + col);
                    if (!mA.x) s[u][nt][0] = neg_inf();
                    if (!mA.y) s[u][nt][1] = neg_inf();
                    if (!mB.x) s[u][nt][2] = neg_inf();
                    if (!mB.y) s[u][nt][3] = neg_inf();
                }
            }
        }

        // Online softmax (log2 domain), per group u, rows g and g+8
        #pragma unroll
        for (int u = 0; u < 2; u++) {
            float mx0 = neg_inf(), mx1 = neg_inf();
            #pragma unroll
            for (int nt = 0; nt < 8; nt++) {
                mx0 = fmaxf(mx0, fmaxf(s[u][nt][0], s[u][nt][1]));
                mx1 = fmaxf(mx1, fmaxf(s[u][nt][2], s[u][nt][3]));
            }
            mx0 = fmaxf(mx0, __shfl_xor_sync(0xffffffffu, mx0, 1));
            mx0 = fmaxf(mx0, __shfl_xor_sync(0xffffffffu, mx0, 2));
            mx1 = fmaxf(mx1, __shfl_xor_sync(0xffffffffu, mx1, 1));
            mx1 = fmaxf(mx1, __shfl_xor_sync(0xffffffffu, mx1, 2));
            const float mn0 = fmaxf(mr[u][0], mx0), mn1 = fmaxf(mr[u][1], mx1);
            const float sc0 = fexp2(fmaxf(mr[u][0] - mn0, -120.0f));
            const float sc1 = fexp2(fmaxf(mr[u][1] - mn1, -120.0f));
            float sum0 = 0.0f, sum1 = 0.0f;
            #pragma unroll
            for (int nt = 0; nt < 8; nt++) {
                float p0 = fexp2(fmaxf(s[u][nt][0] - mn0, -120.0f));
                float p1 = fexp2(fmaxf(s[u][nt][1] - mn0, -120.0f));
                float p2 = fexp2(fmaxf(s[u][nt][2] - mn1, -120.0f));
                float p3 = fexp2(fmaxf(s[u][nt][3] - mn1, -120.0f));
                s[u][nt][0] = p0; s[u][nt][1] = p1; s[u][nt][2] = p2; s[u][nt][3] = p3;
                sum0 += p0 + p1; sum1 += p2 + p3;
            }
            sum0 += __shfl_xor_sync(0xffffffffu, sum0, 1);
            sum0 += __shfl_xor_sync(0xffffffffu, sum0, 2);
            sum1 += __shfl_xor_sync(0xffffffffu, sum1, 1);
            sum1 += __shfl_xor_sync(0xffffffffu, sum1, 2);
            lr[u][0] = lr[u][0] * sc0 + sum0; lr[u][1] = lr[u][1] * sc1 + sum1;
            mr[u][0] = mn0; mr[u][1] = mn1;

            #pragma unroll
            for (int dt = 0; dt < 8; dt++) {
                o[u][dt][0] *= sc0; o[u][dt][1] *= sc0;
                o[u][dt][2] *= sc1; o[u][dt][3] *= sc1;
            }
        }

        // O += P @ V : fp16 k16, 4 kv chunks. P a-frags via quad shfls + f16x2
        // packs; V fragments from transposed smem, loaded once (feed both u).
        #pragma unroll
        for (int kc2 = 0; kc2 < 4; kc2++) {
            const int srcC = (g << 2) | tg;
            uint32_t a[2][4];
            #pragma unroll
            for (int u = 0; u < 2; u++) {
                float v0 = __shfl_sync(0xffffffffu, s[u][kc2 * 2][0], srcC);
                float v1 = __shfl_sync(0xffffffffu, s[u][kc2 * 2][1], srcC);
                float v2 = __shfl_sync(0xffffffffu, s[u][kc2 * 2][2], srcC);
                float v3 = __shfl_sync(0xffffffffu, s[u][kc2 * 2][3], srcC);
                float w0 = __shfl_sync(0xffffffffu, s[u][kc2 * 2 + 1][0], srcC);
                float w1 = __shfl_sync(0xffffffffu, s[u][kc2 * 2 + 1][1], srcC);
                float w2 = __shfl_sync(0xffffffffu, s[u][kc2 * 2 + 1][2], srcC);
                float w3 = __shfl_sync(0xffffffffu, s[u][kc2 * 2 + 1][3], srcC);
                a[u][0] = packh(v1, v0);   // row g,   k = 2tg, 2tg+1
                a[u][1] = packh(v3, v2);   // row g+8, k = 2tg, 2tg+1
                a[u][2] = packh(w1, w0);   // row g,   k = 8+2tg, 8+2tg+1
                a[u][3] = packh(w3, w2);   // row g+8, k = 8+2tg
            }
            #pragma unroll
            for (int dt = 0; dt < 8; dt++) {
                uint32_t bfr[2];
                const int vb = (dt * 8 + g) * VST_ + kc2 * 16 + 2 * tg;
                bfr[0] = *reinterpret_cast<const uint32_t*>(&Vc[vb]);
                bfr[1] = *reinterpret_cast<const uint32_t*>(&Vc[vb + 8]);
                mma16h(o[0][dt], a[0], bfr);
                mma16h(o[1][dt], a[1], bfr);
            }
        }
    }

    // Epilogue: normalize and recombine heads (fp32 g_att)
    #pragma unroll
    for (int u = 0; u < 2; u++) {
        const float il0 = 1.0f / lr[u][0], il1 = 1.0f / lr[u][1];
        #pragma unroll
        for (int dt = 0; dt < 8; dt++) {
            const int dd = h * 64 + dt * 8 + 2 * tg;
            *reinterpret_cast<float2*>(&g_att[(size_t)(b * N_ + qrow[u]) * E_ + dd]) =
                make_float2(o[u][dt][0] * il0, o[u][dt][1] * il0);
            *reinterpret_cast<float2*>(&g_att[(size_t)(b * N_ + qrow[u] + 8) * E_ + dd]) =
                make_float2(o[u][dt][2] * il1, o[u][dt][3] * il1);
        }
    }
}

// ---------------------------------------------------------------------------
extern "C" void kernel_launch(void* const* d_in, const int* in_sizes, int n_in,
                              void* d_out, int out_size)
{
    const float* Q    = (const float*)d_in[0];
    const float* K    = (const float*)d_in[1];
    const float* V    = (const float*)d_in[2];
    const int*   mask = (const int*)  d_in[3];
    const float* Wq   = (const float*)d_in[4];
    const float* Wk   = (const float*)d_in[5];
    const float* Wv   = (const float*)d_in[6];
    const float* Wo   = (const float*)d_in[7];
    const float* bo   = (const float*)d_in[8];
    const float* tau  = (const float*)d_in[9];
    float* out = (float*)d_out;

    const int gemm_smem = 2 * GBUFB_;   // 65536

    cudaFuncSetAttribute(gemm_qkv, cudaFuncAttributeMaxDynamicSharedMemorySize, gemm_smem);
    cudaFuncSetAttribute(gemm_out, cudaFuncAttributeMaxDynamicSharedMemorySize, gemm_smem);

    split_w<<<dim3((int)(WBE_ / 1024), 4), 256>>>(Wq, Wk, Wv, Wo);
    mask_flags<<<dim3(NT_, NT_, B_), 256>>>(mask);

    gemm_qkv<<<dim3(E_ / 64, M_ / 128, 3), 256, gemm_smem>>>(Q, K, V, tau);

    // grid.x = heads (fastest) so the 8 heads sharing a mask tile are adjacent -> L2 reuse
    attn_tc<<<dim3(H_, N_ / 128, B_), 128>>>(mask);

    gemm_out<<<dim3(E_ / 64, M_ / 128), 256, gemm_smem>>>(bo, out);
}